// round 1
// baseline (speedup 1.0000x reference)
#include <cuda_runtime.h>
#include <cstdint>

#define N_NODES 100000
#define N_EDGES 1600000
#define DIN 256
#define HID 128

// ---------------- scratch (static device globals; no allocation) ------------
__device__ __align__(128) float g_bufA[(size_t)N_NODES * HID];  // h0 / h2
__device__ __align__(128) float g_bufB[(size_t)N_NODES * HID];  // h1
__device__ __align__(128) float g_hn[(size_t)N_NODES * HID];    // h_neigh scratch

__device__ int g_cnt[N_NODES];
__device__ int g_off[N_NODES + 1];
__device__ int g_cur[N_NODES];
__device__ int g_csr[N_EDGES];
__device__ int g_blksum[128];
__device__ int g_blkoff[128];

#define SCAN_B 1024
#define NSCANBLK ((N_NODES + SCAN_B - 1) / SCAN_B)   // 98

// ---------------- CSR build -------------------------------------------------
__global__ void k_zero_cnt() {
    int i = blockIdx.x * blockDim.x + threadIdx.x;
    if (i < N_NODES) g_cnt[i] = 0;
}

__global__ void k_hist(const int* __restrict__ dst) {
    int i = blockIdx.x * blockDim.x + threadIdx.x;
    if (i < N_EDGES) atomicAdd(&g_cnt[dst[i]], 1);
}

__global__ void k_scan_block() {
    __shared__ int s[SCAN_B];
    int t = threadIdx.x;
    int i = blockIdx.x * SCAN_B + t;
    int v = (i < N_NODES) ? g_cnt[i] : 0;
    s[t] = v;
    __syncthreads();
    #pragma unroll
    for (int off = 1; off < SCAN_B; off <<= 1) {
        int x = (t >= off) ? s[t - off] : 0;
        __syncthreads();
        s[t] += x;
        __syncthreads();
    }
    if (i < N_NODES) g_off[i + 1] = s[t];   // inclusive, per-block partial
    if (t == SCAN_B - 1) g_blksum[blockIdx.x] = s[t];
}

__global__ void k_scan_top() {
    if (threadIdx.x == 0) {
        int running = 0;
        for (int b = 0; b < NSCANBLK; b++) {
            g_blkoff[b] = running;
            running += g_blksum[b];
        }
        g_off[0] = 0;
    }
}

__global__ void k_scan_add() {
    int i = blockIdx.x * blockDim.x + threadIdx.x;
    if (i < N_NODES) g_off[i + 1] += g_blkoff[i >> 10];
}

__global__ void k_init_cur() {
    int i = blockIdx.x * blockDim.x + threadIdx.x;
    if (i < N_NODES) g_cur[i] = g_off[i];
}

__global__ void k_fill(const int* __restrict__ src, const int* __restrict__ dst) {
    int i = blockIdx.x * blockDim.x + threadIdx.x;
    if (i < N_EDGES) {
        int d = dst[i];
        int p = atomicAdd(&g_cur[d], 1);
        g_csr[p] = src[i];
    }
}

// ---------------- neighbor-mean aggregation (warp per node, no atomics) -----
__global__ void k_aggregate(const float* __restrict__ h) {
    int warp = (blockIdx.x * blockDim.x + threadIdx.x) >> 5;
    int lane = threadIdx.x & 31;
    if (warp >= N_NODES) return;
    int s = g_off[warp];
    int e = g_off[warp + 1];
    float4 acc = make_float4(0.f, 0.f, 0.f, 0.f);
    for (int i = s; i < e; i++) {
        int sc = g_csr[i];
        float4 v = *(const float4*)(h + (size_t)sc * HID + lane * 4);
        acc.x += v.x; acc.y += v.y; acc.z += v.z; acc.w += v.w;
    }
    float inv = 1.f / fmaxf((float)(e - s), 1.f);
    float4 o = make_float4(acc.x * inv, acc.y * inv, acc.z * inv, acc.w * inv);
    *(float4*)(g_hn + (size_t)warp * HID + lane * 4) = o;
}

// ---------------- tiled fp32 GEMM: C[M,128] = relu?(A0@B0 + A1@B1 + bias) ---
// Two K-segments (A1 may be null). B row-major KxN with N=128, ldb=128.
// BM=128, BN=128, BK=16, 256 threads, 8x8 per thread.
__global__ __launch_bounds__(256) void k_gemm(
    const float* __restrict__ A0, const float* __restrict__ B0, int K0,
    const float* __restrict__ A1, const float* __restrict__ B1, int K1,
    const float* __restrict__ bias, float* __restrict__ C, int M, int relu)
{
    __shared__ float As[16][132];
    __shared__ float Bs[16][132];

    int row0 = blockIdx.x * 128;
    int tid = threadIdx.x;
    int tx = tid & 15;
    int ty = tid >> 4;

    float acc[8][8];
    #pragma unroll
    for (int i = 0; i < 8; i++)
        #pragma unroll
        for (int j = 0; j < 8; j++) acc[i][j] = 0.f;

    #pragma unroll 1
    for (int seg = 0; seg < 2; seg++) {
        const float* A = seg ? A1 : A0;
        const float* B = seg ? B1 : B0;
        int K = seg ? K1 : K0;
        if (A == nullptr) continue;

        for (int k0 = 0; k0 < K; k0 += 16) {
            // load A tile 128x16 (transposed into As[k][m])
            #pragma unroll
            for (int r = 0; r < 2; r++) {
                int v  = tid + r * 256;     // 0..511 float4's
                int m  = v >> 2;
                int kk = (v & 3) * 4;
                int row = row0 + m;
                float4 a = make_float4(0.f, 0.f, 0.f, 0.f);
                if (row < M)
                    a = *(const float4*)(A + (size_t)row * K + k0 + kk);
                As[kk + 0][m] = a.x;
                As[kk + 1][m] = a.y;
                As[kk + 2][m] = a.z;
                As[kk + 3][m] = a.w;
            }
            // load B tile 16x128
            #pragma unroll
            for (int r = 0; r < 2; r++) {
                int v  = tid + r * 256;
                int kk = v >> 5;
                int n4 = (v & 31) * 4;
                float4 b = *(const float4*)(B + (size_t)(k0 + kk) * 128 + n4);
                *(float4*)&Bs[kk][n4] = b;
            }
            __syncthreads();

            #pragma unroll
            for (int kk = 0; kk < 16; kk++) {
                float a_frag[8], b_frag[8];
                #pragma unroll
                for (int i = 0; i < 8; i++) a_frag[i] = As[kk][ty * 8 + i];
                #pragma unroll
                for (int j = 0; j < 8; j++) b_frag[j] = Bs[kk][tx * 8 + j];
                #pragma unroll
                for (int i = 0; i < 8; i++)
                    #pragma unroll
                    for (int j = 0; j < 8; j++)
                        acc[i][j] += a_frag[i] * b_frag[j];
            }
            __syncthreads();
        }
    }

    // epilogue
    #pragma unroll
    for (int i = 0; i < 8; i++) {
        int row = row0 + ty * 8 + i;
        if (row >= M) continue;
        #pragma unroll
        for (int j4 = 0; j4 < 2; j4++) {
            float4 o;
            int colb = tx * 8 + j4 * 4;
            o.x = acc[i][j4 * 4 + 0] + bias[colb + 0];
            o.y = acc[i][j4 * 4 + 1] + bias[colb + 1];
            o.z = acc[i][j4 * 4 + 2] + bias[colb + 2];
            o.w = acc[i][j4 * 4 + 3] + bias[colb + 3];
            if (relu) {
                o.x = fmaxf(o.x, 0.f); o.y = fmaxf(o.y, 0.f);
                o.z = fmaxf(o.z, 0.f); o.w = fmaxf(o.w, 0.f);
            }
            *(float4*)(C + (size_t)row * 128 + colb) = o;
        }
    }
}

// ---------------- final projection: out[n] = h[n,:] . W_fin ----------------
__global__ void k_final(const float* __restrict__ h,
                        const float* __restrict__ Wfin,
                        float* __restrict__ out)
{
    int warp = (blockIdx.x * blockDim.x + threadIdx.x) >> 5;
    int lane = threadIdx.x & 31;
    if (warp >= N_NODES) return;
    float4 v = *(const float4*)(h + (size_t)warp * HID + lane * 4);
    float4 w = *(const float4*)(Wfin + lane * 4);
    float s = v.x * w.x + v.y * w.y + v.z * w.z + v.w * w.w;
    #pragma unroll
    for (int o = 16; o; o >>= 1) s += __shfl_xor_sync(0xffffffffu, s, o);
    if (lane == 0) out[warp] = s;
}

// ---------------- launch ----------------------------------------------------
extern "C" void kernel_launch(void* const* d_in, const int* in_sizes, int n_in,
                              void* d_out, int out_size)
{
    const float* x       = (const float*)d_in[0];
    const float* W_t     = (const float*)d_in[1];
    const float* b_t     = (const float*)d_in[2];
    const float* W_self0 = (const float*)d_in[3];
    const float* b_self0 = (const float*)d_in[4];
    const float* W_neigh0= (const float*)d_in[5];
    const float* W_self1 = (const float*)d_in[6];
    const float* b_self1 = (const float*)d_in[7];
    const float* W_neigh1= (const float*)d_in[8];
    const float* W_fin   = (const float*)d_in[9];
    const int*   src     = (const int*)d_in[10];
    const int*   dst     = (const int*)d_in[11];
    float* out = (float*)d_out;

    float* bufA;  cudaGetSymbolAddress((void**)&bufA, g_bufA);
    float* bufB;  cudaGetSymbolAddress((void**)&bufB, g_bufB);
    float* hn;    cudaGetSymbolAddress((void**)&hn,   g_hn);

    const int TB = 256;
    dim3 gridNodes((N_NODES + TB - 1) / TB);
    dim3 gridEdges((N_EDGES + TB - 1) / TB);
    dim3 gridWarp((N_NODES * 32 + TB - 1) / TB);
    dim3 gridGemm((N_NODES + 127) / 128);

    // CSR build (counting sort by dst)
    k_zero_cnt<<<gridNodes, TB>>>();
    k_hist<<<gridEdges, TB>>>(dst);
    k_scan_block<<<NSCANBLK, SCAN_B>>>();
    k_scan_top<<<1, 32>>>();
    k_scan_add<<<gridNodes, TB>>>();
    k_init_cur<<<gridNodes, TB>>>();
    k_fill<<<gridEdges, TB>>>(src, dst);

    // h0 = x @ W_t + b_t
    k_gemm<<<gridGemm, 256>>>(x, W_t, DIN, nullptr, nullptr, 0,
                              b_t, bufA, N_NODES, 0);

    // layer 0
    k_aggregate<<<gridWarp, TB>>>(bufA);
    k_gemm<<<gridGemm, 256>>>(bufA, W_self0, HID, hn, W_neigh0, HID,
                              b_self0, bufB, N_NODES, 1);

    // layer 1
    k_aggregate<<<gridWarp, TB>>>(bufB);
    k_gemm<<<gridGemm, 256>>>(bufB, W_self1, HID, hn, W_neigh1, HID,
                              b_self1, bufA, N_NODES, 1);

    // out = h2 @ W_fin
    k_final<<<gridWarp, TB>>>(bufA, W_fin, out);
}

// round 3
// speedup vs baseline: 1.3138x; 1.3138x over previous
#include <cuda_runtime.h>
#include <cuda_fp16.h>
#include <cstdint>

#define N_NODES 100000
#define N_EDGES 1600000
#define DIN 256
#define HID 128

#define NTILES 782
#define MPAD (NTILES * 128)      // 100096

// ------------------------ device scratch (no allocation) --------------------
__device__ __align__(128) float  g_h32a[(size_t)MPAD * HID];
__device__ __align__(128) float  g_h32b[(size_t)MPAD * HID];
__device__ __align__(256) __half g_Axhi[(size_t)MPAD * 256];
__device__ __align__(256) __half g_Axlo[(size_t)MPAD * 256];
__device__ __align__(256) __half g_A1hi[(size_t)MPAD * 256];
__device__ __align__(256) __half g_A1lo[(size_t)MPAD * 256];
__device__ __align__(256) __half g_A2hi[(size_t)MPAD * 256];
__device__ __align__(256) __half g_A2lo[(size_t)MPAD * 256];
__device__ __align__(256) __half g_Bthi[128 * 256];
__device__ __align__(256) __half g_Btlo[128 * 256];
__device__ __align__(256) __half g_B0hi[128 * 256];
__device__ __align__(256) __half g_B0lo[128 * 256];
__device__ __align__(256) __half g_B1hi[128 * 256];
__device__ __align__(256) __half g_B1lo[128 * 256];

__device__ int g_cnt[N_NODES];
__device__ int g_off[N_NODES + 1];
__device__ int g_cur[N_NODES];
__device__ int g_csr[N_EDGES];
__device__ int g_blksum[128];
__device__ int g_blkoff[128];

#define SCAN_B 1024
#define NSCANBLK ((N_NODES + SCAN_B - 1) / SCAN_B)

// ------------------------ CSR build ------------------------------------------
__global__ void k_zero_cnt() {
    int i = blockIdx.x * blockDim.x + threadIdx.x;
    if (i < N_NODES) g_cnt[i] = 0;
}
__global__ void k_hist(const int* __restrict__ dst) {
    int i = blockIdx.x * blockDim.x + threadIdx.x;
    if (i < N_EDGES) atomicAdd(&g_cnt[dst[i]], 1);
}
__global__ void k_scan_block() {
    __shared__ int s[SCAN_B];
    int t = threadIdx.x;
    int i = blockIdx.x * SCAN_B + t;
    int v = (i < N_NODES) ? g_cnt[i] : 0;
    s[t] = v;
    __syncthreads();
    #pragma unroll
    for (int off = 1; off < SCAN_B; off <<= 1) {
        int x = (t >= off) ? s[t - off] : 0;
        __syncthreads();
        s[t] += x;
        __syncthreads();
    }
    if (i < N_NODES) g_off[i + 1] = s[t];
    if (t == SCAN_B - 1) g_blksum[blockIdx.x] = s[t];
}
__global__ void k_scan_top() {
    if (threadIdx.x == 0) {
        int running = 0;
        for (int b = 0; b < NSCANBLK; b++) { g_blkoff[b] = running; running += g_blksum[b]; }
        g_off[0] = 0;
    }
}
__global__ void k_scan_add() {
    int i = blockIdx.x * blockDim.x + threadIdx.x;
    if (i < N_NODES) g_off[i + 1] += g_blkoff[i >> 10];
}
__global__ void k_init_cur() {
    int i = blockIdx.x * blockDim.x + threadIdx.x;
    if (i < N_NODES) g_cur[i] = g_off[i];
}
__global__ void k_fill(const int* __restrict__ src, const int* __restrict__ dst) {
    int i = blockIdx.x * blockDim.x + threadIdx.x;
    if (i < N_EDGES) {
        int d = dst[i];
        int p = atomicAdd(&g_cur[d], 1);
        g_csr[p] = src[i];
    }
}

// ------------------------ input conversions ---------------------------------
__global__ void k_convx(const float* __restrict__ x) {
    int t = blockIdx.x * blockDim.x + threadIdx.x;
    if (t >= MPAD * 64) return;
    int row = t >> 6;
    int c4 = (t & 63) * 4;
    float4 v = make_float4(0.f, 0.f, 0.f, 0.f);
    if (row < N_NODES) v = *(const float4*)(x + (size_t)row * 256 + c4);
    __half hx = __float2half_rn(v.x), hy = __float2half_rn(v.y);
    __half hz = __float2half_rn(v.z), hw = __float2half_rn(v.w);
    __half lx = __float2half_rn(v.x - __half2float(hx));
    __half ly = __float2half_rn(v.y - __half2float(hy));
    __half lz = __float2half_rn(v.z - __half2float(hz));
    __half lw = __float2half_rn(v.w - __half2float(hw));
    size_t o = (size_t)row * 256 + c4;
    *(__half2*)(g_Axhi + o)     = __halves2half2(hx, hy);
    *(__half2*)(g_Axhi + o + 2) = __halves2half2(hz, hw);
    *(__half2*)(g_Axlo + o)     = __halves2half2(lx, ly);
    *(__half2*)(g_Axlo + o + 2) = __halves2half2(lz, lw);
}

// Weights: B[n][k] N-major rows (so mma "col" operand = B^T), hi/lo split.
__global__ void k_prep_w(const float* __restrict__ W_t,
                         const float* __restrict__ W_self0, const float* __restrict__ W_neigh0,
                         const float* __restrict__ W_self1, const float* __restrict__ W_neigh1) {
    int g = blockIdx.x * blockDim.x + threadIdx.x;
    if (g >= 3 * 128 * 256) return;
    int which = g / (128 * 256);
    int r = g % (128 * 256);
    int n = r / 256;
    int k = r % 256;
    float w;
    __half *dh, *dl;
    if (which == 0) { w = W_t[(size_t)k * 128 + n]; dh = g_Bthi; dl = g_Btlo; }
    else if (which == 1) {
        w = (k < 128) ? W_self0[(size_t)k * 128 + n] : W_neigh0[(size_t)(k - 128) * 128 + n];
        dh = g_B0hi; dl = g_B0lo;
    } else {
        w = (k < 128) ? W_self1[(size_t)k * 128 + n] : W_neigh1[(size_t)(k - 128) * 128 + n];
        dh = g_B1hi; dl = g_B1lo;
    }
    __half hi = __float2half_rn(w);
    __half lo = __float2half_rn(w - __half2float(hi));
    dh[(size_t)n * 256 + k] = hi;
    dl[(size_t)n * 256 + k] = lo;
}

// ------------------------ aggregation (warp per node) ------------------------
__global__ void k_aggregate(const float* __restrict__ h,
                            __half* __restrict__ Ahi, __half* __restrict__ Alo) {
    int warp = (blockIdx.x * blockDim.x + threadIdx.x) >> 5;
    int lane = threadIdx.x & 31;
    if (warp >= N_NODES) return;
    int s = g_off[warp];
    int e = g_off[warp + 1];
    float4 acc = make_float4(0.f, 0.f, 0.f, 0.f);
    for (int i = s; i < e; i++) {
        int sc = g_csr[i];
        float4 v = *(const float4*)(h + (size_t)sc * HID + lane * 4);
        acc.x += v.x; acc.y += v.y; acc.z += v.z; acc.w += v.w;
    }
    float inv = 1.f / fmaxf((float)(e - s), 1.f);
    float vx = acc.x * inv, vy = acc.y * inv, vz = acc.z * inv, vw = acc.w * inv;
    __half hx = __float2half_rn(vx), hy = __float2half_rn(vy);
    __half hz = __float2half_rn(vz), hw = __float2half_rn(vw);
    __half lx = __float2half_rn(vx - __half2float(hx));
    __half ly = __float2half_rn(vy - __half2float(hy));
    __half lz = __float2half_rn(vz - __half2float(hz));
    __half lw = __float2half_rn(vw - __half2float(hw));
    size_t o = (size_t)warp * 256 + 128 + lane * 4;
    *(__half2*)(Ahi + o)     = __halves2half2(hx, hy);
    *(__half2*)(Ahi + o + 2) = __halves2half2(hz, hw);
    *(__half2*)(Alo + o)     = __halves2half2(lx, ly);
    *(__half2*)(Alo + o + 2) = __halves2half2(lz, lw);
}

// ------------------------ HMMA GEMM ------------------------------------------
// C[M,128] = relu?(A @ B^T + bias). A = Ahi+Alo [MPAD,256] fp16, B = [128,256] hi/lo.
// 3-term split: D = Ahi*Bhi + Alo*Bhi + Ahi*Blo. mma.sync m16n8k16.
// CTA 256 thr = 8 warps (2x4), warp tile 64x32. K chunks of 64 via smem.
#define SA_STRIDE 72   // halves per row; 144B => conflict-free LDS.b32 frag loads
#define SM_HALVES (4 * 128 * SA_STRIDE)          // Ahi, Alo, Bhi, Blo
#define SMEM_BYTES (SM_HALVES * 2 + 512)         // + bias(128 f32)

__device__ __forceinline__ void hmma(float* d, const uint32_t* a, const uint32_t* b) {
    asm volatile(
        "mma.sync.aligned.m16n8k16.row.col.f32.f16.f16.f32 "
        "{%0,%1,%2,%3}, {%4,%5,%6,%7}, {%8,%9}, {%0,%1,%2,%3};"
        : "+f"(d[0]), "+f"(d[1]), "+f"(d[2]), "+f"(d[3])
        : "r"(a[0]), "r"(a[1]), "r"(a[2]), "r"(a[3]), "r"(b[0]), "r"(b[1]));
}

__global__ __launch_bounds__(256) void k_gemm_mma(
    const __half* __restrict__ Ahi, const __half* __restrict__ Alo,
    const __half* __restrict__ Bhi, const __half* __restrict__ Blo,
    const float* __restrict__ bias, int relu,
    float* __restrict__ C32,
    __half* __restrict__ Chi, __half* __restrict__ Clo)
{
    extern __shared__ __half sm[];
    __half* sAh = sm;
    __half* sAl = sm + 128 * SA_STRIDE;
    __half* sBh = sm + 2 * 128 * SA_STRIDE;
    __half* sBl = sm + 3 * 128 * SA_STRIDE;
    float* sbias = (float*)(sm + SM_HALVES);

    const int tid = threadIdx.x;
    const int wid = tid >> 5;
    const int lane = tid & 31;
    const int wm = wid >> 2;        // 0..1  -> 64 rows
    const int wn = wid & 3;         // 0..3  -> 32 cols
    const int node0 = blockIdx.x * 128;

    if (tid < 128) sbias[tid] = bias[tid];

    float acc[4][4][4];
    #pragma unroll
    for (int i = 0; i < 4; i++)
        #pragma unroll
        for (int j = 0; j < 4; j++)
            #pragma unroll
            for (int q = 0; q < 4; q++) acc[i][j][q] = 0.f;

    const int ar = lane >> 2;          // 0..7
    const int ac = (lane & 3) * 2;     // 0,2,4,6

    #pragma unroll 1
    for (int c = 0; c < 4; c++) {
        __syncthreads();
        // load chunk c: A rows node0..node0+127 cols [c*64, c*64+64), B same cols
        #pragma unroll
        for (int i = tid; i < 1024; i += 256) {
            int r = i >> 3, s = i & 7;
            size_t ga = (size_t)(node0 + r) * 256 + c * 64 + s * 8;
            size_t gb = (size_t)r * 256 + c * 64 + s * 8;
            int so = r * SA_STRIDE + s * 8;
            *(uint4*)(sAh + so) = *(const uint4*)(Ahi + ga);
            *(uint4*)(sAl + so) = *(const uint4*)(Alo + ga);
            *(uint4*)(sBh + so) = *(const uint4*)(Bhi + gb);
            *(uint4*)(sBl + so) = *(const uint4*)(Blo + gb);
        }
        __syncthreads();

        #pragma unroll
        for (int k = 0; k < 4; k++) {
            const int kc = k * 16;
            uint32_t ah[4][4], al[4][4], bb[4][2];
            // A-hi fragments (4 m16 tiles covering 64 rows)
            #pragma unroll
            for (int mt = 0; mt < 4; mt++) {
                int R = wm * 64 + mt * 16 + ar;
                const __half* base = sAh + R * SA_STRIDE + kc + ac;
                ah[mt][0] = *(const uint32_t*)(base);
                ah[mt][1] = *(const uint32_t*)(base + 8 * SA_STRIDE);
                ah[mt][2] = *(const uint32_t*)(base + 8);
                ah[mt][3] = *(const uint32_t*)(base + 8 * SA_STRIDE + 8);
            }
            // B-hi fragments (4 n8 tiles covering 32 cols)
            #pragma unroll
            for (int nt = 0; nt < 4; nt++) {
                int Nr = wn * 32 + nt * 8 + (lane >> 2);
                const __half* base = sBh + Nr * SA_STRIDE + kc + (lane & 3) * 2;
                bb[nt][0] = *(const uint32_t*)(base);
                bb[nt][1] = *(const uint32_t*)(base + 8);
            }
            // term 1: Ahi * Bhi
            #pragma unroll
            for (int mt = 0; mt < 4; mt++)
                #pragma unroll
                for (int nt = 0; nt < 4; nt++)
                    hmma(acc[mt][nt], ah[mt], bb[nt]);
            // A-lo fragments
            #pragma unroll
            for (int mt = 0; mt < 4; mt++) {
                int R = wm * 64 + mt * 16 + ar;
                const __half* base = sAl + R * SA_STRIDE + kc + ac;
                al[mt][0] = *(const uint32_t*)(base);
                al[mt][1] = *(const uint32_t*)(base + 8 * SA_STRIDE);
                al[mt][2] = *(const uint32_t*)(base + 8);
                al[mt][3] = *(const uint32_t*)(base + 8 * SA_STRIDE + 8);
            }
            // term 2: Alo * Bhi
            #pragma unroll
            for (int mt = 0; mt < 4; mt++)
                #pragma unroll
                for (int nt = 0; nt < 4; nt++)
                    hmma(acc[mt][nt], al[mt], bb[nt]);
            // B-lo fragments (overwrite bb)
            #pragma unroll
            for (int nt = 0; nt < 4; nt++) {
                int Nr = wn * 32 + nt * 8 + (lane >> 2);
                const __half* base = sBl + Nr * SA_STRIDE + kc + (lane & 3) * 2;
                bb[nt][0] = *(const uint32_t*)(base);
                bb[nt][1] = *(const uint32_t*)(base + 8);
            }
            // term 3: Ahi * Blo
            #pragma unroll
            for (int mt = 0; mt < 4; mt++)
                #pragma unroll
                for (int nt = 0; nt < 4; nt++)
                    hmma(acc[mt][nt], ah[mt], bb[nt]);
        }
    }
    __syncthreads();

    // epilogue
    #pragma unroll
    for (int mt = 0; mt < 4; mt++) {
        #pragma unroll
        for (int half = 0; half < 2; half++) {
            int node = node0 + wm * 64 + mt * 16 + ar + half * 8;
            #pragma unroll
            for (int nt = 0; nt < 4; nt++) {
                int col = wn * 32 + nt * 8 + ac;
                float v0 = acc[mt][nt][half * 2 + 0] + sbias[col];
                float v1 = acc[mt][nt][half * 2 + 1] + sbias[col + 1];
                if (relu) { v0 = fmaxf(v0, 0.f); v1 = fmaxf(v1, 0.f); }
                *(float2*)(C32 + (size_t)node * 128 + col) = make_float2(v0, v1);
                if (Chi) {
                    __half h0 = __float2half_rn(v0);
                    __half h1 = __float2half_rn(v1);
                    __half l0 = __float2half_rn(v0 - __half2float(h0));
                    __half l1 = __float2half_rn(v1 - __half2float(h1));
                    size_t o = (size_t)node * 256 + col;
                    *(__half2*)(Chi + o) = __halves2half2(h0, h1);
                    *(__half2*)(Clo + o) = __halves2half2(l0, l1);
                }
            }
        }
    }
}

// ------------------------ final projection ----------------------------------
__global__ void k_final(const float* __restrict__ h,
                        const float* __restrict__ Wfin,
                        float* __restrict__ out) {
    int warp = (blockIdx.x * blockDim.x + threadIdx.x) >> 5;
    int lane = threadIdx.x & 31;
    if (warp >= N_NODES) return;
    float4 v = *(const float4*)(h + (size_t)warp * HID + lane * 4);
    float4 w = *(const float4*)(Wfin + lane * 4);
    float s = v.x * w.x + v.y * w.y + v.z * w.z + v.w * w.w;
    #pragma unroll
    for (int o = 16; o; o >>= 1) s += __shfl_xor_sync(0xffffffffu, s, o);
    if (lane == 0) out[warp] = s;
}

// ------------------------ launch ---------------------------------------------
extern "C" void kernel_launch(void* const* d_in, const int* in_sizes, int n_in,
                              void* d_out, int out_size)
{
    const float* x        = (const float*)d_in[0];
    const float* W_t      = (const float*)d_in[1];
    const float* b_t      = (const float*)d_in[2];
    const float* W_self0  = (const float*)d_in[3];
    const float* b_self0  = (const float*)d_in[4];
    const float* W_neigh0 = (const float*)d_in[5];
    const float* W_self1  = (const float*)d_in[6];
    const float* b_self1  = (const float*)d_in[7];
    const float* W_neigh1 = (const float*)d_in[8];
    const float* W_fin    = (const float*)d_in[9];
    const int*   src      = (const int*)d_in[10];
    const int*   dst      = (const int*)d_in[11];
    float* out = (float*)d_out;

    cudaFuncSetAttribute(k_gemm_mma, cudaFuncAttributeMaxDynamicSharedMemorySize,
                         SMEM_BYTES);

    float *h32a, *h32b;
    cudaGetSymbolAddress((void**)&h32a, g_h32a);
    cudaGetSymbolAddress((void**)&h32b, g_h32b);
    __half *Axhi, *Axlo, *A1hi, *A1lo, *A2hi, *A2lo;
    cudaGetSymbolAddress((void**)&Axhi, g_Axhi);
    cudaGetSymbolAddress((void**)&Axlo, g_Axlo);
    cudaGetSymbolAddress((void**)&A1hi, g_A1hi);
    cudaGetSymbolAddress((void**)&A1lo, g_A1lo);
    cudaGetSymbolAddress((void**)&A2hi, g_A2hi);
    cudaGetSymbolAddress((void**)&A2lo, g_A2lo);
    __half *Bthi, *Btlo, *B0hi, *B0lo, *B1hi, *B1lo;
    cudaGetSymbolAddress((void**)&Bthi, g_Bthi);
    cudaGetSymbolAddress((void**)&Btlo, g_Btlo);
    cudaGetSymbolAddress((void**)&B0hi, g_B0hi);
    cudaGetSymbolAddress((void**)&B0lo, g_B0lo);
    cudaGetSymbolAddress((void**)&B1hi, g_B1hi);
    cudaGetSymbolAddress((void**)&B1lo, g_B1lo);

    const int TB = 256;
    dim3 gridNodes((N_NODES + TB - 1) / TB);
    dim3 gridEdges((N_EDGES + TB - 1) / TB);
    dim3 gridWarp((N_NODES * 32 + TB - 1) / TB);

    // CSR build
    k_zero_cnt<<<gridNodes, TB>>>();
    k_hist<<<gridEdges, TB>>>(dst);
    k_scan_block<<<NSCANBLK, SCAN_B>>>();
    k_scan_top<<<1, 32>>>();
    k_scan_add<<<gridNodes, TB>>>();
    k_init_cur<<<gridNodes, TB>>>();
    k_fill<<<gridEdges, TB>>>(src, dst);

    // conversions
    k_convx<<<(MPAD * 64 + TB - 1) / TB, TB>>>(x);
    k_prep_w<<<(3 * 128 * 256 + TB - 1) / TB, TB>>>(W_t, W_self0, W_neigh0, W_self1, W_neigh1);

    // h0 = x @ W_t + b_t
    k_gemm_mma<<<NTILES, 256, SMEM_BYTES>>>(Axhi, Axlo, Bthi, Btlo, b_t, 0,
                                            h32a, A1hi, A1lo);
    // layer 0
    k_aggregate<<<gridWarp, TB>>>(h32a, A1hi, A1lo);
    k_gemm_mma<<<NTILES, 256, SMEM_BYTES>>>(A1hi, A1lo, B0hi, B0lo, b_self0, 1,
                                            h32b, A2hi, A2lo);
    // layer 1
    k_aggregate<<<gridWarp, TB>>>(h32b, A2hi, A2lo);
    k_gemm_mma<<<NTILES, 256, SMEM_BYTES>>>(A2hi, A2lo, B1hi, B1lo, b_self1, 1,
                                            h32a, nullptr, nullptr);
    // out = h2 @ W_fin
    k_final<<<gridWarp, TB>>>(h32a, W_fin, out);
}

// round 4
// speedup vs baseline: 1.6388x; 1.2474x over previous
#include <cuda_runtime.h>
#include <cuda_fp16.h>
#include <cstdint>

#define N_NODES 100000
#define N_EDGES 1600000
#define DIN 256
#define HID 128

#define NTILES 782
#define MPAD (NTILES * 128)      // 100096

// ------------------------ device scratch (no allocation) --------------------
__device__ __align__(128) float  g_h32[(size_t)MPAD * HID];     // GEMM3 out only
__device__ __align__(256) __half g_Axhi[(size_t)MPAD * 256];
__device__ __align__(256) __half g_Axlo[(size_t)MPAD * 256];
__device__ __align__(256) __half g_A1hi[(size_t)MPAD * 256];
__device__ __align__(256) __half g_A1lo[(size_t)MPAD * 256];
__device__ __align__(256) __half g_A2hi[(size_t)MPAD * 256];
__device__ __align__(256) __half g_A2lo[(size_t)MPAD * 256];
__device__ __align__(256) __half g_Bthi[128 * 256];
__device__ __align__(256) __half g_Btlo[128 * 256];
__device__ __align__(256) __half g_B0hi[128 * 256];
__device__ __align__(256) __half g_B0lo[128 * 256];
__device__ __align__(256) __half g_B1hi[128 * 256];
__device__ __align__(256) __half g_B1lo[128 * 256];

__device__ int g_cnt[N_NODES];
__device__ int g_off[N_NODES + 1];
__device__ int g_cur[N_NODES];
__device__ int g_csr[N_EDGES];
__device__ int g_blksum[128];
__device__ int g_blkoff[128];

#define SCAN_B 1024
#define NSCANBLK ((N_NODES + SCAN_B - 1) / SCAN_B)

// ------------------------ helpers --------------------------------------------
__device__ __forceinline__ uint32_t smem_u32(const void* p) {
    uint32_t a;
    asm("{ .reg .u64 t; cvta.to.shared.u64 t, %1; cvt.u32.u64 %0, t; }"
        : "=r"(a) : "l"(p));
    return a;
}
__device__ __forceinline__ void cpa16(uint32_t dst, const void* src) {
    asm volatile("cp.async.cg.shared.global [%0], [%1], 16;" :: "r"(dst), "l"(src));
}
#define CP_COMMIT() asm volatile("cp.async.commit_group;" ::: "memory")

// ------------------------ CSR build ------------------------------------------
__global__ void k_zero_cnt() {
    int i = blockIdx.x * blockDim.x + threadIdx.x;
    if (i < N_NODES) g_cnt[i] = 0;
}
__global__ void k_hist(const int* __restrict__ dst) {
    int i = blockIdx.x * blockDim.x + threadIdx.x;
    if (i < N_EDGES) atomicAdd(&g_cnt[dst[i]], 1);
}
__global__ void k_scan_block() {
    __shared__ int s[SCAN_B];
    int t = threadIdx.x;
    int i = blockIdx.x * SCAN_B + t;
    int v = (i < N_NODES) ? g_cnt[i] : 0;
    s[t] = v;
    __syncthreads();
    #pragma unroll
    for (int off = 1; off < SCAN_B; off <<= 1) {
        int x = (t >= off) ? s[t - off] : 0;
        __syncthreads();
        s[t] += x;
        __syncthreads();
    }
    if (i < N_NODES) g_off[i + 1] = s[t];
    if (t == SCAN_B - 1) g_blksum[blockIdx.x] = s[t];
}
__global__ void k_scan_top() {
    if (threadIdx.x == 0) {
        int running = 0;
        for (int b = 0; b < NSCANBLK; b++) { g_blkoff[b] = running; running += g_blksum[b]; }
        g_off[0] = 0;
    }
}
__global__ void k_scan_add() {
    int i = blockIdx.x * blockDim.x + threadIdx.x;
    if (i < N_NODES) g_off[i + 1] += g_blkoff[i >> 10];
}
__global__ void k_init_cur() {
    int i = blockIdx.x * blockDim.x + threadIdx.x;
    if (i < N_NODES) g_cur[i] = g_off[i];
}
__global__ void k_fill(const int* __restrict__ src, const int* __restrict__ dst) {
    int i = blockIdx.x * blockDim.x + threadIdx.x;
    if (i < N_EDGES) {
        int d = dst[i];
        int p = atomicAdd(&g_cur[d], 1);
        g_csr[p] = src[i];
    }
}

// ------------------------ input conversions ---------------------------------
__global__ void k_convx(const float* __restrict__ x) {
    int t = blockIdx.x * blockDim.x + threadIdx.x;
    if (t >= MPAD * 64) return;
    int row = t >> 6;
    int c4 = (t & 63) * 4;
    float4 v = make_float4(0.f, 0.f, 0.f, 0.f);
    if (row < N_NODES) v = *(const float4*)(x + (size_t)row * 256 + c4);
    __half hx = __float2half_rn(v.x), hy = __float2half_rn(v.y);
    __half hz = __float2half_rn(v.z), hw = __float2half_rn(v.w);
    __half lx = __float2half_rn(v.x - __half2float(hx));
    __half ly = __float2half_rn(v.y - __half2float(hy));
    __half lz = __float2half_rn(v.z - __half2float(hz));
    __half lw = __float2half_rn(v.w - __half2float(hw));
    size_t o = (size_t)row * 256 + c4;
    *(__half2*)(g_Axhi + o)     = __halves2half2(hx, hy);
    *(__half2*)(g_Axhi + o + 2) = __halves2half2(hz, hw);
    *(__half2*)(g_Axlo + o)     = __halves2half2(lx, ly);
    *(__half2*)(g_Axlo + o + 2) = __halves2half2(lz, lw);
}

__global__ void k_prep_w(const float* __restrict__ W_t,
                         const float* __restrict__ W_self0, const float* __restrict__ W_neigh0,
                         const float* __restrict__ W_self1, const float* __restrict__ W_neigh1) {
    int g = blockIdx.x * blockDim.x + threadIdx.x;
    if (g >= 3 * 128 * 256) return;
    int which = g / (128 * 256);
    int r = g % (128 * 256);
    int n = r / 256;
    int k = r % 256;
    float w;
    __half *dh, *dl;
    if (which == 0) { w = W_t[(size_t)k * 128 + n]; dh = g_Bthi; dl = g_Btlo; }
    else if (which == 1) {
        w = (k < 128) ? W_self0[(size_t)k * 128 + n] : W_neigh0[(size_t)(k - 128) * 128 + n];
        dh = g_B0hi; dl = g_B0lo;
    } else {
        w = (k < 128) ? W_self1[(size_t)k * 128 + n] : W_neigh1[(size_t)(k - 128) * 128 + n];
        dh = g_B1hi; dl = g_B1lo;
    }
    __half hi = __float2half_rn(w);
    __half lo = __float2half_rn(w - __half2float(hi));
    dh[(size_t)n * 256 + k] = hi;
    dl[(size_t)n * 256 + k] = lo;
}

// ------------------------ aggregation (warp per node, fp16-hi gather) --------
__global__ void k_aggregate(const __half* __restrict__ Hhi,
                            __half* __restrict__ Ahi, __half* __restrict__ Alo) {
    int warp = (blockIdx.x * blockDim.x + threadIdx.x) >> 5;
    int lane = threadIdx.x & 31;
    if (warp >= N_NODES) return;
    int s = g_off[warp];
    int e = g_off[warp + 1];
    float vx = 0.f, vy = 0.f, vz = 0.f, vw = 0.f;
    for (int i = s; i < e; i++) {
        int sc = g_csr[i];
        // 4 halves (8B) per lane from hi buffer, cols 0..127 of row sc
        uint2 raw = *(const uint2*)(Hhi + (size_t)sc * 256 + lane * 4);
        float2 p0 = __half22float2(*(__half2*)&raw.x);
        float2 p1 = __half22float2(*(__half2*)&raw.y);
        vx += p0.x; vy += p0.y; vz += p1.x; vw += p1.y;
    }
    float inv = 1.f / fmaxf((float)(e - s), 1.f);
    vx *= inv; vy *= inv; vz *= inv; vw *= inv;
    __half hx = __float2half_rn(vx), hy = __float2half_rn(vy);
    __half hz = __float2half_rn(vz), hw = __float2half_rn(vw);
    __half lx = __float2half_rn(vx - __half2float(hx));
    __half ly = __float2half_rn(vy - __half2float(hy));
    __half lz = __float2half_rn(vz - __half2float(hz));
    __half lw = __float2half_rn(vw - __half2float(hw));
    size_t o = (size_t)warp * 256 + 128 + lane * 4;
    *(__half2*)(Ahi + o)     = __halves2half2(hx, hy);
    *(__half2*)(Ahi + o + 2) = __halves2half2(hz, hw);
    *(__half2*)(Alo + o)     = __halves2half2(lx, ly);
    *(__half2*)(Alo + o + 2) = __halves2half2(lz, lw);
}

// ------------------------ HMMA GEMM, cp.async double-buffered ----------------
// C[M,128] = relu?(A @ B^T + bias). 3-term fp16 split. K=256 in 4 chunks of 64,
// 2-stage ping-pong smem. CTA 256 thr = 8 warps (2x4), warp tile 64x32.
#define SA_STRIDE 72                       // halves per row (144 B)
#define TILE_B (128 * SA_STRIDE * 2)       // 18432 bytes per tile
#define STAGE_B (4 * TILE_B)               // Ah, Al, Bh, Bl
#define SMEM_BYTES (2 * STAGE_B + 512)     // + bias

__device__ __forceinline__ void hmma(float* d, const uint32_t* a, const uint32_t* b) {
    asm volatile(
        "mma.sync.aligned.m16n8k16.row.col.f32.f16.f16.f32 "
        "{%0,%1,%2,%3}, {%4,%5,%6,%7}, {%8,%9}, {%0,%1,%2,%3};"
        : "+f"(d[0]), "+f"(d[1]), "+f"(d[2]), "+f"(d[3])
        : "r"(a[0]), "r"(a[1]), "r"(a[2]), "r"(a[3]), "r"(b[0]), "r"(b[1]));
}

__global__ __launch_bounds__(256) void k_gemm_mma(
    const __half* __restrict__ Ahi, const __half* __restrict__ Alo,
    const __half* __restrict__ Bhi, const __half* __restrict__ Blo,
    const float* __restrict__ bias, int relu,
    float* __restrict__ C32,
    __half* __restrict__ Chi, __half* __restrict__ Clo)
{
    extern __shared__ __align__(16) char smem[];
    float* sbias = (float*)(smem + 2 * STAGE_B);

    const int tid = threadIdx.x;
    const int wid = tid >> 5;
    const int lane = tid & 31;
    const int wm = wid >> 2;        // 0..1
    const int wn = wid & 3;         // 0..3
    const int node0 = blockIdx.x * 128;
    const uint32_t sb = smem_u32(smem);

    if (tid < 128) sbias[tid] = bias[tid];

    // prefetch helper data
    const int r0 = tid >> 3;              // row this thread loads (r0, r0+32, ...)
    const int s0 = tid & 7;               // 16B segment within 64-col chunk

    // ---- prefetch chunk 0 into stage 0 ----
    {
        #pragma unroll
        for (int it = 0; it < 4; it++) {
            int r = r0 + it * 32;
            size_t ga = (size_t)(node0 + r) * 256 + s0 * 8;
            size_t gb = (size_t)r * 256 + s0 * 8;
            uint32_t so = (uint32_t)(r * SA_STRIDE + s0 * 8) * 2;
            cpa16(sb + 0 * TILE_B + so, Ahi + ga);
            cpa16(sb + 1 * TILE_B + so, Alo + ga);
            cpa16(sb + 2 * TILE_B + so, Bhi + gb);
            cpa16(sb + 3 * TILE_B + so, Blo + gb);
        }
        CP_COMMIT();
    }

    float acc[4][4][4];
    #pragma unroll
    for (int i = 0; i < 4; i++)
        #pragma unroll
        for (int j = 0; j < 4; j++)
            #pragma unroll
            for (int q = 0; q < 4; q++) acc[i][j][q] = 0.f;

    const int ar = lane >> 2;
    const int ac = (lane & 3) * 2;
    const int br = lane >> 2;
    const int bc = (lane & 3) * 2;

    #pragma unroll 1
    for (int c = 0; c < 4; c++) {
        // prefetch chunk c+1 into opposite stage
        if (c < 3) {
            uint32_t st = ((c + 1) & 1) * STAGE_B;
            #pragma unroll
            for (int it = 0; it < 4; it++) {
                int r = r0 + it * 32;
                size_t ga = (size_t)(node0 + r) * 256 + (c + 1) * 64 + s0 * 8;
                size_t gb = (size_t)r * 256 + (c + 1) * 64 + s0 * 8;
                uint32_t so = (uint32_t)(r * SA_STRIDE + s0 * 8) * 2;
                cpa16(sb + st + 0 * TILE_B + so, Ahi + ga);
                cpa16(sb + st + 1 * TILE_B + so, Alo + ga);
                cpa16(sb + st + 2 * TILE_B + so, Bhi + gb);
                cpa16(sb + st + 3 * TILE_B + so, Blo + gb);
            }
            CP_COMMIT();
            asm volatile("cp.async.wait_group 1;" ::: "memory");
        } else {
            asm volatile("cp.async.wait_group 0;" ::: "memory");
        }
        __syncthreads();

        const char* stg = smem + (c & 1) * STAGE_B;
        const __half* sAh = (const __half*)(stg + 0 * TILE_B);
        const __half* sAl = (const __half*)(stg + 1 * TILE_B);
        const __half* sBh = (const __half*)(stg + 2 * TILE_B);
        const __half* sBl = (const __half*)(stg + 3 * TILE_B);

        #pragma unroll
        for (int k = 0; k < 4; k++) {
            const int kc = k * 16;
            uint32_t ah[4][4], al[4][4], bb[4][2];
            #pragma unroll
            for (int mt = 0; mt < 4; mt++) {
                const __half* base = sAh + (wm * 64 + mt * 16 + ar) * SA_STRIDE + kc + ac;
                ah[mt][0] = *(const uint32_t*)(base);
                ah[mt][1] = *(const uint32_t*)(base + 8 * SA_STRIDE);
                ah[mt][2] = *(const uint32_t*)(base + 8);
                ah[mt][3] = *(const uint32_t*)(base + 8 * SA_STRIDE + 8);
            }
            #pragma unroll
            for (int nt = 0; nt < 4; nt++) {
                const __half* base = sBh + (wn * 32 + nt * 8 + br) * SA_STRIDE + kc + bc;
                bb[nt][0] = *(const uint32_t*)(base);
                bb[nt][1] = *(const uint32_t*)(base + 8);
            }
            #pragma unroll
            for (int mt = 0; mt < 4; mt++)
                #pragma unroll
                for (int nt = 0; nt < 4; nt++)
                    hmma(acc[mt][nt], ah[mt], bb[nt]);
            #pragma unroll
            for (int mt = 0; mt < 4; mt++) {
                const __half* base = sAl + (wm * 64 + mt * 16 + ar) * SA_STRIDE + kc + ac;
                al[mt][0] = *(const uint32_t*)(base);
                al[mt][1] = *(const uint32_t*)(base + 8 * SA_STRIDE);
                al[mt][2] = *(const uint32_t*)(base + 8);
                al[mt][3] = *(const uint32_t*)(base + 8 * SA_STRIDE + 8);
            }
            #pragma unroll
            for (int mt = 0; mt < 4; mt++)
                #pragma unroll
                for (int nt = 0; nt < 4; nt++)
                    hmma(acc[mt][nt], al[mt], bb[nt]);
            #pragma unroll
            for (int nt = 0; nt < 4; nt++) {
                const __half* base = sBl + (wn * 32 + nt * 8 + br) * SA_STRIDE + kc + bc;
                bb[nt][0] = *(const uint32_t*)(base);
                bb[nt][1] = *(const uint32_t*)(base + 8);
            }
            #pragma unroll
            for (int mt = 0; mt < 4; mt++)
                #pragma unroll
                for (int nt = 0; nt < 4; nt++)
                    hmma(acc[mt][nt], ah[mt], bb[nt]);
        }
        __syncthreads();
    }

    // epilogue
    #pragma unroll
    for (int mt = 0; mt < 4; mt++) {
        #pragma unroll
        for (int half = 0; half < 2; half++) {
            int node = node0 + wm * 64 + mt * 16 + ar + half * 8;
            #pragma unroll
            for (int nt = 0; nt < 4; nt++) {
                int col = wn * 32 + nt * 8 + ac;
                float v0 = acc[mt][nt][half * 2 + 0] + sbias[col];
                float v1 = acc[mt][nt][half * 2 + 1] + sbias[col + 1];
                if (relu) { v0 = fmaxf(v0, 0.f); v1 = fmaxf(v1, 0.f); }
                if (C32) {
                    *(float2*)(C32 + (size_t)node * 128 + col) = make_float2(v0, v1);
                } else {
                    __half h0 = __float2half_rn(v0);
                    __half h1 = __float2half_rn(v1);
                    __half l0 = __float2half_rn(v0 - __half2float(h0));
                    __half l1 = __float2half_rn(v1 - __half2float(h1));
                    size_t o = (size_t)node * 256 + col;
                    *(__half2*)(Chi + o) = __halves2half2(h0, h1);
                    *(__half2*)(Clo + o) = __halves2half2(l0, l1);
                }
            }
        }
    }
}

// ------------------------ final projection ----------------------------------
__global__ void k_final(const float* __restrict__ h,
                        const float* __restrict__ Wfin,
                        float* __restrict__ out) {
    int warp = (blockIdx.x * blockDim.x + threadIdx.x) >> 5;
    int lane = threadIdx.x & 31;
    if (warp >= N_NODES) return;
    float4 v = *(const float4*)(h + (size_t)warp * HID + lane * 4);
    float4 w = *(const float4*)(Wfin + lane * 4);
    float s = v.x * w.x + v.y * w.y + v.z * w.z + v.w * w.w;
    #pragma unroll
    for (int o = 16; o; o >>= 1) s += __shfl_xor_sync(0xffffffffu, s, o);
    if (lane == 0) out[warp] = s;
}

// ------------------------ launch ---------------------------------------------
extern "C" void kernel_launch(void* const* d_in, const int* in_sizes, int n_in,
                              void* d_out, int out_size)
{
    const float* x        = (const float*)d_in[0];
    const float* W_t      = (const float*)d_in[1];
    const float* b_t      = (const float*)d_in[2];
    const float* W_self0  = (const float*)d_in[3];
    const float* b_self0  = (const float*)d_in[4];
    const float* W_neigh0 = (const float*)d_in[5];
    const float* W_self1  = (const float*)d_in[6];
    const float* b_self1  = (const float*)d_in[7];
    const float* W_neigh1 = (const float*)d_in[8];
    const float* W_fin    = (const float*)d_in[9];
    const int*   src      = (const int*)d_in[10];
    const int*   dst      = (const int*)d_in[11];
    float* out = (float*)d_out;

    cudaFuncSetAttribute(k_gemm_mma, cudaFuncAttributeMaxDynamicSharedMemorySize,
                         SMEM_BYTES);

    float* h32;
    cudaGetSymbolAddress((void**)&h32, g_h32);
    __half *Axhi, *Axlo, *A1hi, *A1lo, *A2hi, *A2lo;
    cudaGetSymbolAddress((void**)&Axhi, g_Axhi);
    cudaGetSymbolAddress((void**)&Axlo, g_Axlo);
    cudaGetSymbolAddress((void**)&A1hi, g_A1hi);
    cudaGetSymbolAddress((void**)&A1lo, g_A1lo);
    cudaGetSymbolAddress((void**)&A2hi, g_A2hi);
    cudaGetSymbolAddress((void**)&A2lo, g_A2lo);
    __half *Bthi, *Btlo, *B0hi, *B0lo, *B1hi, *B1lo;
    cudaGetSymbolAddress((void**)&Bthi, g_Bthi);
    cudaGetSymbolAddress((void**)&Btlo, g_Btlo);
    cudaGetSymbolAddress((void**)&B0hi, g_B0hi);
    cudaGetSymbolAddress((void**)&B0lo, g_B0lo);
    cudaGetSymbolAddress((void**)&B1hi, g_B1hi);
    cudaGetSymbolAddress((void**)&B1lo, g_B1lo);

    const int TB = 256;
    dim3 gridNodes((N_NODES + TB - 1) / TB);
    dim3 gridEdges((N_EDGES + TB - 1) / TB);
    dim3 gridWarp((N_NODES * 32 + TB - 1) / TB);

    // CSR build
    k_zero_cnt<<<gridNodes, TB>>>();
    k_hist<<<gridEdges, TB>>>(dst);
    k_scan_block<<<NSCANBLK, SCAN_B>>>();
    k_scan_top<<<1, 32>>>();
    k_scan_add<<<gridNodes, TB>>>();
    k_init_cur<<<gridNodes, TB>>>();
    k_fill<<<gridEdges, TB>>>(src, dst);

    // conversions
    k_convx<<<(MPAD * 64 + TB - 1) / TB, TB>>>(x);
    k_prep_w<<<(3 * 128 * 256 + TB - 1) / TB, TB>>>(W_t, W_self0, W_neigh0, W_self1, W_neigh1);

    // h0 = x @ W_t + b_t  -> A1 cols 0..127 (hi/lo)
    k_gemm_mma<<<NTILES, 256, SMEM_BYTES>>>(Axhi, Axlo, Bthi, Btlo, b_t, 0,
                                            nullptr, A1hi, A1lo);
    // layer 0
    k_aggregate<<<gridWarp, TB>>>(A1hi, A1hi, A1lo);
    k_gemm_mma<<<NTILES, 256, SMEM_BYTES>>>(A1hi, A1lo, B0hi, B0lo, b_self0, 1,
                                            nullptr, A2hi, A2lo);
    // layer 1
    k_aggregate<<<gridWarp, TB>>>(A2hi, A2hi, A2lo);
    k_gemm_mma<<<NTILES, 256, SMEM_BYTES>>>(A2hi, A2lo, B1hi, B1lo, b_self1, 1,
                                            h32, nullptr, nullptr);
    // out = h2 @ W_fin
    k_final<<<gridWarp, TB>>>(h32, W_fin, out);
}

// round 5
// speedup vs baseline: 1.6826x; 1.0267x over previous
#include <cuda_runtime.h>
#include <cuda_fp16.h>
#include <cstdint>

#define N_NODES 100000
#define N_EDGES 1600000
#define DIN 256
#define HID 128

#define NTILES 782
#define MPAD (NTILES * 128)      // 100096

// ------------------------ device scratch (no allocation) --------------------
__device__ __align__(256) __half g_Axhi[(size_t)MPAD * 256];
__device__ __align__(256) __half g_Axlo[(size_t)MPAD * 256];
__device__ __align__(256) __half g_A1hi[(size_t)MPAD * 256];
__device__ __align__(256) __half g_A1lo[(size_t)MPAD * 256];
__device__ __align__(256) __half g_A2hi[(size_t)MPAD * 256];
__device__ __align__(256) __half g_A2lo[(size_t)MPAD * 256];
__device__ __align__(256) __half g_Bthi[128 * 256];
__device__ __align__(256) __half g_Btlo[128 * 256];
__device__ __align__(256) __half g_B0hi[128 * 256];
__device__ __align__(256) __half g_B0lo[128 * 256];
__device__ __align__(256) __half g_B1hi[128 * 256];
__device__ __align__(256) __half g_B1lo[128 * 256];

__device__ int g_cnt[N_NODES];
__device__ int g_off[N_NODES + 1];
__device__ int g_cur[N_NODES];
__device__ int g_csr[N_EDGES];
__device__ int g_blksum[128];
__device__ int g_blkoff[128];

#define SCAN_B 1024
#define NSCANBLK ((N_NODES + SCAN_B - 1) / SCAN_B)

// ------------------------ helpers --------------------------------------------
__device__ __forceinline__ uint32_t smem_u32(const void* p) {
    uint32_t a;
    asm("{ .reg .u64 t; cvta.to.shared.u64 t, %1; cvt.u32.u64 %0, t; }"
        : "=r"(a) : "l"(p));
    return a;
}
__device__ __forceinline__ void cpa16(uint32_t dst, const void* src) {
    asm volatile("cp.async.cg.shared.global [%0], [%1], 16;" :: "r"(dst), "l"(src));
}
#define CP_COMMIT() asm volatile("cp.async.commit_group;" ::: "memory")

// ------------------------ CSR build ------------------------------------------
__global__ void k_zero_cnt() {
    int i = blockIdx.x * blockDim.x + threadIdx.x;
    if (i < N_NODES) g_cnt[i] = 0;
}
__global__ void k_hist(const int* __restrict__ dst) {
    int i = blockIdx.x * blockDim.x + threadIdx.x;
    if (i < N_EDGES) atomicAdd(&g_cnt[dst[i]], 1);
}
__global__ void k_scan_block() {
    __shared__ int s[SCAN_B];
    int t = threadIdx.x;
    int i = blockIdx.x * SCAN_B + t;
    int v = (i < N_NODES) ? g_cnt[i] : 0;
    s[t] = v;
    __syncthreads();
    #pragma unroll
    for (int off = 1; off < SCAN_B; off <<= 1) {
        int x = (t >= off) ? s[t - off] : 0;
        __syncthreads();
        s[t] += x;
        __syncthreads();
    }
    if (i < N_NODES) g_off[i + 1] = s[t];
    if (t == SCAN_B - 1) g_blksum[blockIdx.x] = s[t];
}
__global__ void k_scan_top() {
    if (threadIdx.x == 0) {
        int running = 0;
        for (int b = 0; b < NSCANBLK; b++) { g_blkoff[b] = running; running += g_blksum[b]; }
        g_off[0] = 0;
    }
}
__global__ void k_scan_add() {
    int i = blockIdx.x * blockDim.x + threadIdx.x;
    if (i < N_NODES) g_off[i + 1] += g_blkoff[i >> 10];
}
__global__ void k_init_cur() {
    int i = blockIdx.x * blockDim.x + threadIdx.x;
    if (i < N_NODES) g_cur[i] = g_off[i];
}
__global__ void k_fill(const int* __restrict__ src, const int* __restrict__ dst) {
    int i = blockIdx.x * blockDim.x + threadIdx.x;
    if (i < N_EDGES) {
        int d = dst[i];
        int p = atomicAdd(&g_cur[d], 1);
        g_csr[p] = src[i];
    }
}

// ------------------------ input conversions ---------------------------------
__global__ void k_convx(const float* __restrict__ x) {
    int t = blockIdx.x * blockDim.x + threadIdx.x;
    if (t >= MPAD * 64) return;
    int row = t >> 6;
    int c4 = (t & 63) * 4;
    float4 v = make_float4(0.f, 0.f, 0.f, 0.f);
    if (row < N_NODES) v = *(const float4*)(x + (size_t)row * 256 + c4);
    __half hx = __float2half_rn(v.x), hy = __float2half_rn(v.y);
    __half hz = __float2half_rn(v.z), hw = __float2half_rn(v.w);
    __half lx = __float2half_rn(v.x - __half2float(hx));
    __half ly = __float2half_rn(v.y - __half2float(hy));
    __half lz = __float2half_rn(v.z - __half2float(hz));
    __half lw = __float2half_rn(v.w - __half2float(hw));
    size_t o = (size_t)row * 256 + c4;
    *(__half2*)(g_Axhi + o)     = __halves2half2(hx, hy);
    *(__half2*)(g_Axhi + o + 2) = __halves2half2(hz, hw);
    *(__half2*)(g_Axlo + o)     = __halves2half2(lx, ly);
    *(__half2*)(g_Axlo + o + 2) = __halves2half2(lz, lw);
}

__global__ void k_prep_w(const float* __restrict__ W_t,
                         const float* __restrict__ W_self0, const float* __restrict__ W_neigh0,
                         const float* __restrict__ W_self1, const float* __restrict__ W_neigh1) {
    int g = blockIdx.x * blockDim.x + threadIdx.x;
    if (g >= 3 * 128 * 256) return;
    int which = g / (128 * 256);
    int r = g % (128 * 256);
    int n = r / 256;
    int k = r % 256;
    float w;
    __half *dh, *dl;
    if (which == 0) { w = W_t[(size_t)k * 128 + n]; dh = g_Bthi; dl = g_Btlo; }
    else if (which == 1) {
        w = (k < 128) ? W_self0[(size_t)k * 128 + n] : W_neigh0[(size_t)(k - 128) * 128 + n];
        dh = g_B0hi; dl = g_B0lo;
    } else {
        w = (k < 128) ? W_self1[(size_t)k * 128 + n] : W_neigh1[(size_t)(k - 128) * 128 + n];
        dh = g_B1hi; dl = g_B1lo;
    }
    __half hi = __float2half_rn(w);
    __half lo = __float2half_rn(w - __half2float(hi));
    dh[(size_t)n * 256 + k] = hi;
    dl[(size_t)n * 256 + k] = lo;
}

// ------------------------ aggregation (warp per node, unrolled x4) -----------
__global__ void k_aggregate(const __half* __restrict__ Hhi,
                            __half* __restrict__ Ahi, __half* __restrict__ Alo) {
    int warp = (blockIdx.x * blockDim.x + threadIdx.x) >> 5;
    int lane = threadIdx.x & 31;
    if (warp >= N_NODES) return;
    int s = g_off[warp];
    int e = g_off[warp + 1];
    float vx = 0.f, vy = 0.f, vz = 0.f, vw = 0.f;
    int i = s;
    const size_t loff = (size_t)(lane * 4);
    for (; i + 4 <= e; i += 4) {
        int n0 = g_csr[i], n1 = g_csr[i + 1], n2 = g_csr[i + 2], n3 = g_csr[i + 3];
        uint2 r0 = *(const uint2*)(Hhi + (size_t)n0 * 256 + loff);
        uint2 r1 = *(const uint2*)(Hhi + (size_t)n1 * 256 + loff);
        uint2 r2 = *(const uint2*)(Hhi + (size_t)n2 * 256 + loff);
        uint2 r3 = *(const uint2*)(Hhi + (size_t)n3 * 256 + loff);
        float2 a0 = __half22float2(*(__half2*)&r0.x), b0 = __half22float2(*(__half2*)&r0.y);
        float2 a1 = __half22float2(*(__half2*)&r1.x), b1 = __half22float2(*(__half2*)&r1.y);
        float2 a2 = __half22float2(*(__half2*)&r2.x), b2 = __half22float2(*(__half2*)&r2.y);
        float2 a3 = __half22float2(*(__half2*)&r3.x), b3 = __half22float2(*(__half2*)&r3.y);
        vx += (a0.x + a1.x) + (a2.x + a3.x);
        vy += (a0.y + a1.y) + (a2.y + a3.y);
        vz += (b0.x + b1.x) + (b2.x + b3.x);
        vw += (b0.y + b1.y) + (b2.y + b3.y);
    }
    for (; i < e; i++) {
        int sc = g_csr[i];
        uint2 raw = *(const uint2*)(Hhi + (size_t)sc * 256 + loff);
        float2 p0 = __half22float2(*(__half2*)&raw.x);
        float2 p1 = __half22float2(*(__half2*)&raw.y);
        vx += p0.x; vy += p0.y; vz += p1.x; vw += p1.y;
    }
    float inv = 1.f / fmaxf((float)(e - s), 1.f);
    vx *= inv; vy *= inv; vz *= inv; vw *= inv;
    __half hx = __float2half_rn(vx), hy = __float2half_rn(vy);
    __half hz = __float2half_rn(vz), hw = __float2half_rn(vw);
    __half lx = __float2half_rn(vx - __half2float(hx));
    __half ly = __float2half_rn(vy - __half2float(hy));
    __half lz = __float2half_rn(vz - __half2float(hz));
    __half lw = __float2half_rn(vw - __half2float(hw));
    size_t o = (size_t)warp * 256 + 128 + loff;
    *(__half2*)(Ahi + o)     = __halves2half2(hx, hy);
    *(__half2*)(Ahi + o + 2) = __halves2half2(hz, hw);
    *(__half2*)(Alo + o)     = __halves2half2(lx, ly);
    *(__half2*)(Alo + o + 2) = __halves2half2(lz, lw);
}

// ------------------------ HMMA GEMM, cp.async double-buffered ----------------
#define SA_STRIDE 72                       // halves per row (144 B)
#define TILE_B (128 * SA_STRIDE * 2)       // 18432 bytes per tile
#define STAGE_B (4 * TILE_B)               // Ah, Al, Bh, Bl
// after stages: bias(512) + wfin(512) + sred(2048)
#define SMEM_BYTES (2 * STAGE_B + 512 + 512 + 2048)

__device__ __forceinline__ void hmma(float* d, const uint32_t* a, const uint32_t* b) {
    asm volatile(
        "mma.sync.aligned.m16n8k16.row.col.f32.f16.f16.f32 "
        "{%0,%1,%2,%3}, {%4,%5,%6,%7}, {%8,%9}, {%0,%1,%2,%3};"
        : "+f"(d[0]), "+f"(d[1]), "+f"(d[2]), "+f"(d[3])
        : "r"(a[0]), "r"(a[1]), "r"(a[2]), "r"(a[3]), "r"(b[0]), "r"(b[1]));
}

__global__ __launch_bounds__(256) void k_gemm_mma(
    const __half* __restrict__ Ahi, const __half* __restrict__ Alo,
    const __half* __restrict__ Bhi, const __half* __restrict__ Blo,
    const float* __restrict__ bias, int relu,
    __half* __restrict__ Chi, __half* __restrict__ Clo,
    const float* __restrict__ Wfin, float* __restrict__ outv)
{
    extern __shared__ __align__(16) char smem[];
    float* sbias = (float*)(smem + 2 * STAGE_B);
    float* swfin = (float*)(smem + 2 * STAGE_B + 512);
    float (*sred)[4] = (float (*)[4])(smem + 2 * STAGE_B + 1024);

    const int tid = threadIdx.x;
    const int wid = tid >> 5;
    const int lane = tid & 31;
    const int wm = wid >> 2;
    const int wn = wid & 3;
    const int node0 = blockIdx.x * 128;
    const uint32_t sb = smem_u32(smem);

    if (tid < 128) {
        sbias[tid] = bias[tid];
        if (Wfin) {
            swfin[tid] = Wfin[tid];
            sred[tid][0] = sred[tid][1] = sred[tid][2] = sred[tid][3] = 0.f;
        }
    }

    const int r0 = tid >> 3;
    const int s0 = tid & 7;

    {
        #pragma unroll
        for (int it = 0; it < 4; it++) {
            int r = r0 + it * 32;
            size_t ga = (size_t)(node0 + r) * 256 + s0 * 8;
            size_t gb = (size_t)r * 256 + s0 * 8;
            uint32_t so = (uint32_t)(r * SA_STRIDE + s0 * 8) * 2;
            cpa16(sb + 0 * TILE_B + so, Ahi + ga);
            cpa16(sb + 1 * TILE_B + so, Alo + ga);
            cpa16(sb + 2 * TILE_B + so, Bhi + gb);
            cpa16(sb + 3 * TILE_B + so, Blo + gb);
        }
        CP_COMMIT();
    }

    float acc[4][4][4];
    #pragma unroll
    for (int i = 0; i < 4; i++)
        #pragma unroll
        for (int j = 0; j < 4; j++)
            #pragma unroll
            for (int q = 0; q < 4; q++) acc[i][j][q] = 0.f;

    const int ar = lane >> 2;
    const int ac = (lane & 3) * 2;

    #pragma unroll 1
    for (int c = 0; c < 4; c++) {
        if (c < 3) {
            uint32_t st = ((c + 1) & 1) * STAGE_B;
            #pragma unroll
            for (int it = 0; it < 4; it++) {
                int r = r0 + it * 32;
                size_t ga = (size_t)(node0 + r) * 256 + (c + 1) * 64 + s0 * 8;
                size_t gb = (size_t)r * 256 + (c + 1) * 64 + s0 * 8;
                uint32_t so = (uint32_t)(r * SA_STRIDE + s0 * 8) * 2;
                cpa16(sb + st + 0 * TILE_B + so, Ahi + ga);
                cpa16(sb + st + 1 * TILE_B + so, Alo + ga);
                cpa16(sb + st + 2 * TILE_B + so, Bhi + gb);
                cpa16(sb + st + 3 * TILE_B + so, Blo + gb);
            }
            CP_COMMIT();
            asm volatile("cp.async.wait_group 1;" ::: "memory");
        } else {
            asm volatile("cp.async.wait_group 0;" ::: "memory");
        }
        __syncthreads();

        const char* stg = smem + (c & 1) * STAGE_B;
        const __half* sAh = (const __half*)(stg + 0 * TILE_B);
        const __half* sAl = (const __half*)(stg + 1 * TILE_B);
        const __half* sBh = (const __half*)(stg + 2 * TILE_B);
        const __half* sBl = (const __half*)(stg + 3 * TILE_B);

        #pragma unroll
        for (int k = 0; k < 4; k++) {
            const int kc = k * 16;
            uint32_t ah[4][4], al[4][4], bb[4][2];
            #pragma unroll
            for (int mt = 0; mt < 4; mt++) {
                const __half* base = sAh + (wm * 64 + mt * 16 + ar) * SA_STRIDE + kc + ac;
                ah[mt][0] = *(const uint32_t*)(base);
                ah[mt][1] = *(const uint32_t*)(base + 8 * SA_STRIDE);
                ah[mt][2] = *(const uint32_t*)(base + 8);
                ah[mt][3] = *(const uint32_t*)(base + 8 * SA_STRIDE + 8);
            }
            #pragma unroll
            for (int nt = 0; nt < 4; nt++) {
                const __half* base = sBh + (wn * 32 + nt * 8 + ar) * SA_STRIDE + kc + ac;
                bb[nt][0] = *(const uint32_t*)(base);
                bb[nt][1] = *(const uint32_t*)(base + 8);
            }
            #pragma unroll
            for (int mt = 0; mt < 4; mt++)
                #pragma unroll
                for (int nt = 0; nt < 4; nt++)
                    hmma(acc[mt][nt], ah[mt], bb[nt]);
            #pragma unroll
            for (int mt = 0; mt < 4; mt++) {
                const __half* base = sAl + (wm * 64 + mt * 16 + ar) * SA_STRIDE + kc + ac;
                al[mt][0] = *(const uint32_t*)(base);
                al[mt][1] = *(const uint32_t*)(base + 8 * SA_STRIDE);
                al[mt][2] = *(const uint32_t*)(base + 8);
                al[mt][3] = *(const uint32_t*)(base + 8 * SA_STRIDE + 8);
            }
            #pragma unroll
            for (int mt = 0; mt < 4; mt++)
                #pragma unroll
                for (int nt = 0; nt < 4; nt++)
                    hmma(acc[mt][nt], al[mt], bb[nt]);
            #pragma unroll
            for (int nt = 0; nt < 4; nt++) {
                const __half* base = sBl + (wn * 32 + nt * 8 + ar) * SA_STRIDE + kc + ac;
                bb[nt][0] = *(const uint32_t*)(base);
                bb[nt][1] = *(const uint32_t*)(base + 8);
            }
            #pragma unroll
            for (int mt = 0; mt < 4; mt++)
                #pragma unroll
                for (int nt = 0; nt < 4; nt++)
                    hmma(acc[mt][nt], ah[mt], bb[nt]);
        }
        __syncthreads();
    }

    if (outv) {
        // fused: out[node] = relu(acc + bias) . Wfin
        #pragma unroll
        for (int mt = 0; mt < 4; mt++) {
            #pragma unroll
            for (int half = 0; half < 2; half++) {
                int rloc = wm * 64 + mt * 16 + ar + half * 8;
                float p = 0.f;
                #pragma unroll
                for (int nt = 0; nt < 4; nt++) {
                    int col = wn * 32 + nt * 8 + ac;
                    float v0 = acc[mt][nt][half * 2 + 0] + sbias[col];
                    float v1 = acc[mt][nt][half * 2 + 1] + sbias[col + 1];
                    if (relu) { v0 = fmaxf(v0, 0.f); v1 = fmaxf(v1, 0.f); }
                    p += v0 * swfin[col] + v1 * swfin[col + 1];
                }
                p += __shfl_xor_sync(0xffffffffu, p, 1);
                p += __shfl_xor_sync(0xffffffffu, p, 2);
                if ((lane & 3) == 0) sred[rloc][wn] = p;
            }
        }
        __syncthreads();
        if (tid < 128) {
            int node = node0 + tid;
            if (node < N_NODES)
                outv[node] = (sred[tid][0] + sred[tid][1]) + (sred[tid][2] + sred[tid][3]);
        }
        return;
    }

    // epilogue: write hi/lo halves for next layer
    #pragma unroll
    for (int mt = 0; mt < 4; mt++) {
        #pragma unroll
        for (int half = 0; half < 2; half++) {
            int node = node0 + wm * 64 + mt * 16 + ar + half * 8;
            #pragma unroll
            for (int nt = 0; nt < 4; nt++) {
                int col = wn * 32 + nt * 8 + ac;
                float v0 = acc[mt][nt][half * 2 + 0] + sbias[col];
                float v1 = acc[mt][nt][half * 2 + 1] + sbias[col + 1];
                if (relu) { v0 = fmaxf(v0, 0.f); v1 = fmaxf(v1, 0.f); }
                __half h0 = __float2half_rn(v0);
                __half h1 = __float2half_rn(v1);
                __half l0 = __float2half_rn(v0 - __half2float(h0));
                __half l1 = __float2half_rn(v1 - __half2float(h1));
                size_t o = (size_t)node * 256 + col;
                *(__half2*)(Chi + o) = __halves2half2(h0, h1);
                *(__half2*)(Clo + o) = __halves2half2(l0, l1);
            }
        }
    }
}

// ------------------------ launch ---------------------------------------------
extern "C" void kernel_launch(void* const* d_in, const int* in_sizes, int n_in,
                              void* d_out, int out_size)
{
    const float* x        = (const float*)d_in[0];
    const float* W_t      = (const float*)d_in[1];
    const float* b_t      = (const float*)d_in[2];
    const float* W_self0  = (const float*)d_in[3];
    const float* b_self0  = (const float*)d_in[4];
    const float* W_neigh0 = (const float*)d_in[5];
    const float* W_self1  = (const float*)d_in[6];
    const float* b_self1  = (const float*)d_in[7];
    const float* W_neigh1 = (const float*)d_in[8];
    const float* W_fin    = (const float*)d_in[9];
    const int*   src      = (const int*)d_in[10];
    const int*   dst      = (const int*)d_in[11];
    float* out = (float*)d_out;

    cudaFuncSetAttribute(k_gemm_mma, cudaFuncAttributeMaxDynamicSharedMemorySize,
                         SMEM_BYTES);

    __half *Axhi, *Axlo, *A1hi, *A1lo, *A2hi, *A2lo;
    cudaGetSymbolAddress((void**)&Axhi, g_Axhi);
    cudaGetSymbolAddress((void**)&Axlo, g_Axlo);
    cudaGetSymbolAddress((void**)&A1hi, g_A1hi);
    cudaGetSymbolAddress((void**)&A1lo, g_A1lo);
    cudaGetSymbolAddress((void**)&A2hi, g_A2hi);
    cudaGetSymbolAddress((void**)&A2lo, g_A2lo);
    __half *Bthi, *Btlo, *B0hi, *B0lo, *B1hi, *B1lo;
    cudaGetSymbolAddress((void**)&Bthi, g_Bthi);
    cudaGetSymbolAddress((void**)&Btlo, g_Btlo);
    cudaGetSymbolAddress((void**)&B0hi, g_B0hi);
    cudaGetSymbolAddress((void**)&B0lo, g_B0lo);
    cudaGetSymbolAddress((void**)&B1hi, g_B1hi);
    cudaGetSymbolAddress((void**)&B1lo, g_B1lo);

    const int TB = 256;
    dim3 gridNodes((N_NODES + TB - 1) / TB);
    dim3 gridEdges((N_EDGES + TB - 1) / TB);
    dim3 gridWarp((N_NODES * 32 + TB - 1) / TB);

    // CSR build
    k_zero_cnt<<<gridNodes, TB>>>();
    k_hist<<<gridEdges, TB>>>(dst);
    k_scan_block<<<NSCANBLK, SCAN_B>>>();
    k_scan_top<<<1, 32>>>();
    k_scan_add<<<gridNodes, TB>>>();
    k_init_cur<<<gridNodes, TB>>>();
    k_fill<<<gridEdges, TB>>>(src, dst);

    // conversions
    k_convx<<<(MPAD * 64 + TB - 1) / TB, TB>>>(x);
    k_prep_w<<<(3 * 128 * 256 + TB - 1) / TB, TB>>>(W_t, W_self0, W_neigh0, W_self1, W_neigh1);

    // h0 = x @ W_t + b_t  -> A1 cols 0..127 (hi/lo)
    k_gemm_mma<<<NTILES, 256, SMEM_BYTES>>>(Axhi, Axlo, Bthi, Btlo, b_t, 0,
                                            A1hi, A1lo, nullptr, nullptr);
    // layer 0
    k_aggregate<<<gridWarp, TB>>>(A1hi, A1hi, A1lo);
    k_gemm_mma<<<NTILES, 256, SMEM_BYTES>>>(A1hi, A1lo, B0hi, B0lo, b_self0, 1,
                                            A2hi, A2lo, nullptr, nullptr);
    // layer 1
    k_aggregate<<<gridWarp, TB>>>(A2hi, A2hi, A2lo);
    // GEMM3 fused with final projection: out = relu(...) @ W_fin
    k_gemm_mma<<<NTILES, 256, SMEM_BYTES>>>(A2hi, A2lo, B1hi, B1lo, b_self1, 1,
                                            nullptr, nullptr, W_fin, out);
}

// round 6
// speedup vs baseline: 1.7420x; 1.0354x over previous
#include <cuda_runtime.h>
#include <cuda_fp16.h>
#include <cstdint>

#define N_NODES 100000
#define N_EDGES 1600000
#define DIN 256
#define HID 128

#define NTILES 782
#define MPAD (NTILES * 128)      // 100096

// ------------------------ device scratch (no allocation) --------------------
__device__ __align__(256) __half g_Axhi[(size_t)MPAD * 256];
__device__ __align__(256) __half g_Axlo[(size_t)MPAD * 256];
__device__ __align__(256) __half g_A1hi[(size_t)MPAD * 256];
__device__ __align__(256) __half g_A1lo[(size_t)MPAD * 256];
__device__ __align__(256) __half g_A2hi[(size_t)MPAD * 256];
__device__ __align__(256) __half g_A2lo[(size_t)MPAD * 256];
__device__ __align__(256) __half g_Bthi[128 * 256];
__device__ __align__(256) __half g_Btlo[128 * 256];
__device__ __align__(256) __half g_B0hi[128 * 256];
__device__ __align__(256) __half g_B0lo[128 * 256];
__device__ __align__(256) __half g_B1hi[128 * 256];
__device__ __align__(256) __half g_B1lo[128 * 256];

__device__ int g_cnt[N_NODES];
__device__ int g_off[N_NODES + 1];
__device__ int g_cur[N_NODES];
__device__ int g_csr[N_EDGES];
__device__ int g_blksum[128];
__device__ int g_blkoff[128];

#define SCAN_B 1024
#define NSCANBLK ((N_NODES + SCAN_B - 1) / SCAN_B)   // 98

// ------------------------ helpers --------------------------------------------
__device__ __forceinline__ uint32_t smem_u32(const void* p) {
    uint32_t a;
    asm("{ .reg .u64 t; cvta.to.shared.u64 t, %1; cvt.u32.u64 %0, t; }"
        : "=r"(a) : "l"(p));
    return a;
}
__device__ __forceinline__ void cpa16(uint32_t dst, const void* src) {
    asm volatile("cp.async.cg.shared.global [%0], [%1], 16;" :: "r"(dst), "l"(src));
}
#define CP_COMMIT() asm volatile("cp.async.commit_group;" ::: "memory")

__device__ __forceinline__ void ldsm4(uint32_t* r, uint32_t addr) {
    asm volatile("ldmatrix.sync.aligned.m8n8.x4.shared.b16 {%0,%1,%2,%3}, [%4];"
                 : "=r"(r[0]), "=r"(r[1]), "=r"(r[2]), "=r"(r[3]) : "r"(addr));
}
__device__ __forceinline__ void hmma(float* d, const uint32_t* a, const uint32_t* b) {
    asm volatile(
        "mma.sync.aligned.m16n8k16.row.col.f32.f16.f16.f32 "
        "{%0,%1,%2,%3}, {%4,%5,%6,%7}, {%8,%9}, {%0,%1,%2,%3};"
        : "+f"(d[0]), "+f"(d[1]), "+f"(d[2]), "+f"(d[3])
        : "r"(a[0]), "r"(a[1]), "r"(a[2]), "r"(a[3]), "r"(b[0]), "r"(b[1]));
}

// ------------------------ input conversions ---------------------------------
__global__ void k_convx(const float* __restrict__ x) {
    int t = blockIdx.x * blockDim.x + threadIdx.x;
    if (t >= MPAD * 64) return;
    int row = t >> 6;
    int c4 = (t & 63) * 4;
    float4 v = make_float4(0.f, 0.f, 0.f, 0.f);
    if (row < N_NODES) v = *(const float4*)(x + (size_t)row * 256 + c4);
    __half hx = __float2half_rn(v.x), hy = __float2half_rn(v.y);
    __half hz = __float2half_rn(v.z), hw = __float2half_rn(v.w);
    __half lx = __float2half_rn(v.x - __half2float(hx));
    __half ly = __float2half_rn(v.y - __half2float(hy));
    __half lz = __float2half_rn(v.z - __half2float(hz));
    __half lw = __float2half_rn(v.w - __half2float(hw));
    size_t o = (size_t)row * 256 + c4;
    *(__half2*)(g_Axhi + o)     = __halves2half2(hx, hy);
    *(__half2*)(g_Axhi + o + 2) = __halves2half2(hz, hw);
    *(__half2*)(g_Axlo + o)     = __halves2half2(lx, ly);
    *(__half2*)(g_Axlo + o + 2) = __halves2half2(lz, lw);
}

__global__ void k_prep_w(const float* __restrict__ W_t,
                         const float* __restrict__ W_self0, const float* __restrict__ W_neigh0,
                         const float* __restrict__ W_self1, const float* __restrict__ W_neigh1) {
    int g = blockIdx.x * blockDim.x + threadIdx.x;
    if (g >= 3 * 128 * 256) return;
    int which = g / (128 * 256);
    int r = g % (128 * 256);
    int n = r / 256;
    int k = r % 256;
    float w;
    __half *dh, *dl;
    if (which == 0) { w = W_t[(size_t)k * 128 + n]; dh = g_Bthi; dl = g_Btlo; }
    else if (which == 1) {
        w = (k < 128) ? W_self0[(size_t)k * 128 + n] : W_neigh0[(size_t)(k - 128) * 128 + n];
        dh = g_B0hi; dl = g_B0lo;
    } else {
        w = (k < 128) ? W_self1[(size_t)k * 128 + n] : W_neigh1[(size_t)(k - 128) * 128 + n];
        dh = g_B1hi; dl = g_B1lo;
    }
    __half hi = __float2half_rn(w);
    __half lo = __float2half_rn(w - __half2float(hi));
    dh[(size_t)n * 256 + k] = hi;
    dl[(size_t)n * 256 + k] = lo;
}

// ------------------------ CSR build ------------------------------------------
__global__ void k_zero_cnt() {
    int i = blockIdx.x * blockDim.x + threadIdx.x;
    if (i < N_NODES) g_cnt[i] = 0;
}
__global__ void k_hist(const int* __restrict__ dst) {
    int i = blockIdx.x * blockDim.x + threadIdx.x;
    if (i < N_EDGES) atomicAdd(&g_cnt[dst[i]], 1);
}
__global__ void k_scan_block() {
    __shared__ int s[SCAN_B];
    int t = threadIdx.x;
    int i = blockIdx.x * SCAN_B + t;
    int v = (i < N_NODES) ? g_cnt[i] : 0;
    s[t] = v;
    __syncthreads();
    #pragma unroll
    for (int off = 1; off < SCAN_B; off <<= 1) {
        int x = (t >= off) ? s[t - off] : 0;
        __syncthreads();
        s[t] += x;
        __syncthreads();
    }
    if (i < N_NODES) g_off[i + 1] = s[t];
    if (t == SCAN_B - 1) g_blksum[blockIdx.x] = s[t];
}
// parallel top-level exclusive scan over NSCANBLK block sums (1 block, 128 thr)
__global__ void k_scan_top() {
    __shared__ int s[128];
    int t = threadIdx.x;
    int v = (t < NSCANBLK) ? g_blksum[t] : 0;
    s[t] = v;
    __syncthreads();
    #pragma unroll
    for (int off = 1; off < 128; off <<= 1) {
        int x = (t >= off) ? s[t - off] : 0;
        __syncthreads();
        s[t] += x;
        __syncthreads();
    }
    if (t < NSCANBLK) g_blkoff[t] = s[t] - v;   // exclusive
    if (t == 0) { g_off[0] = 0; g_cur[0] = 0; }
}
// finalize g_off[i+1] and mirror into g_cur[i+1]
__global__ void k_scan_fin() {
    int i = blockIdx.x * blockDim.x + threadIdx.x;
    if (i < N_NODES) {
        int v = g_off[i + 1] + g_blkoff[i >> 10];
        g_off[i + 1] = v;
        if (i + 1 < N_NODES) g_cur[i + 1] = v;
    }
}
__global__ void k_fill(const int* __restrict__ src, const int* __restrict__ dst) {
    int i = blockIdx.x * blockDim.x + threadIdx.x;
    if (i < N_EDGES) {
        int d = dst[i];
        int p = atomicAdd(&g_cur[d], 1);
        g_csr[p] = src[i];
    }
}

// ------------------------ aggregation (warp per node, unrolled x4) -----------
__global__ void k_aggregate(const __half* __restrict__ Hhi,
                            __half* __restrict__ Ahi, __half* __restrict__ Alo) {
    int warp = (blockIdx.x * blockDim.x + threadIdx.x) >> 5;
    int lane = threadIdx.x & 31;
    if (warp >= N_NODES) return;
    int s = g_off[warp];
    int e = g_off[warp + 1];
    float vx = 0.f, vy = 0.f, vz = 0.f, vw = 0.f;
    int i = s;
    const size_t loff = (size_t)(lane * 4);
    for (; i + 4 <= e; i += 4) {
        int n0 = g_csr[i], n1 = g_csr[i + 1], n2 = g_csr[i + 2], n3 = g_csr[i + 3];
        uint2 r0 = *(const uint2*)(Hhi + (size_t)n0 * 256 + loff);
        uint2 r1 = *(const uint2*)(Hhi + (size_t)n1 * 256 + loff);
        uint2 r2 = *(const uint2*)(Hhi + (size_t)n2 * 256 + loff);
        uint2 r3 = *(const uint2*)(Hhi + (size_t)n3 * 256 + loff);
        float2 a0 = __half22float2(*(__half2*)&r0.x), b0 = __half22float2(*(__half2*)&r0.y);
        float2 a1 = __half22float2(*(__half2*)&r1.x), b1 = __half22float2(*(__half2*)&r1.y);
        float2 a2 = __half22float2(*(__half2*)&r2.x), b2 = __half22float2(*(__half2*)&r2.y);
        float2 a3 = __half22float2(*(__half2*)&r3.x), b3 = __half22float2(*(__half2*)&r3.y);
        vx += (a0.x + a1.x) + (a2.x + a3.x);
        vy += (a0.y + a1.y) + (a2.y + a3.y);
        vz += (b0.x + b1.x) + (b2.x + b3.x);
        vw += (b0.y + b1.y) + (b2.y + b3.y);
    }
    for (; i < e; i++) {
        int sc = g_csr[i];
        uint2 raw = *(const uint2*)(Hhi + (size_t)sc * 256 + loff);
        float2 p0 = __half22float2(*(__half2*)&raw.x);
        float2 p1 = __half22float2(*(__half2*)&raw.y);
        vx += p0.x; vy += p0.y; vz += p1.x; vw += p1.y;
    }
    float inv = 1.f / fmaxf((float)(e - s), 1.f);
    vx *= inv; vy *= inv; vz *= inv; vw *= inv;
    __half hx = __float2half_rn(vx), hy = __float2half_rn(vy);
    __half hz = __float2half_rn(vz), hw = __float2half_rn(vw);
    __half lx = __float2half_rn(vx - __half2float(hx));
    __half ly = __float2half_rn(vy - __half2float(hy));
    __half lz = __float2half_rn(vz - __half2float(hz));
    __half lw = __float2half_rn(vw - __half2float(hw));
    size_t o = (size_t)warp * 256 + 128 + loff;
    *(__half2*)(Ahi + o)     = __halves2half2(hx, hy);
    *(__half2*)(Ahi + o + 2) = __halves2half2(hz, hw);
    *(__half2*)(Alo + o)     = __halves2half2(lx, ly);
    *(__half2*)(Alo + o + 2) = __halves2half2(lz, lw);
}

// ------------------------ HMMA GEMM, cp.async double-buffered, ldmatrix ------
#define SA_STRIDE 72                       // halves per row (144 B)
#define TILE_B (128 * SA_STRIDE * 2)       // 18432 bytes per tile
#define STAGE_B (4 * TILE_B)               // Ah, Al, Bh, Bl
#define SMEM_BYTES (2 * STAGE_B + 512 + 512 + 2048)

__global__ __launch_bounds__(256) void k_gemm_mma(
    const __half* __restrict__ Ahi, const __half* __restrict__ Alo,
    const __half* __restrict__ Bhi, const __half* __restrict__ Blo,
    const float* __restrict__ bias, int relu,
    __half* __restrict__ Chi, __half* __restrict__ Clo,
    const float* __restrict__ Wfin, float* __restrict__ outv)
{
    extern __shared__ __align__(16) char smem[];
    float* sbias = (float*)(smem + 2 * STAGE_B);
    float* swfin = (float*)(smem + 2 * STAGE_B + 512);
    float (*sred)[4] = (float (*)[4])(smem + 2 * STAGE_B + 1024);

    const int tid = threadIdx.x;
    const int wid = tid >> 5;
    const int lane = tid & 31;
    const int wm = wid >> 2;
    const int wn = wid & 3;
    const int node0 = blockIdx.x * 128;
    const uint32_t sb = smem_u32(smem);

    if (tid < 128) {
        sbias[tid] = bias[tid];
        if (Wfin) {
            swfin[tid] = Wfin[tid];
            sred[tid][0] = sred[tid][1] = sred[tid][2] = sred[tid][3] = 0.f;
        }
    }

    const int r0 = tid >> 3;
    const int s0 = tid & 7;

    {
        #pragma unroll
        for (int it = 0; it < 4; it++) {
            int r = r0 + it * 32;
            size_t ga = (size_t)(node0 + r) * 256 + s0 * 8;
            size_t gb = (size_t)r * 256 + s0 * 8;
            uint32_t so = (uint32_t)(r * SA_STRIDE + s0 * 8) * 2;
            cpa16(sb + 0 * TILE_B + so, Ahi + ga);
            cpa16(sb + 1 * TILE_B + so, Alo + ga);
            cpa16(sb + 2 * TILE_B + so, Bhi + gb);
            cpa16(sb + 3 * TILE_B + so, Blo + gb);
        }
        CP_COMMIT();
    }

    float acc[4][4][4];
    #pragma unroll
    for (int i = 0; i < 4; i++)
        #pragma unroll
        for (int j = 0; j < 4; j++)
            #pragma unroll
            for (int q = 0; q < 4; q++) acc[i][j][q] = 0.f;

    // ldmatrix per-lane byte offsets (within a tile)
    // A x4 tile (16x16): row = m_base + (lane&15), col8 = (lane>>4)*8
    const uint32_t a_off =
        (uint32_t)(((wm * 64 + (lane & 15)) * SA_STRIDE + (lane >> 4) * 8) * 2);
    // B x4 covering two n8 tiles: row = n_base + (lane&7) + (lane>>4)*8,
    // col8 = ((lane>>3)&1)*8
    const uint32_t b_off =
        (uint32_t)(((wn * 32 + (lane & 7) + (lane >> 4) * 8) * SA_STRIDE +
                    ((lane >> 3) & 1) * 8) * 2);

    const int ar = lane >> 2;
    const int ac = (lane & 3) * 2;

    #pragma unroll 1
    for (int c = 0; c < 4; c++) {
        if (c < 3) {
            uint32_t st = ((c + 1) & 1) * STAGE_B;
            #pragma unroll
            for (int it = 0; it < 4; it++) {
                int r = r0 + it * 32;
                size_t ga = (size_t)(node0 + r) * 256 + (c + 1) * 64 + s0 * 8;
                size_t gb = (size_t)r * 256 + (c + 1) * 64 + s0 * 8;
                uint32_t so = (uint32_t)(r * SA_STRIDE + s0 * 8) * 2;
                cpa16(sb + st + 0 * TILE_B + so, Ahi + ga);
                cpa16(sb + st + 1 * TILE_B + so, Alo + ga);
                cpa16(sb + st + 2 * TILE_B + so, Bhi + gb);
                cpa16(sb + st + 3 * TILE_B + so, Blo + gb);
            }
            CP_COMMIT();
            asm volatile("cp.async.wait_group 1;" ::: "memory");
        } else {
            asm volatile("cp.async.wait_group 0;" ::: "memory");
        }
        __syncthreads();

        const uint32_t stg = sb + (c & 1) * STAGE_B;
        const uint32_t aH = stg + 0 * TILE_B + a_off;
        const uint32_t aL = stg + 1 * TILE_B + a_off;
        const uint32_t bH = stg + 2 * TILE_B + b_off;
        const uint32_t bL = stg + 3 * TILE_B + b_off;

        #pragma unroll
        for (int k = 0; k < 4; k++) {
            const uint32_t kb = (uint32_t)(k * 32);   // 16 halves
            uint32_t ah[4][4], al[4][4], bh[2][4], bl[2][4];
            #pragma unroll
            for (int mt = 0; mt < 4; mt++)
                ldsm4(ah[mt], aH + (uint32_t)(mt * 16 * SA_STRIDE * 2) + kb);
            ldsm4(bh[0], bH + kb);                                    // n-tiles 0,1
            ldsm4(bh[1], bH + (uint32_t)(16 * SA_STRIDE * 2) + kb);   // n-tiles 2,3
            // term 1: Ahi * Bhi
            #pragma unroll
            for (int mt = 0; mt < 4; mt++)
                #pragma unroll
                for (int nt = 0; nt < 4; nt++)
                    hmma(acc[mt][nt], ah[mt], &bh[nt >> 1][(nt & 1) * 2]);
            #pragma unroll
            for (int mt = 0; mt < 4; mt++)
                ldsm4(al[mt], aL + (uint32_t)(mt * 16 * SA_STRIDE * 2) + kb);
            // term 2: Alo * Bhi
            #pragma unroll
            for (int mt = 0; mt < 4; mt++)
                #pragma unroll
                for (int nt = 0; nt < 4; nt++)
                    hmma(acc[mt][nt], al[mt], &bh[nt >> 1][(nt & 1) * 2]);
            ldsm4(bl[0], bL + kb);
            ldsm4(bl[1], bL + (uint32_t)(16 * SA_STRIDE * 2) + kb);
            // term 3: Ahi * Blo
            #pragma unroll
            for (int mt = 0; mt < 4; mt++)
                #pragma unroll
                for (int nt = 0; nt < 4; nt++)
                    hmma(acc[mt][nt], ah[mt], &bl[nt >> 1][(nt & 1) * 2]);
        }
        __syncthreads();
    }

    if (outv) {
        #pragma unroll
        for (int mt = 0; mt < 4; mt++) {
            #pragma unroll
            for (int half = 0; half < 2; half++) {
                int rloc = wm * 64 + mt * 16 + ar + half * 8;
                float p = 0.f;
                #pragma unroll
                for (int nt = 0; nt < 4; nt++) {
                    int col = wn * 32 + nt * 8 + ac;
                    float v0 = acc[mt][nt][half * 2 + 0] + sbias[col];
                    float v1 = acc[mt][nt][half * 2 + 1] + sbias[col + 1];
                    if (relu) { v0 = fmaxf(v0, 0.f); v1 = fmaxf(v1, 0.f); }
                    p += v0 * swfin[col] + v1 * swfin[col + 1];
                }
                p += __shfl_xor_sync(0xffffffffu, p, 1);
                p += __shfl_xor_sync(0xffffffffu, p, 2);
                if ((lane & 3) == 0) sred[rloc][wn] = p;
            }
        }
        __syncthreads();
        if (tid < 128) {
            int node = node0 + tid;
            if (node < N_NODES)
                outv[node] = (sred[tid][0] + sred[tid][1]) + (sred[tid][2] + sred[tid][3]);
        }
        return;
    }

    #pragma unroll
    for (int mt = 0; mt < 4; mt++) {
        #pragma unroll
        for (int half = 0; half < 2; half++) {
            int node = node0 + wm * 64 + mt * 16 + ar + half * 8;
            #pragma unroll
            for (int nt = 0; nt < 4; nt++) {
                int col = wn * 32 + nt * 8 + ac;
                float v0 = acc[mt][nt][half * 2 + 0] + sbias[col];
                float v1 = acc[mt][nt][half * 2 + 1] + sbias[col + 1];
                if (relu) { v0 = fmaxf(v0, 0.f); v1 = fmaxf(v1, 0.f); }
                __half h0 = __float2half_rn(v0);
                __half h1 = __float2half_rn(v1);
                __half l0 = __float2half_rn(v0 - __half2float(h0));
                __half l1 = __float2half_rn(v1 - __half2float(h1));
                size_t o = (size_t)node * 256 + col;
                *(__half2*)(Chi + o) = __halves2half2(h0, h1);
                *(__half2*)(Clo + o) = __halves2half2(l0, l1);
            }
        }
    }
}

// ------------------------ launch ---------------------------------------------
extern "C" void kernel_launch(void* const* d_in, const int* in_sizes, int n_in,
                              void* d_out, int out_size)
{
    const float* x        = (const float*)d_in[0];
    const float* W_t      = (const float*)d_in[1];
    const float* b_t      = (const float*)d_in[2];
    const float* W_self0  = (const float*)d_in[3];
    const float* b_self0  = (const float*)d_in[4];
    const float* W_neigh0 = (const float*)d_in[5];
    const float* W_self1  = (const float*)d_in[6];
    const float* b_self1  = (const float*)d_in[7];
    const float* W_neigh1 = (const float*)d_in[8];
    const float* W_fin    = (const float*)d_in[9];
    const int*   src      = (const int*)d_in[10];
    const int*   dst      = (const int*)d_in[11];
    float* out = (float*)d_out;

    cudaFuncSetAttribute(k_gemm_mma, cudaFuncAttributeMaxDynamicSharedMemorySize,
                         SMEM_BYTES);

    __half *Axhi, *Axlo, *A1hi, *A1lo, *A2hi, *A2lo;
    cudaGetSymbolAddress((void**)&Axhi, g_Axhi);
    cudaGetSymbolAddress((void**)&Axlo, g_Axlo);
    cudaGetSymbolAddress((void**)&A1hi, g_A1hi);
    cudaGetSymbolAddress((void**)&A1lo, g_A1lo);
    cudaGetSymbolAddress((void**)&A2hi, g_A2hi);
    cudaGetSymbolAddress((void**)&A2lo, g_A2lo);
    __half *Bthi, *Btlo, *B0hi, *B0lo, *B1hi, *B1lo;
    cudaGetSymbolAddress((void**)&Bthi, g_Bthi);
    cudaGetSymbolAddress((void**)&Btlo, g_Btlo);
    cudaGetSymbolAddress((void**)&B0hi, g_B0hi);
    cudaGetSymbolAddress((void**)&B0lo, g_B0lo);
    cudaGetSymbolAddress((void**)&B1hi, g_B1hi);
    cudaGetSymbolAddress((void**)&B1lo, g_B1lo);

    const int TB = 256;
    dim3 gridNodes((N_NODES + TB - 1) / TB);
    dim3 gridEdges((N_EDGES + TB - 1) / TB);
    dim3 gridWarp((N_NODES * 32 + TB - 1) / TB);

    // conversions + GEMM1 first (also puts a GEMM into the ncu capture window)
    k_convx<<<(MPAD * 64 + TB - 1) / TB, TB>>>(x);
    k_prep_w<<<(3 * 128 * 256 + TB - 1) / TB, TB>>>(W_t, W_self0, W_neigh0, W_self1, W_neigh1);
    k_gemm_mma<<<NTILES, 256, SMEM_BYTES>>>(Axhi, Axlo, Bthi, Btlo, b_t, 0,
                                            A1hi, A1lo, nullptr, nullptr);

    // CSR build (independent of GEMM1; must finish before aggregation)
    k_zero_cnt<<<gridNodes, TB>>>();
    k_hist<<<gridEdges, TB>>>(dst);
    k_scan_block<<<NSCANBLK, SCAN_B>>>();
    k_scan_top<<<1, 128>>>();
    k_scan_fin<<<gridNodes, TB>>>();
    k_fill<<<gridEdges, TB>>>(src, dst);

    // layer 0
    k_aggregate<<<gridWarp, TB>>>(A1hi, A1hi, A1lo);
    k_gemm_mma<<<NTILES, 256, SMEM_BYTES>>>(A1hi, A1lo, B0hi, B0lo, b_self0, 1,
                                            A2hi, A2lo, nullptr, nullptr);
    // layer 1
    k_aggregate<<<gridWarp, TB>>>(A2hi, A2hi, A2lo);
    k_gemm_mma<<<NTILES, 256, SMEM_BYTES>>>(A2hi, A2lo, B1hi, B1lo, b_self1, 1,
                                            nullptr, nullptr, W_fin, out);
}

// round 7
// speedup vs baseline: 2.1803x; 1.2516x over previous
#include <cuda_runtime.h>
#include <cuda_fp16.h>
#include <cstdint>

#define N_NODES 100000
#define N_EDGES 1600000
#define DIN 256
#define HID 128

#define NTILES 782
#define MPAD (NTILES * 128)      // 100096

// ------------------------ device scratch (no allocation) --------------------
__device__ __align__(256) __half g_Axhi[(size_t)MPAD * 256];
__device__ __align__(256) __half g_Axlo[(size_t)MPAD * 256];
__device__ __align__(256) __half g_A1hi[(size_t)MPAD * 256];
__device__ __align__(256) __half g_A1lo[(size_t)MPAD * 256];
__device__ __align__(256) __half g_A2hi[(size_t)MPAD * 256];
__device__ __align__(256) __half g_A2lo[(size_t)MPAD * 256];
__device__ __align__(256) __half g_Bt[128 * 256];
__device__ __align__(256) __half g_B0[128 * 256];
__device__ __align__(256) __half g_B1[128 * 256];

__device__ int g_cnt[N_NODES];
__device__ int g_off[N_NODES + 1];
__device__ int g_cur[N_NODES];
__device__ int g_csr[N_EDGES];
__device__ int g_blksum[128];
__device__ int g_blkoff[128];

#define SCAN_B 1024
#define NSCANBLK ((N_NODES + SCAN_B - 1) / SCAN_B)   // 98

// ------------------------ helpers --------------------------------------------
__device__ __forceinline__ uint32_t smem_u32(const void* p) {
    uint32_t a;
    asm("{ .reg .u64 t; cvta.to.shared.u64 t, %1; cvt.u32.u64 %0, t; }"
        : "=r"(a) : "l"(p));
    return a;
}
__device__ __forceinline__ void cpa16(uint32_t dst, const void* src) {
    asm volatile("cp.async.cg.shared.global [%0], [%1], 16;" :: "r"(dst), "l"(src));
}
#define CP_COMMIT() asm volatile("cp.async.commit_group;" ::: "memory")

__device__ __forceinline__ void ldsm4(uint32_t* r, uint32_t addr) {
    asm volatile("ldmatrix.sync.aligned.m8n8.x4.shared.b16 {%0,%1,%2,%3}, [%4];"
                 : "=r"(r[0]), "=r"(r[1]), "=r"(r[2]), "=r"(r[3]) : "r"(addr));
}
__device__ __forceinline__ void hmma(float* d, const uint32_t* a, const uint32_t* b) {
    asm volatile(
        "mma.sync.aligned.m16n8k16.row.col.f32.f16.f16.f32 "
        "{%0,%1,%2,%3}, {%4,%5,%6,%7}, {%8,%9}, {%0,%1,%2,%3};"
        : "+f"(d[0]), "+f"(d[1]), "+f"(d[2]), "+f"(d[3])
        : "r"(a[0]), "r"(a[1]), "r"(a[2]), "r"(a[3]), "r"(b[0]), "r"(b[1]));
}

// ------------------------ input conversions ---------------------------------
__global__ void k_convx(const float* __restrict__ x) {
    int t = blockIdx.x * blockDim.x + threadIdx.x;
    if (t >= MPAD * 64) return;
    int row = t >> 6;
    int c4 = (t & 63) * 4;
    float4 v = make_float4(0.f, 0.f, 0.f, 0.f);
    if (row < N_NODES) v = *(const float4*)(x + (size_t)row * 256 + c4);
    __half hx = __float2half_rn(v.x), hy = __float2half_rn(v.y);
    __half hz = __float2half_rn(v.z), hw = __float2half_rn(v.w);
    __half lx = __float2half_rn(v.x - __half2float(hx));
    __half ly = __float2half_rn(v.y - __half2float(hy));
    __half lz = __float2half_rn(v.z - __half2float(hz));
    __half lw = __float2half_rn(v.w - __half2float(hw));
    size_t o = (size_t)row * 256 + c4;
    *(__half2*)(g_Axhi + o)     = __halves2half2(hx, hy);
    *(__half2*)(g_Axhi + o + 2) = __halves2half2(hz, hw);
    *(__half2*)(g_Axlo + o)     = __halves2half2(lx, ly);
    *(__half2*)(g_Axlo + o + 2) = __halves2half2(lz, lw);
}

// Weights -> fp16 (rounded), N-major rows [n][k]
__global__ void k_prep_w(const float* __restrict__ W_t,
                         const float* __restrict__ W_self0, const float* __restrict__ W_neigh0,
                         const float* __restrict__ W_self1, const float* __restrict__ W_neigh1) {
    int g = blockIdx.x * blockDim.x + threadIdx.x;
    if (g >= 3 * 128 * 256) return;
    int which = g / (128 * 256);
    int r = g % (128 * 256);
    int n = r / 256;
    int k = r % 256;
    float w;
    __half* dh;
    if (which == 0) { w = W_t[(size_t)k * 128 + n]; dh = g_Bt; }
    else if (which == 1) {
        w = (k < 128) ? W_self0[(size_t)k * 128 + n] : W_neigh0[(size_t)(k - 128) * 128 + n];
        dh = g_B0;
    } else {
        w = (k < 128) ? W_self1[(size_t)k * 128 + n] : W_neigh1[(size_t)(k - 128) * 128 + n];
        dh = g_B1;
    }
    dh[(size_t)n * 256 + k] = __float2half_rn(w);
}

// ------------------------ CSR build ------------------------------------------
__global__ void k_zero_cnt() {
    int i = blockIdx.x * blockDim.x + threadIdx.x;
    if (i < N_NODES) g_cnt[i] = 0;
}
__global__ void k_hist(const int* __restrict__ dst) {
    int i = blockIdx.x * blockDim.x + threadIdx.x;
    if (i < N_EDGES) atomicAdd(&g_cnt[dst[i]], 1);
}
__global__ void k_scan_block() {
    __shared__ int s[SCAN_B];
    int t = threadIdx.x;
    int i = blockIdx.x * SCAN_B + t;
    int v = (i < N_NODES) ? g_cnt[i] : 0;
    s[t] = v;
    __syncthreads();
    #pragma unroll
    for (int off = 1; off < SCAN_B; off <<= 1) {
        int x = (t >= off) ? s[t - off] : 0;
        __syncthreads();
        s[t] += x;
        __syncthreads();
    }
    if (i < N_NODES) g_off[i + 1] = s[t];
    if (t == SCAN_B - 1) g_blksum[blockIdx.x] = s[t];
}
__global__ void k_scan_top() {
    __shared__ int s[128];
    int t = threadIdx.x;
    int v = (t < NSCANBLK) ? g_blksum[t] : 0;
    s[t] = v;
    __syncthreads();
    #pragma unroll
    for (int off = 1; off < 128; off <<= 1) {
        int x = (t >= off) ? s[t - off] : 0;
        __syncthreads();
        s[t] += x;
        __syncthreads();
    }
    if (t < NSCANBLK) g_blkoff[t] = s[t] - v;
    if (t == 0) { g_off[0] = 0; g_cur[0] = 0; }
}
__global__ void k_scan_fin() {
    int i = blockIdx.x * blockDim.x + threadIdx.x;
    if (i < N_NODES) {
        int v = g_off[i + 1] + g_blkoff[i >> 10];
        g_off[i + 1] = v;
        if (i + 1 < N_NODES) g_cur[i + 1] = v;
    }
}
__global__ void k_fill(const int* __restrict__ src, const int* __restrict__ dst) {
    int i = blockIdx.x * blockDim.x + threadIdx.x;
    if (i < N_EDGES) {
        int d = dst[i];
        int p = atomicAdd(&g_cur[d], 1);
        g_csr[p] = src[i];
    }
}

// ------------------------ aggregation (warp per node, unrolled x4) -----------
__global__ void k_aggregate(const __half* __restrict__ Hhi,
                            __half* __restrict__ Ahi, __half* __restrict__ Alo) {
    int warp = (blockIdx.x * blockDim.x + threadIdx.x) >> 5;
    int lane = threadIdx.x & 31;
    if (warp >= N_NODES) return;
    int s = g_off[warp];
    int e = g_off[warp + 1];
    float vx = 0.f, vy = 0.f, vz = 0.f, vw = 0.f;
    int i = s;
    const size_t loff = (size_t)(lane * 4);
    for (; i + 4 <= e; i += 4) {
        int n0 = g_csr[i], n1 = g_csr[i + 1], n2 = g_csr[i + 2], n3 = g_csr[i + 3];
        uint2 r0 = *(const uint2*)(Hhi + (size_t)n0 * 256 + loff);
        uint2 r1 = *(const uint2*)(Hhi + (size_t)n1 * 256 + loff);
        uint2 r2 = *(const uint2*)(Hhi + (size_t)n2 * 256 + loff);
        uint2 r3 = *(const uint2*)(Hhi + (size_t)n3 * 256 + loff);
        float2 a0 = __half22float2(*(__half2*)&r0.x), b0 = __half22float2(*(__half2*)&r0.y);
        float2 a1 = __half22float2(*(__half2*)&r1.x), b1 = __half22float2(*(__half2*)&r1.y);
        float2 a2 = __half22float2(*(__half2*)&r2.x), b2 = __half22float2(*(__half2*)&r2.y);
        float2 a3 = __half22float2(*(__half2*)&r3.x), b3 = __half22float2(*(__half2*)&r3.y);
        vx += (a0.x + a1.x) + (a2.x + a3.x);
        vy += (a0.y + a1.y) + (a2.y + a3.y);
        vz += (b0.x + b1.x) + (b2.x + b3.x);
        vw += (b0.y + b1.y) + (b2.y + b3.y);
    }
    for (; i < e; i++) {
        int sc = g_csr[i];
        uint2 raw = *(const uint2*)(Hhi + (size_t)sc * 256 + loff);
        float2 p0 = __half22float2(*(__half2*)&raw.x);
        float2 p1 = __half22float2(*(__half2*)&raw.y);
        vx += p0.x; vy += p0.y; vz += p1.x; vw += p1.y;
    }
    float inv = 1.f / fmaxf((float)(e - s), 1.f);
    vx *= inv; vy *= inv; vz *= inv; vw *= inv;
    __half hx = __float2half_rn(vx), hy = __float2half_rn(vy);
    __half hz = __float2half_rn(vz), hw = __float2half_rn(vw);
    __half lx = __float2half_rn(vx - __half2float(hx));
    __half ly = __float2half_rn(vy - __half2float(hy));
    __half lz = __float2half_rn(vz - __half2float(hz));
    __half lw = __float2half_rn(vw - __half2float(hw));
    size_t o = (size_t)warp * 256 + 128 + loff;
    *(__half2*)(Ahi + o)     = __halves2half2(hx, hy);
    *(__half2*)(Ahi + o + 2) = __halves2half2(hz, hw);
    *(__half2*)(Alo + o)     = __halves2half2(lx, ly);
    *(__half2*)(Alo + o + 2) = __halves2half2(lz, lw);
}

// ------------------------ HMMA GEMM, 2-term, 2-stage cp.async, ldmatrix ------
// C = relu?( (Ahi+Alo) @ B^T + bias ).  A hi/lo fp16 [MPAD,256], B fp16 [128,256].
#define SA_STRIDE 72                       // halves per row (144 B)
#define TILE_B (128 * SA_STRIDE * 2)       // 18432 B
#define STAGE_B (3 * TILE_B)               // Ah, Al, Bh
#define SMEM_BYTES (2 * STAGE_B + 512 + 512 + 2048)   // 113664

__global__ __launch_bounds__(256, 2) void k_gemm_mma(
    const __half* __restrict__ Ahi, const __half* __restrict__ Alo,
    const __half* __restrict__ B,
    const float* __restrict__ bias, int relu,
    __half* __restrict__ Chi, __half* __restrict__ Clo,
    const float* __restrict__ Wfin, float* __restrict__ outv)
{
    extern __shared__ __align__(16) char smem[];
    float* sbias = (float*)(smem + 2 * STAGE_B);
    float* swfin = (float*)(smem + 2 * STAGE_B + 512);
    float (*sred)[4] = (float (*)[4])(smem + 2 * STAGE_B + 1024);

    const int tid = threadIdx.x;
    const int wid = tid >> 5;
    const int lane = tid & 31;
    const int wm = wid >> 2;
    const int wn = wid & 3;
    const int node0 = blockIdx.x * 128;
    const uint32_t sb = smem_u32(smem);

    if (tid < 128) {
        sbias[tid] = bias[tid];
        if (Wfin) {
            swfin[tid] = Wfin[tid];
            sred[tid][0] = sred[tid][1] = sred[tid][2] = sred[tid][3] = 0.f;
        }
    }

    const int r0 = tid >> 3;
    const int s0 = tid & 7;

    {
        #pragma unroll
        for (int it = 0; it < 4; it++) {
            int r = r0 + it * 32;
            size_t ga = (size_t)(node0 + r) * 256 + s0 * 8;
            size_t gb = (size_t)r * 256 + s0 * 8;
            uint32_t so = (uint32_t)(r * SA_STRIDE + s0 * 8) * 2;
            cpa16(sb + 0 * TILE_B + so, Ahi + ga);
            cpa16(sb + 1 * TILE_B + so, Alo + ga);
            cpa16(sb + 2 * TILE_B + so, B + gb);
        }
        CP_COMMIT();
    }

    float acc[4][4][4];
    #pragma unroll
    for (int i = 0; i < 4; i++)
        #pragma unroll
        for (int j = 0; j < 4; j++)
            #pragma unroll
            for (int q = 0; q < 4; q++) acc[i][j][q] = 0.f;

    const uint32_t a_off =
        (uint32_t)(((wm * 64 + (lane & 15)) * SA_STRIDE + (lane >> 4) * 8) * 2);
    const uint32_t b_off =
        (uint32_t)(((wn * 32 + (lane & 7) + (lane >> 4) * 8) * SA_STRIDE +
                    ((lane >> 3) & 1) * 8) * 2);

    const int ar = lane >> 2;
    const int ac = (lane & 3) * 2;

    #pragma unroll 1
    for (int c = 0; c < 4; c++) {
        if (c < 3) {
            uint32_t st = ((c + 1) & 1) * STAGE_B;
            #pragma unroll
            for (int it = 0; it < 4; it++) {
                int r = r0 + it * 32;
                size_t ga = (size_t)(node0 + r) * 256 + (c + 1) * 64 + s0 * 8;
                size_t gb = (size_t)r * 256 + (c + 1) * 64 + s0 * 8;
                uint32_t so = (uint32_t)(r * SA_STRIDE + s0 * 8) * 2;
                cpa16(sb + st + 0 * TILE_B + so, Ahi + ga);
                cpa16(sb + st + 1 * TILE_B + so, Alo + ga);
                cpa16(sb + st + 2 * TILE_B + so, B + gb);
            }
            CP_COMMIT();
            asm volatile("cp.async.wait_group 1;" ::: "memory");
        } else {
            asm volatile("cp.async.wait_group 0;" ::: "memory");
        }
        __syncthreads();

        const uint32_t stg = sb + (c & 1) * STAGE_B;
        const uint32_t aH = stg + 0 * TILE_B + a_off;
        const uint32_t aL = stg + 1 * TILE_B + a_off;
        const uint32_t bH = stg + 2 * TILE_B + b_off;

        #pragma unroll
        for (int k = 0; k < 4; k++) {
            const uint32_t kb = (uint32_t)(k * 32);
            uint32_t a[4][4], bh[2][4];
            #pragma unroll
            for (int mt = 0; mt < 4; mt++)
                ldsm4(a[mt], aH + (uint32_t)(mt * 16 * SA_STRIDE * 2) + kb);
            ldsm4(bh[0], bH + kb);
            ldsm4(bh[1], bH + (uint32_t)(16 * SA_STRIDE * 2) + kb);
            // term 1: Ahi * B
            #pragma unroll
            for (int mt = 0; mt < 4; mt++)
                #pragma unroll
                for (int nt = 0; nt < 4; nt++)
                    hmma(acc[mt][nt], a[mt], &bh[nt >> 1][(nt & 1) * 2]);
            #pragma unroll
            for (int mt = 0; mt < 4; mt++)
                ldsm4(a[mt], aL + (uint32_t)(mt * 16 * SA_STRIDE * 2) + kb);
            // term 2: Alo * B
            #pragma unroll
            for (int mt = 0; mt < 4; mt++)
                #pragma unroll
                for (int nt = 0; nt < 4; nt++)
                    hmma(acc[mt][nt], a[mt], &bh[nt >> 1][(nt & 1) * 2]);
        }
        __syncthreads();
    }

    if (outv) {
        #pragma unroll
        for (int mt = 0; mt < 4; mt++) {
            #pragma unroll
            for (int half = 0; half < 2; half++) {
                int rloc = wm * 64 + mt * 16 + ar + half * 8;
                float p = 0.f;
                #pragma unroll
                for (int nt = 0; nt < 4; nt++) {
                    int col = wn * 32 + nt * 8 + ac;
                    float v0 = acc[mt][nt][half * 2 + 0] + sbias[col];
                    float v1 = acc[mt][nt][half * 2 + 1] + sbias[col + 1];
                    if (relu) { v0 = fmaxf(v0, 0.f); v1 = fmaxf(v1, 0.f); }
                    p += v0 * swfin[col] + v1 * swfin[col + 1];
                }
                p += __shfl_xor_sync(0xffffffffu, p, 1);
                p += __shfl_xor_sync(0xffffffffu, p, 2);
                if ((lane & 3) == 0) sred[rloc][wn] = p;
            }
        }
        __syncthreads();
        if (tid < 128) {
            int node = node0 + tid;
            if (node < N_NODES)
                outv[node] = (sred[tid][0] + sred[tid][1]) + (sred[tid][2] + sred[tid][3]);
        }
        return;
    }

    #pragma unroll
    for (int mt = 0; mt < 4; mt++) {
        #pragma unroll
        for (int half = 0; half < 2; half++) {
            int node = node0 + wm * 64 + mt * 16 + ar + half * 8;
            #pragma unroll
            for (int nt = 0; nt < 4; nt++) {
                int col = wn * 32 + nt * 8 + ac;
                float v0 = acc[mt][nt][half * 2 + 0] + sbias[col];
                float v1 = acc[mt][nt][half * 2 + 1] + sbias[col + 1];
                if (relu) { v0 = fmaxf(v0, 0.f); v1 = fmaxf(v1, 0.f); }
                __half h0 = __float2half_rn(v0);
                __half h1 = __float2half_rn(v1);
                __half l0 = __float2half_rn(v0 - __half2float(h0));
                __half l1 = __float2half_rn(v1 - __half2float(h1));
                size_t o = (size_t)node * 256 + col;
                *(__half2*)(Chi + o) = __halves2half2(h0, h1);
                *(__half2*)(Clo + o) = __halves2half2(l0, l1);
            }
        }
    }
}

// ------------------------ launch ---------------------------------------------
extern "C" void kernel_launch(void* const* d_in, const int* in_sizes, int n_in,
                              void* d_out, int out_size)
{
    const float* x        = (const float*)d_in[0];
    const float* W_t      = (const float*)d_in[1];
    const float* b_t      = (const float*)d_in[2];
    const float* W_self0  = (const float*)d_in[3];
    const float* b_self0  = (const float*)d_in[4];
    const float* W_neigh0 = (const float*)d_in[5];
    const float* W_self1  = (const float*)d_in[6];
    const float* b_self1  = (const float*)d_in[7];
    const float* W_neigh1 = (const float*)d_in[8];
    const float* W_fin    = (const float*)d_in[9];
    const int*   src      = (const int*)d_in[10];
    const int*   dst      = (const int*)d_in[11];
    float* out = (float*)d_out;

    cudaFuncSetAttribute(k_gemm_mma, cudaFuncAttributeMaxDynamicSharedMemorySize,
                         SMEM_BYTES);

    __half *Axhi, *Axlo, *A1hi, *A1lo, *A2hi, *A2lo;
    cudaGetSymbolAddress((void**)&Axhi, g_Axhi);
    cudaGetSymbolAddress((void**)&Axlo, g_Axlo);
    cudaGetSymbolAddress((void**)&A1hi, g_A1hi);
    cudaGetSymbolAddress((void**)&A1lo, g_A1lo);
    cudaGetSymbolAddress((void**)&A2hi, g_A2hi);
    cudaGetSymbolAddress((void**)&A2lo, g_A2lo);
    __half *Bt, *B0, *B1;
    cudaGetSymbolAddress((void**)&Bt, g_Bt);
    cudaGetSymbolAddress((void**)&B0, g_B0);
    cudaGetSymbolAddress((void**)&B1, g_B1);

    const int TB = 256;
    dim3 gridNodes((N_NODES + TB - 1) / TB);
    dim3 gridEdges((N_EDGES + TB - 1) / TB);
    dim3 gridWarp((N_NODES * 32 + TB - 1) / TB);

    // order chosen so launch #4 (the ncu capture slot) is a GEMM
    k_zero_cnt<<<gridNodes, TB>>>();
    k_convx<<<(MPAD * 64 + TB - 1) / TB, TB>>>(x);
    k_prep_w<<<(3 * 128 * 256 + TB - 1) / TB, TB>>>(W_t, W_self0, W_neigh0, W_self1, W_neigh1);
    k_gemm_mma<<<NTILES, 256, SMEM_BYTES>>>(Axhi, Axlo, Bt, b_t, 0,
                                            A1hi, A1lo, nullptr, nullptr);

    // CSR build
    k_hist<<<gridEdges, TB>>>(dst);
    k_scan_block<<<NSCANBLK, SCAN_B>>>();
    k_scan_top<<<1, 128>>>();
    k_scan_fin<<<gridNodes, TB>>>();
    k_fill<<<gridEdges, TB>>>(src, dst);

    // layer 0
    k_aggregate<<<gridWarp, TB>>>(A1hi, A1hi, A1lo);
    k_gemm_mma<<<NTILES, 256, SMEM_BYTES>>>(A1hi, A1lo, B0, b_self0, 1,
                                            A2hi, A2lo, nullptr, nullptr);
    // layer 1
    k_aggregate<<<gridWarp, TB>>>(A2hi, A2hi, A2lo);
    k_gemm_mma<<<NTILES, 256, SMEM_BYTES>>>(A2hi, A2lo, B1, b_self1, 1,
                                            nullptr, nullptr, W_fin, out);
}

// round 8
// speedup vs baseline: 2.2275x; 1.0216x over previous
#include <cuda_runtime.h>
#include <cuda_fp16.h>
#include <cstdint>

#define N_NODES 100000
#define N_EDGES 1600000
#define DIN 256
#define HID 128

#define NTILES 782
#define MPAD (NTILES * 128)      // 100096

// ------------------------ device scratch (no allocation) --------------------
__device__ __align__(256) __half g_Axhi[(size_t)MPAD * 256];
__device__ __align__(256) __half g_Axlo[(size_t)MPAD * 256];
__device__ __align__(256) __half g_A1hi[(size_t)MPAD * 256];
__device__ __align__(256) __half g_A1lo[(size_t)MPAD * 256];
__device__ __align__(256) __half g_A2hi[(size_t)MPAD * 256];
__device__ __align__(256) __half g_A2lo[(size_t)MPAD * 256];
__device__ __align__(256) __half g_Bt[128 * 256];
__device__ __align__(256) __half g_B0[128 * 256];
__device__ __align__(256) __half g_B1[128 * 256];

__device__ int g_cnt[N_NODES];
__device__ int g_off[N_NODES + 1];
__device__ int g_cur[N_NODES];
__device__ int g_csr[N_EDGES];
__device__ int g_blksum[128];
__device__ int g_blkoff[128];

#define SCAN_B 1024
#define NSCANBLK ((N_NODES + SCAN_B - 1) / SCAN_B)   // 98

// ------------------------ helpers --------------------------------------------
__device__ __forceinline__ uint32_t smem_u32(const void* p) {
    uint32_t a;
    asm("{ .reg .u64 t; cvta.to.shared.u64 t, %1; cvt.u32.u64 %0, t; }"
        : "=r"(a) : "l"(p));
    return a;
}
__device__ __forceinline__ void cpa16(uint32_t dst, const void* src) {
    asm volatile("cp.async.cg.shared.global [%0], [%1], 16;" :: "r"(dst), "l"(src));
}
#define CP_COMMIT() asm volatile("cp.async.commit_group;" ::: "memory")

__device__ __forceinline__ void ldsm4(uint32_t* r, uint32_t addr) {
    asm volatile("ldmatrix.sync.aligned.m8n8.x4.shared.b16 {%0,%1,%2,%3}, [%4];"
                 : "=r"(r[0]), "=r"(r[1]), "=r"(r[2]), "=r"(r[3]) : "r"(addr));
}
__device__ __forceinline__ void hmma(float* d, const uint32_t* a, const uint32_t* b) {
    asm volatile(
        "mma.sync.aligned.m16n8k16.row.col.f32.f16.f16.f32 "
        "{%0,%1,%2,%3}, {%4,%5,%6,%7}, {%8,%9}, {%0,%1,%2,%3};"
        : "+f"(d[0]), "+f"(d[1]), "+f"(d[2]), "+f"(d[3])
        : "r"(a[0]), "r"(a[1]), "r"(a[2]), "r"(a[3]), "r"(b[0]), "r"(b[1]));
}

// ------------------------ input conversions ---------------------------------
__global__ void k_convx(const float* __restrict__ x) {
    int t = blockIdx.x * blockDim.x + threadIdx.x;
    if (t >= MPAD * 64) return;
    int row = t >> 6;
    int c4 = (t & 63) * 4;
    float4 v = make_float4(0.f, 0.f, 0.f, 0.f);
    if (row < N_NODES) v = *(const float4*)(x + (size_t)row * 256 + c4);
    __half hx = __float2half_rn(v.x), hy = __float2half_rn(v.y);
    __half hz = __float2half_rn(v.z), hw = __float2half_rn(v.w);
    __half lx = __float2half_rn(v.x - __half2float(hx));
    __half ly = __float2half_rn(v.y - __half2float(hy));
    __half lz = __float2half_rn(v.z - __half2float(hz));
    __half lw = __float2half_rn(v.w - __half2float(hw));
    size_t o = (size_t)row * 256 + c4;
    *(__half2*)(g_Axhi + o)     = __halves2half2(hx, hy);
    *(__half2*)(g_Axhi + o + 2) = __halves2half2(hz, hw);
    *(__half2*)(g_Axlo + o)     = __halves2half2(lx, ly);
    *(__half2*)(g_Axlo + o + 2) = __halves2half2(lz, lw);
}

// Weights -> fp16 (rounded), N-major rows [n][k]
__global__ void k_prep_w(const float* __restrict__ W_t,
                         const float* __restrict__ W_self0, const float* __restrict__ W_neigh0,
                         const float* __restrict__ W_self1, const float* __restrict__ W_neigh1) {
    int g = blockIdx.x * blockDim.x + threadIdx.x;
    if (g >= 3 * 128 * 256) return;
    int which = g / (128 * 256);
    int r = g % (128 * 256);
    int n = r / 256;
    int k = r % 256;
    float w;
    __half* dh;
    if (which == 0) { w = W_t[(size_t)k * 128 + n]; dh = g_Bt; }
    else if (which == 1) {
        w = (k < 128) ? W_self0[(size_t)k * 128 + n] : W_neigh0[(size_t)(k - 128) * 128 + n];
        dh = g_B0;
    } else {
        w = (k < 128) ? W_self1[(size_t)k * 128 + n] : W_neigh1[(size_t)(k - 128) * 128 + n];
        dh = g_B1;
    }
    dh[(size_t)n * 256 + k] = __float2half_rn(w);
}

// ------------------------ CSR build ------------------------------------------
__global__ void k_hist(const int* __restrict__ dst) {
    int i = blockIdx.x * blockDim.x + threadIdx.x;
    if (i < N_EDGES) atomicAdd(&g_cnt[dst[i]], 1);
}
__global__ void k_scan_block() {
    __shared__ int s[SCAN_B];
    int t = threadIdx.x;
    int i = blockIdx.x * SCAN_B + t;
    int v = (i < N_NODES) ? g_cnt[i] : 0;
    s[t] = v;
    __syncthreads();
    #pragma unroll
    for (int off = 1; off < SCAN_B; off <<= 1) {
        int x = (t >= off) ? s[t - off] : 0;
        __syncthreads();
        s[t] += x;
        __syncthreads();
    }
    if (i < N_NODES) g_off[i + 1] = s[t];
    if (t == SCAN_B - 1) g_blksum[blockIdx.x] = s[t];
}
__global__ void k_scan_top() {
    __shared__ int s[128];
    int t = threadIdx.x;
    int v = (t < NSCANBLK) ? g_blksum[t] : 0;
    s[t] = v;
    __syncthreads();
    #pragma unroll
    for (int off = 1; off < 128; off <<= 1) {
        int x = (t >= off) ? s[t - off] : 0;
        __syncthreads();
        s[t] += x;
        __syncthreads();
    }
    if (t < NSCANBLK) g_blkoff[t] = s[t] - v;
    if (t == 0) { g_off[0] = 0; g_cur[0] = 0; }
}
__global__ void k_scan_fin() {
    int i = blockIdx.x * blockDim.x + threadIdx.x;
    if (i < N_NODES) {
        int v = g_off[i + 1] + g_blkoff[i >> 10];
        g_off[i + 1] = v;
        if (i + 1 < N_NODES) g_cur[i + 1] = v;
    }
}
__global__ void k_fill(const int* __restrict__ src, const int* __restrict__ dst) {
    int i = blockIdx.x * blockDim.x + threadIdx.x;
    if (i < N_EDGES) {
        int d = dst[i];
        int p = atomicAdd(&g_cur[d], 1);
        g_csr[p] = src[i];
    }
}

// ------------------------ aggregation (warp per node, unrolled x4) -----------
__global__ void k_aggregate(const __half* __restrict__ Hhi,
                            __half* __restrict__ Ahi, __half* __restrict__ Alo) {
    int warp = (blockIdx.x * blockDim.x + threadIdx.x) >> 5;
    int lane = threadIdx.x & 31;
    if (warp >= N_NODES) return;
    int s = g_off[warp];
    int e = g_off[warp + 1];
    float vx = 0.f, vy = 0.f, vz = 0.f, vw = 0.f;
    int i = s;
    const size_t loff = (size_t)(lane * 4);
    for (; i + 4 <= e; i += 4) {
        int n0 = g_csr[i], n1 = g_csr[i + 1], n2 = g_csr[i + 2], n3 = g_csr[i + 3];
        uint2 r0 = *(const uint2*)(Hhi + (size_t)n0 * 256 + loff);
        uint2 r1 = *(const uint2*)(Hhi + (size_t)n1 * 256 + loff);
        uint2 r2 = *(const uint2*)(Hhi + (size_t)n2 * 256 + loff);
        uint2 r3 = *(const uint2*)(Hhi + (size_t)n3 * 256 + loff);
        float2 a0 = __half22float2(*(__half2*)&r0.x), b0 = __half22float2(*(__half2*)&r0.y);
        float2 a1 = __half22float2(*(__half2*)&r1.x), b1 = __half22float2(*(__half2*)&r1.y);
        float2 a2 = __half22float2(*(__half2*)&r2.x), b2 = __half22float2(*(__half2*)&r2.y);
        float2 a3 = __half22float2(*(__half2*)&r3.x), b3 = __half22float2(*(__half2*)&r3.y);
        vx += (a0.x + a1.x) + (a2.x + a3.x);
        vy += (a0.y + a1.y) + (a2.y + a3.y);
        vz += (b0.x + b1.x) + (b2.x + b3.x);
        vw += (b0.y + b1.y) + (b2.y + b3.y);
    }
    for (; i < e; i++) {
        int sc = g_csr[i];
        uint2 raw = *(const uint2*)(Hhi + (size_t)sc * 256 + loff);
        float2 p0 = __half22float2(*(__half2*)&raw.x);
        float2 p1 = __half22float2(*(__half2*)&raw.y);
        vx += p0.x; vy += p0.y; vz += p1.x; vw += p1.y;
    }
    float inv = 1.f / fmaxf((float)(e - s), 1.f);
    vx *= inv; vy *= inv; vz *= inv; vw *= inv;
    __half hx = __float2half_rn(vx), hy = __float2half_rn(vy);
    __half hz = __float2half_rn(vz), hw = __float2half_rn(vw);
    __half lx = __float2half_rn(vx - __half2float(hx));
    __half ly = __float2half_rn(vy - __half2float(hy));
    __half lz = __float2half_rn(vz - __half2float(hz));
    __half lw = __float2half_rn(vw - __half2float(hw));
    size_t o = (size_t)warp * 256 + 128 + loff;
    *(__half2*)(Ahi + o)     = __halves2half2(hx, hy);
    *(__half2*)(Ahi + o + 2) = __halves2half2(hz, hw);
    *(__half2*)(Alo + o)     = __halves2half2(lx, ly);
    *(__half2*)(Alo + o + 2) = __halves2half2(lz, lw);
}

// ------------------------ HMMA GEMM, 2-term, 2-stage cp.async, ldmatrix ------
// C = relu?( (Ahi+Alo) @ B^T + bias ).  A hi/lo fp16 [MPAD,256], B fp16 [128,256].
#define SA_STRIDE 72                       // halves per row (144 B)
#define TILE_B (128 * SA_STRIDE * 2)       // 18432 B
#define STAGE_B (3 * TILE_B)               // Ah, Al, Bh
#define SMEM_BYTES (2 * STAGE_B + 512 + 512 + 2048)   // 113664

__global__ __launch_bounds__(256, 2) void k_gemm_mma(
    const __half* __restrict__ Ahi, const __half* __restrict__ Alo,
    const __half* __restrict__ B,
    const float* __restrict__ bias, int relu,
    __half* __restrict__ Chi, __half* __restrict__ Clo,
    const float* __restrict__ Wfin, float* __restrict__ outv)
{
    extern __shared__ __align__(16) char smem[];
    float* sbias = (float*)(smem + 2 * STAGE_B);
    float* swfin = (float*)(smem + 2 * STAGE_B + 512);
    float (*sred)[4] = (float (*)[4])(smem + 2 * STAGE_B + 1024);

    const int tid = threadIdx.x;
    const int wid = tid >> 5;
    const int lane = tid & 31;
    const int wm = wid >> 2;
    const int wn = wid & 3;
    const int node0 = blockIdx.x * 128;
    const uint32_t sb = smem_u32(smem);

    if (tid < 128) {
        sbias[tid] = bias[tid];
        if (Wfin) {
            swfin[tid] = Wfin[tid];
            sred[tid][0] = sred[tid][1] = sred[tid][2] = sred[tid][3] = 0.f;
        }
    }

    const int r0 = tid >> 3;
    const int s0 = tid & 7;

    {
        #pragma unroll
        for (int it = 0; it < 4; it++) {
            int r = r0 + it * 32;
            size_t ga = (size_t)(node0 + r) * 256 + s0 * 8;
            size_t gb = (size_t)r * 256 + s0 * 8;
            uint32_t so = (uint32_t)(r * SA_STRIDE + s0 * 8) * 2;
            cpa16(sb + 0 * TILE_B + so, Ahi + ga);
            cpa16(sb + 1 * TILE_B + so, Alo + ga);
            cpa16(sb + 2 * TILE_B + so, B + gb);
        }
        CP_COMMIT();
    }

    float acc[4][4][4];
    #pragma unroll
    for (int i = 0; i < 4; i++)
        #pragma unroll
        for (int j = 0; j < 4; j++)
            #pragma unroll
            for (int q = 0; q < 4; q++) acc[i][j][q] = 0.f;

    const uint32_t a_off =
        (uint32_t)(((wm * 64 + (lane & 15)) * SA_STRIDE + (lane >> 4) * 8) * 2);
    const uint32_t b_off =
        (uint32_t)(((wn * 32 + (lane & 7) + (lane >> 4) * 8) * SA_STRIDE +
                    ((lane >> 3) & 1) * 8) * 2);

    const int ar = lane >> 2;
    const int ac = (lane & 3) * 2;

    #pragma unroll 1
    for (int c = 0; c < 4; c++) {
        if (c < 3) {
            uint32_t st = ((c + 1) & 1) * STAGE_B;
            #pragma unroll
            for (int it = 0; it < 4; it++) {
                int r = r0 + it * 32;
                size_t ga = (size_t)(node0 + r) * 256 + (c + 1) * 64 + s0 * 8;
                size_t gb = (size_t)r * 256 + (c + 1) * 64 + s0 * 8;
                uint32_t so = (uint32_t)(r * SA_STRIDE + s0 * 8) * 2;
                cpa16(sb + st + 0 * TILE_B + so, Ahi + ga);
                cpa16(sb + st + 1 * TILE_B + so, Alo + ga);
                cpa16(sb + st + 2 * TILE_B + so, B + gb);
            }
            CP_COMMIT();
            asm volatile("cp.async.wait_group 1;" ::: "memory");
        } else {
            asm volatile("cp.async.wait_group 0;" ::: "memory");
        }
        __syncthreads();

        const uint32_t stg = sb + (c & 1) * STAGE_B;
        const uint32_t aH = stg + 0 * TILE_B + a_off;
        const uint32_t aL = stg + 1 * TILE_B + a_off;
        const uint32_t bH = stg + 2 * TILE_B + b_off;

        #pragma unroll
        for (int k = 0; k < 4; k++) {
            const uint32_t kb = (uint32_t)(k * 32);
            uint32_t a[4][4], bh[2][4], al2[2][4];
            #pragma unroll
            for (int mt = 0; mt < 4; mt++)
                ldsm4(a[mt], aH + (uint32_t)(mt * 16 * SA_STRIDE * 2) + kb);
            ldsm4(bh[0], bH + kb);
            ldsm4(bh[1], bH + (uint32_t)(16 * SA_STRIDE * 2) + kb);
            // prefetch lo fragments for m-tiles 0,1 (independent of hi HMMAs)
            ldsm4(al2[0], aL + kb);
            ldsm4(al2[1], aL + (uint32_t)(16 * SA_STRIDE * 2) + kb);
            // term 1: Ahi * B (16 HMMA) — hides al2 load latency
            #pragma unroll
            for (int mt = 0; mt < 4; mt++)
                #pragma unroll
                for (int nt = 0; nt < 4; nt++)
                    hmma(acc[mt][nt], a[mt], &bh[nt >> 1][(nt & 1) * 2]);
            // term 2a: Alo * B for m-tiles 0,1
            #pragma unroll
            for (int mt = 0; mt < 2; mt++)
                #pragma unroll
                for (int nt = 0; nt < 4; nt++)
                    hmma(acc[mt][nt], al2[mt], &bh[nt >> 1][(nt & 1) * 2]);
            // load lo fragments for m-tiles 2,3 (overlaps 2a tail)
            ldsm4(al2[0], aL + (uint32_t)(2 * 16 * SA_STRIDE * 2) + kb);
            ldsm4(al2[1], aL + (uint32_t)(3 * 16 * SA_STRIDE * 2) + kb);
            // term 2b: Alo * B for m-tiles 2,3
            #pragma unroll
            for (int mt = 0; mt < 2; mt++)
                #pragma unroll
                for (int nt = 0; nt < 4; nt++)
                    hmma(acc[mt + 2][nt], al2[mt], &bh[nt >> 1][(nt & 1) * 2]);
        }
        __syncthreads();
    }

    if (outv) {
        #pragma unroll
        for (int mt = 0; mt < 4; mt++) {
            #pragma unroll
            for (int half = 0; half < 2; half++) {
                int rloc = wm * 64 + mt * 16 + ar + half * 8;
                float p = 0.f;
                #pragma unroll
                for (int nt = 0; nt < 4; nt++) {
                    int col = wn * 32 + nt * 8 + ac;
                    float v0 = acc[mt][nt][half * 2 + 0] + sbias[col];
                    float v1 = acc[mt][nt][half * 2 + 1] + sbias[col + 1];
                    if (relu) { v0 = fmaxf(v0, 0.f); v1 = fmaxf(v1, 0.f); }
                    p += v0 * swfin[col] + v1 * swfin[col + 1];
                }
                p += __shfl_xor_sync(0xffffffffu, p, 1);
                p += __shfl_xor_sync(0xffffffffu, p, 2);
                if ((lane & 3) == 0) sred[rloc][wn] = p;
            }
        }
        __syncthreads();
        if (tid < 128) {
            int node = node0 + tid;
            if (node < N_NODES)
                outv[node] = (sred[tid][0] + sred[tid][1]) + (sred[tid][2] + sred[tid][3]);
        }
        return;
    }

    #pragma unroll
    for (int mt = 0; mt < 4; mt++) {
        #pragma unroll
        for (int half = 0; half < 2; half++) {
            int node = node0 + wm * 64 + mt * 16 + ar + half * 8;
            #pragma unroll
            for (int nt = 0; nt < 4; nt++) {
                int col = wn * 32 + nt * 8 + ac;
                float v0 = acc[mt][nt][half * 2 + 0] + sbias[col];
                float v1 = acc[mt][nt][half * 2 + 1] + sbias[col + 1];
                if (relu) { v0 = fmaxf(v0, 0.f); v1 = fmaxf(v1, 0.f); }
                __half h0 = __float2half_rn(v0);
                __half h1 = __float2half_rn(v1);
                __half l0 = __float2half_rn(v0 - __half2float(h0));
                __half l1 = __float2half_rn(v1 - __half2float(h1));
                size_t o = (size_t)node * 256 + col;
                *(__half2*)(Chi + o) = __halves2half2(h0, h1);
                *(__half2*)(Clo + o) = __halves2half2(l0, l1);
            }
        }
    }
}

// ------------------------ launch ---------------------------------------------
extern "C" void kernel_launch(void* const* d_in, const int* in_sizes, int n_in,
                              void* d_out, int out_size)
{
    const float* x        = (const float*)d_in[0];
    const float* W_t      = (const float*)d_in[1];
    const float* b_t      = (const float*)d_in[2];
    const float* W_self0  = (const float*)d_in[3];
    const float* b_self0  = (const float*)d_in[4];
    const float* W_neigh0 = (const float*)d_in[5];
    const float* W_self1  = (const float*)d_in[6];
    const float* b_self1  = (const float*)d_in[7];
    const float* W_neigh1 = (const float*)d_in[8];
    const float* W_fin    = (const float*)d_in[9];
    const int*   src      = (const int*)d_in[10];
    const int*   dst      = (const int*)d_in[11];
    float* out = (float*)d_out;

    cudaFuncSetAttribute(k_gemm_mma, cudaFuncAttributeMaxDynamicSharedMemorySize,
                         SMEM_BYTES);

    __half *Axhi, *Axlo, *A1hi, *A1lo, *A2hi, *A2lo;
    cudaGetSymbolAddress((void**)&Axhi, g_Axhi);
    cudaGetSymbolAddress((void**)&Axlo, g_Axlo);
    cudaGetSymbolAddress((void**)&A1hi, g_A1hi);
    cudaGetSymbolAddress((void**)&A1lo, g_A1lo);
    cudaGetSymbolAddress((void**)&A2hi, g_A2hi);
    cudaGetSymbolAddress((void**)&A2lo, g_A2lo);
    __half *Bt, *B0, *B1;
    cudaGetSymbolAddress((void**)&Bt, g_Bt);
    cudaGetSymbolAddress((void**)&B0, g_B0);
    cudaGetSymbolAddress((void**)&B1, g_B1);
    int* cntp;
    cudaGetSymbolAddress((void**)&cntp, g_cnt);

    // streams/events created once (outside any graph capture: first call is
    // the uncaptured correctness run)
    static cudaStream_t s2 = nullptr;
    static cudaEvent_t ev_fork = nullptr, ev_join = nullptr;
    if (s2 == nullptr) {
        cudaStreamCreateWithFlags(&s2, cudaStreamNonBlocking);
        cudaEventCreateWithFlags(&ev_fork, cudaEventDisableTiming);
        cudaEventCreateWithFlags(&ev_join, cudaEventDisableTiming);
    }

    const int TB = 256;
    dim3 gridNodes((N_NODES + TB - 1) / TB);
    dim3 gridEdges((N_EDGES + TB - 1) / TB);
    dim3 gridWarp((N_NODES * 32 + TB - 1) / TB);

    // ---- fork: CSR build on s2, concurrent with convx/prep/GEMM1 ----
    cudaEventRecord(ev_fork, 0);
    cudaStreamWaitEvent(s2, ev_fork, 0);

    // default stream: conversion + GEMM1 path
    k_convx<<<(MPAD * 64 + TB - 1) / TB, TB>>>(x);                       // launch 1
    k_prep_w<<<(3 * 128 * 256 + TB - 1) / TB, TB>>>(W_t, W_self0,       // launch 2
                                                    W_neigh0, W_self1, W_neigh1);
    // s2: CSR build
    cudaMemsetAsync(cntp, 0, N_NODES * sizeof(int), s2);
    k_hist<<<gridEdges, TB, 0, s2>>>(dst);                               // launch 3
    // default: GEMM1 = launch 4 (ncu capture slot)
    k_gemm_mma<<<NTILES, 256, SMEM_BYTES>>>(Axhi, Axlo, Bt, b_t, 0,
                                            A1hi, A1lo, nullptr, nullptr);
    k_scan_block<<<NSCANBLK, SCAN_B, 0, s2>>>();
    k_scan_top<<<1, 128, 0, s2>>>();
    k_scan_fin<<<gridNodes, TB, 0, s2>>>();
    k_fill<<<gridEdges, TB, 0, s2>>>(src, dst);

    // ---- join ----
    cudaEventRecord(ev_join, s2);
    cudaStreamWaitEvent(0, ev_join, 0);

    // layer 0
    k_aggregate<<<gridWarp, TB>>>(A1hi, A1hi, A1lo);
    k_gemm_mma<<<NTILES, 256, SMEM_BYTES>>>(A1hi, A1lo, B0, b_self0, 1,
                                            A2hi, A2lo, nullptr, nullptr);
    // layer 1
    k_aggregate<<<gridWarp, TB>>>(A2hi, A2hi, A2lo);
    k_gemm_mma<<<NTILES, 256, SMEM_BYTES>>>(A2hi, A2lo, B1, b_self1, 1,
                                            nullptr, nullptr, W_fin, out);
}

// round 9
// speedup vs baseline: 2.3453x; 1.0529x over previous
#include <cuda_runtime.h>
#include <cuda_fp16.h>
#include <cstdint>

#define N_NODES 100000
#define N_EDGES 1600000
#define DIN 256
#define HID 128

#define MPAD 100096
#define NTILES64 (MPAD / 64)     // 1564

// ------------------------ device scratch (no allocation) --------------------
__device__ __align__(256) __half g_Axhi[(size_t)MPAD * 256];
__device__ __align__(256) __half g_Axlo[(size_t)MPAD * 256];
__device__ __align__(256) __half g_A1hi[(size_t)MPAD * 256];
__device__ __align__(256) __half g_A1lo[(size_t)MPAD * 256];
__device__ __align__(256) __half g_A2hi[(size_t)MPAD * 256];
__device__ __align__(256) __half g_A2lo[(size_t)MPAD * 256];
__device__ __align__(256) __half g_Bt[128 * 256];
__device__ __align__(256) __half g_B0[128 * 256];
__device__ __align__(256) __half g_B1[128 * 256];

__device__ int g_cnt[N_NODES];
__device__ int g_off[N_NODES + 1];
__device__ int g_cur[N_NODES];
__device__ int g_csr[N_EDGES];
__device__ int g_blksum[128];
__device__ int g_blkoff[128];

#define SCAN_B 1024
#define NSCANBLK ((N_NODES + SCAN_B - 1) / SCAN_B)   // 98

// ------------------------ helpers --------------------------------------------
__device__ __forceinline__ uint32_t smem_u32(const void* p) {
    uint32_t a;
    asm("{ .reg .u64 t; cvta.to.shared.u64 t, %1; cvt.u32.u64 %0, t; }"
        : "=r"(a) : "l"(p));
    return a;
}
__device__ __forceinline__ void cpa16(uint32_t dst, const void* src) {
    asm volatile("cp.async.cg.shared.global [%0], [%1], 16;" :: "r"(dst), "l"(src));
}
#define CP_COMMIT() asm volatile("cp.async.commit_group;" ::: "memory")

__device__ __forceinline__ void ldsm4(uint32_t* r, uint32_t addr) {
    asm volatile("ldmatrix.sync.aligned.m8n8.x4.shared.b16 {%0,%1,%2,%3}, [%4];"
                 : "=r"(r[0]), "=r"(r[1]), "=r"(r[2]), "=r"(r[3]) : "r"(addr));
}
__device__ __forceinline__ void hmma(float* d, const uint32_t* a, const uint32_t* b) {
    asm volatile(
        "mma.sync.aligned.m16n8k16.row.col.f32.f16.f16.f32 "
        "{%0,%1,%2,%3}, {%4,%5,%6,%7}, {%8,%9}, {%0,%1,%2,%3};"
        : "+f"(d[0]), "+f"(d[1]), "+f"(d[2]), "+f"(d[3])
        : "r"(a[0]), "r"(a[1]), "r"(a[2]), "r"(a[3]), "r"(b[0]), "r"(b[1]));
}

// ------------------------ input conversions ---------------------------------
__global__ void k_convx(const float* __restrict__ x) {
    int t = blockIdx.x * blockDim.x + threadIdx.x;
    if (t >= MPAD * 64) return;
    int row = t >> 6;
    int c4 = (t & 63) * 4;
    float4 v = make_float4(0.f, 0.f, 0.f, 0.f);
    if (row < N_NODES) v = *(const float4*)(x + (size_t)row * 256 + c4);
    __half hx = __float2half_rn(v.x), hy = __float2half_rn(v.y);
    __half hz = __float2half_rn(v.z), hw = __float2half_rn(v.w);
    __half lx = __float2half_rn(v.x - __half2float(hx));
    __half ly = __float2half_rn(v.y - __half2float(hy));
    __half lz = __float2half_rn(v.z - __half2float(hz));
    __half lw = __float2half_rn(v.w - __half2float(hw));
    size_t o = (size_t)row * 256 + c4;
    *(__half2*)(g_Axhi + o)     = __halves2half2(hx, hy);
    *(__half2*)(g_Axhi + o + 2) = __halves2half2(hz, hw);
    *(__half2*)(g_Axlo + o)     = __halves2half2(lx, ly);
    *(__half2*)(g_Axlo + o + 2) = __halves2half2(lz, lw);
}

__global__ void k_prep_w(const float* __restrict__ W_t,
                         const float* __restrict__ W_self0, const float* __restrict__ W_neigh0,
                         const float* __restrict__ W_self1, const float* __restrict__ W_neigh1) {
    int g = blockIdx.x * blockDim.x + threadIdx.x;
    if (g >= 3 * 128 * 256) return;
    int which = g / (128 * 256);
    int r = g % (128 * 256);
    int n = r / 256;
    int k = r % 256;
    float w;
    __half* dh;
    if (which == 0) { w = W_t[(size_t)k * 128 + n]; dh = g_Bt; }
    else if (which == 1) {
        w = (k < 128) ? W_self0[(size_t)k * 128 + n] : W_neigh0[(size_t)(k - 128) * 128 + n];
        dh = g_B0;
    } else {
        w = (k < 128) ? W_self1[(size_t)k * 128 + n] : W_neigh1[(size_t)(k - 128) * 128 + n];
        dh = g_B1;
    }
    dh[(size_t)n * 256 + k] = __float2half_rn(w);
}

// ------------------------ CSR build ------------------------------------------
__global__ void k_hist(const int* __restrict__ dst) {
    int i = blockIdx.x * blockDim.x + threadIdx.x;
    if (i < N_EDGES) atomicAdd(&g_cnt[dst[i]], 1);
}
__global__ void k_scan_block() {
    __shared__ int s[SCAN_B];
    int t = threadIdx.x;
    int i = blockIdx.x * SCAN_B + t;
    int v = (i < N_NODES) ? g_cnt[i] : 0;
    s[t] = v;
    __syncthreads();
    #pragma unroll
    for (int off = 1; off < SCAN_B; off <<= 1) {
        int x = (t >= off) ? s[t - off] : 0;
        __syncthreads();
        s[t] += x;
        __syncthreads();
    }
    if (i < N_NODES) g_off[i + 1] = s[t];
    if (t == SCAN_B - 1) g_blksum[blockIdx.x] = s[t];
}
__global__ void k_scan_top() {
    __shared__ int s[128];
    int t = threadIdx.x;
    int v = (t < NSCANBLK) ? g_blksum[t] : 0;
    s[t] = v;
    __syncthreads();
    #pragma unroll
    for (int off = 1; off < 128; off <<= 1) {
        int x = (t >= off) ? s[t - off] : 0;
        __syncthreads();
        s[t] += x;
        __syncthreads();
    }
    if (t < NSCANBLK) g_blkoff[t] = s[t] - v;
    if (t == 0) { g_off[0] = 0; g_cur[0] = 0; }
}
__global__ void k_scan_fin() {
    int i = blockIdx.x * blockDim.x + threadIdx.x;
    if (i < N_NODES) {
        int v = g_off[i + 1] + g_blkoff[i >> 10];
        g_off[i + 1] = v;
        if (i + 1 < N_NODES) g_cur[i + 1] = v;
    }
}
__global__ void k_fill(const int* __restrict__ src, const int* __restrict__ dst) {
    int i = blockIdx.x * blockDim.x + threadIdx.x;
    if (i < N_EDGES) {
        int d = dst[i];
        int p = atomicAdd(&g_cur[d], 1);
        g_csr[p] = src[i];
    }
}

// ------------------------ aggregation (warp per node, unrolled x4) -----------
__global__ void k_aggregate(const __half* __restrict__ Hhi,
                            __half* __restrict__ Ahi, __half* __restrict__ Alo) {
    int warp = (blockIdx.x * blockDim.x + threadIdx.x) >> 5;
    int lane = threadIdx.x & 31;
    if (warp >= N_NODES) return;
    int s = g_off[warp];
    int e = g_off[warp + 1];
    float vx = 0.f, vy = 0.f, vz = 0.f, vw = 0.f;
    int i = s;
    const size_t loff = (size_t)(lane * 4);
    for (; i + 4 <= e; i += 4) {
        int n0 = g_csr[i], n1 = g_csr[i + 1], n2 = g_csr[i + 2], n3 = g_csr[i + 3];
        uint2 r0 = *(const uint2*)(Hhi + (size_t)n0 * 256 + loff);
        uint2 r1 = *(const uint2*)(Hhi + (size_t)n1 * 256 + loff);
        uint2 r2 = *(const uint2*)(Hhi + (size_t)n2 * 256 + loff);
        uint2 r3 = *(const uint2*)(Hhi + (size_t)n3 * 256 + loff);
        float2 a0 = __half22float2(*(__half2*)&r0.x), b0 = __half22float2(*(__half2*)&r0.y);
        float2 a1 = __half22float2(*(__half2*)&r1.x), b1 = __half22float2(*(__half2*)&r1.y);
        float2 a2 = __half22float2(*(__half2*)&r2.x), b2 = __half22float2(*(__half2*)&r2.y);
        float2 a3 = __half22float2(*(__half2*)&r3.x), b3 = __half22float2(*(__half2*)&r3.y);
        vx += (a0.x + a1.x) + (a2.x + a3.x);
        vy += (a0.y + a1.y) + (a2.y + a3.y);
        vz += (b0.x + b1.x) + (b2.x + b3.x);
        vw += (b0.y + b1.y) + (b2.y + b3.y);
    }
    for (; i < e; i++) {
        int sc = g_csr[i];
        uint2 raw = *(const uint2*)(Hhi + (size_t)sc * 256 + loff);
        float2 p0 = __half22float2(*(__half2*)&raw.x);
        float2 p1 = __half22float2(*(__half2*)&raw.y);
        vx += p0.x; vy += p0.y; vz += p1.x; vw += p1.y;
    }
    float inv = 1.f / fmaxf((float)(e - s), 1.f);
    vx *= inv; vy *= inv; vz *= inv; vw *= inv;
    __half hx = __float2half_rn(vx), hy = __float2half_rn(vy);
    __half hz = __float2half_rn(vz), hw = __float2half_rn(vw);
    __half lx = __float2half_rn(vx - __half2float(hx));
    __half ly = __float2half_rn(vy - __half2float(hy));
    __half lz = __float2half_rn(vz - __half2float(hz));
    __half lw = __float2half_rn(vw - __half2float(hw));
    size_t o = (size_t)warp * 256 + 128 + loff;
    *(__half2*)(Ahi + o)     = __halves2half2(hx, hy);
    *(__half2*)(Ahi + o + 2) = __halves2half2(hz, hw);
    *(__half2*)(Alo + o)     = __halves2half2(lx, ly);
    *(__half2*)(Alo + o + 2) = __halves2half2(lz, lw);
}

// ------------------------ HMMA GEMM: CTA 64x128, 3 CTAs/SM -------------------
// C = relu?( (Ahi+Alo) @ B^T + bias ).  2-term split, K=256 in 4 chunks of 64,
// 2-stage cp.async. 8 warps: wm in {0,1} x 32 rows, wn in {0..3} x 32 cols.
#define SA_STRIDE 72                        // halves per row (144 B)
#define A_TILE_B (64 * SA_STRIDE * 2)       // 9216 B
#define B_TILE_B (128 * SA_STRIDE * 2)      // 18432 B
#define STAGE_B (2 * A_TILE_B + B_TILE_B)   // 36864 B
#define SMEM_BYTES (2 * STAGE_B + 512 + 512 + 1024)   // 75776

__global__ __launch_bounds__(256, 3) void k_gemm_mma(
    const __half* __restrict__ Ahi, const __half* __restrict__ Alo,
    const __half* __restrict__ B,
    const float* __restrict__ bias, int relu,
    __half* __restrict__ Chi, __half* __restrict__ Clo,
    const float* __restrict__ Wfin, float* __restrict__ outv)
{
    extern __shared__ __align__(16) char smem[];
    float* sbias = (float*)(smem + 2 * STAGE_B);
    float* swfin = (float*)(smem + 2 * STAGE_B + 512);
    float (*sred)[4] = (float (*)[4])(smem + 2 * STAGE_B + 1024);

    const int tid = threadIdx.x;
    const int wid = tid >> 5;
    const int lane = tid & 31;
    const int wm = wid >> 2;        // 0..1 -> 32 rows
    const int wn = wid & 3;         // 0..3 -> 32 cols
    const int node0 = blockIdx.x * 64;
    const uint32_t sb = smem_u32(smem);

    if (tid < 128) {
        sbias[tid] = bias[tid];
        if (Wfin) swfin[tid] = Wfin[tid];
    }

    const int r0 = tid >> 3;            // 0..31
    const int s0 = tid & 7;

    // prefetch chunk 0 into stage 0
    {
        #pragma unroll
        for (int it = 0; it < 2; it++) {
            int r = r0 + it * 32;
            size_t ga = (size_t)(node0 + r) * 256 + s0 * 8;
            uint32_t so = (uint32_t)(r * SA_STRIDE + s0 * 8) * 2;
            cpa16(sb + 0 * A_TILE_B + so, Ahi + ga);
            cpa16(sb + 1 * A_TILE_B + so, Alo + ga);
        }
        #pragma unroll
        for (int it = 0; it < 4; it++) {
            int r = r0 + it * 32;
            size_t gb = (size_t)r * 256 + s0 * 8;
            uint32_t so = (uint32_t)(r * SA_STRIDE + s0 * 8) * 2;
            cpa16(sb + 2 * A_TILE_B + so, B + gb);
        }
        CP_COMMIT();
    }

    float acc[2][4][4];
    #pragma unroll
    for (int i = 0; i < 2; i++)
        #pragma unroll
        for (int j = 0; j < 4; j++)
            #pragma unroll
            for (int q = 0; q < 4; q++) acc[i][j][q] = 0.f;

    const uint32_t a_off =
        (uint32_t)(((wm * 32 + (lane & 15)) * SA_STRIDE + (lane >> 4) * 8) * 2);
    const uint32_t b_off =
        (uint32_t)(((wn * 32 + (lane & 7) + (lane >> 4) * 8) * SA_STRIDE +
                    ((lane >> 3) & 1) * 8) * 2);

    const int ar = lane >> 2;
    const int ac = (lane & 3) * 2;

    #pragma unroll 1
    for (int c = 0; c < 4; c++) {
        if (c < 3) {
            uint32_t st = ((c + 1) & 1) * STAGE_B;
            #pragma unroll
            for (int it = 0; it < 2; it++) {
                int r = r0 + it * 32;
                size_t ga = (size_t)(node0 + r) * 256 + (c + 1) * 64 + s0 * 8;
                uint32_t so = (uint32_t)(r * SA_STRIDE + s0 * 8) * 2;
                cpa16(sb + st + 0 * A_TILE_B + so, Ahi + ga);
                cpa16(sb + st + 1 * A_TILE_B + so, Alo + ga);
            }
            #pragma unroll
            for (int it = 0; it < 4; it++) {
                int r = r0 + it * 32;
                size_t gb = (size_t)r * 256 + (c + 1) * 64 + s0 * 8;
                uint32_t so = (uint32_t)(r * SA_STRIDE + s0 * 8) * 2;
                cpa16(sb + st + 2 * A_TILE_B + so, B + gb);
            }
            CP_COMMIT();
            asm volatile("cp.async.wait_group 1;" ::: "memory");
        } else {
            asm volatile("cp.async.wait_group 0;" ::: "memory");
        }
        __syncthreads();

        const uint32_t stg = sb + (c & 1) * STAGE_B;
        const uint32_t aH = stg + 0 * A_TILE_B + a_off;
        const uint32_t aL = stg + 1 * A_TILE_B + a_off;
        const uint32_t bH = stg + 2 * A_TILE_B + b_off;

        #pragma unroll
        for (int k = 0; k < 4; k++) {
            const uint32_t kb = (uint32_t)(k * 32);
            uint32_t ah[2][4], al[2][4], bb[2][4];
            ldsm4(ah[0], aH + kb);
            ldsm4(ah[1], aH + (uint32_t)(16 * SA_STRIDE * 2) + kb);
            ldsm4(bb[0], bH + kb);
            ldsm4(bb[1], bH + (uint32_t)(16 * SA_STRIDE * 2) + kb);
            ldsm4(al[0], aL + kb);
            ldsm4(al[1], aL + (uint32_t)(16 * SA_STRIDE * 2) + kb);
            // term 1: Ahi * B
            #pragma unroll
            for (int mt = 0; mt < 2; mt++)
                #pragma unroll
                for (int nt = 0; nt < 4; nt++)
                    hmma(acc[mt][nt], ah[mt], &bb[nt >> 1][(nt & 1) * 2]);
            // term 2: Alo * B
            #pragma unroll
            for (int mt = 0; mt < 2; mt++)
                #pragma unroll
                for (int nt = 0; nt < 4; nt++)
                    hmma(acc[mt][nt], al[mt], &bb[nt >> 1][(nt & 1) * 2]);
        }
        __syncthreads();
    }

    if (outv) {
        #pragma unroll
        for (int mt = 0; mt < 2; mt++) {
            #pragma unroll
            for (int half = 0; half < 2; half++) {
                int rloc = wm * 32 + mt * 16 + ar + half * 8;
                float p = 0.f;
                #pragma unroll
                for (int nt = 0; nt < 4; nt++) {
                    int col = wn * 32 + nt * 8 + ac;
                    float v0 = acc[mt][nt][half * 2 + 0] + sbias[col];
                    float v1 = acc[mt][nt][half * 2 + 1] + sbias[col + 1];
                    if (relu) { v0 = fmaxf(v0, 0.f); v1 = fmaxf(v1, 0.f); }
                    p += v0 * swfin[col] + v1 * swfin[col + 1];
                }
                p += __shfl_xor_sync(0xffffffffu, p, 1);
                p += __shfl_xor_sync(0xffffffffu, p, 2);
                if ((lane & 3) == 0) sred[rloc][wn] = p;
            }
        }
        __syncthreads();
        if (tid < 64) {
            int node = node0 + tid;
            if (node < N_NODES)
                outv[node] = (sred[tid][0] + sred[tid][1]) + (sred[tid][2] + sred[tid][3]);
        }
        return;
    }

    #pragma unroll
    for (int mt = 0; mt < 2; mt++) {
        #pragma unroll
        for (int half = 0; half < 2; half++) {
            int node = node0 + wm * 32 + mt * 16 + ar + half * 8;
            #pragma unroll
            for (int nt = 0; nt < 4; nt++) {
                int col = wn * 32 + nt * 8 + ac;
                float v0 = acc[mt][nt][half * 2 + 0] + sbias[col];
                float v1 = acc[mt][nt][half * 2 + 1] + sbias[col + 1];
                if (relu) { v0 = fmaxf(v0, 0.f); v1 = fmaxf(v1, 0.f); }
                __half h0 = __float2half_rn(v0);
                __half h1 = __float2half_rn(v1);
                __half l0 = __float2half_rn(v0 - __half2float(h0));
                __half l1 = __float2half_rn(v1 - __half2float(h1));
                size_t o = (size_t)node * 256 + col;
                *(__half2*)(Chi + o) = __halves2half2(h0, h1);
                *(__half2*)(Clo + o) = __halves2half2(l0, l1);
            }
        }
    }
}

// ------------------------ launch ---------------------------------------------
extern "C" void kernel_launch(void* const* d_in, const int* in_sizes, int n_in,
                              void* d_out, int out_size)
{
    const float* x        = (const float*)d_in[0];
    const float* W_t      = (const float*)d_in[1];
    const float* b_t      = (const float*)d_in[2];
    const float* W_self0  = (const float*)d_in[3];
    const float* b_self0  = (const float*)d_in[4];
    const float* W_neigh0 = (const float*)d_in[5];
    const float* W_self1  = (const float*)d_in[6];
    const float* b_self1  = (const float*)d_in[7];
    const float* W_neigh1 = (const float*)d_in[8];
    const float* W_fin    = (const float*)d_in[9];
    const int*   src      = (const int*)d_in[10];
    const int*   dst      = (const int*)d_in[11];
    float* out = (float*)d_out;

    cudaFuncSetAttribute(k_gemm_mma, cudaFuncAttributeMaxDynamicSharedMemorySize,
                         SMEM_BYTES);

    __half *Axhi, *Axlo, *A1hi, *A1lo, *A2hi, *A2lo;
    cudaGetSymbolAddress((void**)&Axhi, g_Axhi);
    cudaGetSymbolAddress((void**)&Axlo, g_Axlo);
    cudaGetSymbolAddress((void**)&A1hi, g_A1hi);
    cudaGetSymbolAddress((void**)&A1lo, g_A1lo);
    cudaGetSymbolAddress((void**)&A2hi, g_A2hi);
    cudaGetSymbolAddress((void**)&A2lo, g_A2lo);
    __half *Bt, *B0, *B1;
    cudaGetSymbolAddress((void**)&Bt, g_Bt);
    cudaGetSymbolAddress((void**)&B0, g_B0);
    cudaGetSymbolAddress((void**)&B1, g_B1);
    int* cntp;
    cudaGetSymbolAddress((void**)&cntp, g_cnt);

    static cudaStream_t s2 = nullptr;
    static cudaEvent_t ev_fork = nullptr, ev_join = nullptr;
    if (s2 == nullptr) {
        cudaStreamCreateWithFlags(&s2, cudaStreamNonBlocking);
        cudaEventCreateWithFlags(&ev_fork, cudaEventDisableTiming);
        cudaEventCreateWithFlags(&ev_join, cudaEventDisableTiming);
    }

    const int TB = 256;
    dim3 gridNodes((N_NODES + TB - 1) / TB);
    dim3 gridEdges((N_EDGES + TB - 1) / TB);
    dim3 gridWarp((N_NODES * 32 + TB - 1) / TB);

    // ---- fork: CSR build on s2, concurrent with convx/prep/GEMM1 ----
    cudaEventRecord(ev_fork, 0);
    cudaStreamWaitEvent(s2, ev_fork, 0);

    k_convx<<<(MPAD * 64 + TB - 1) / TB, TB>>>(x);
    k_prep_w<<<(3 * 128 * 256 + TB - 1) / TB, TB>>>(W_t, W_self0, W_neigh0,
                                                    W_self1, W_neigh1);
    cudaMemsetAsync(cntp, 0, N_NODES * sizeof(int), s2);
    k_hist<<<gridEdges, TB, 0, s2>>>(dst);
    // GEMM1 = 4th kernel launch (ncu capture slot)
    k_gemm_mma<<<NTILES64, 256, SMEM_BYTES>>>(Axhi, Axlo, Bt, b_t, 0,
                                              A1hi, A1lo, nullptr, nullptr);
    k_scan_block<<<NSCANBLK, SCAN_B, 0, s2>>>();
    k_scan_top<<<1, 128, 0, s2>>>();
    k_scan_fin<<<gridNodes, TB, 0, s2>>>();
    k_fill<<<gridEdges, TB, 0, s2>>>(src, dst);

    cudaEventRecord(ev_join, s2);
    cudaStreamWaitEvent(0, ev_join, 0);

    // layer 0
    k_aggregate<<<gridWarp, TB>>>(A1hi, A1hi, A1lo);
    k_gemm_mma<<<NTILES64, 256, SMEM_BYTES>>>(A1hi, A1lo, B0, b_self0, 1,
                                              A2hi, A2lo, nullptr, nullptr);
    // layer 1
    k_aggregate<<<gridWarp, TB>>>(A2hi, A2hi, A2lo);
    k_gemm_mma<<<NTILES64, 256, SMEM_BYTES>>>(A2hi, A2lo, B1, b_self1, 1,
                                              nullptr, nullptr, W_fin, out);
}

// round 10
// speedup vs baseline: 2.5902x; 1.1044x over previous
#include <cuda_runtime.h>
#include <cuda_fp16.h>
#include <cstdint>

#define N_NODES 100000
#define N_EDGES 1600000
#define DIN 256
#define HID 128

#define MPAD 100096
#define NTILES64 (MPAD / 64)     // 1564

// ------------------------ device scratch (no allocation) --------------------
__device__ __align__(256) __half g_A1hi[(size_t)MPAD * 256];
__device__ __align__(256) __half g_A1lo[(size_t)MPAD * 256];
__device__ __align__(256) __half g_A2hi[(size_t)MPAD * 256];
__device__ __align__(256) __half g_A2lo[(size_t)MPAD * 256];
__device__ __align__(256) __half g_Bt[128 * 256];
__device__ __align__(256) __half g_B0[128 * 256];
__device__ __align__(256) __half g_B1[128 * 256];

__device__ int g_cnt[N_NODES];
__device__ int g_off[N_NODES + 1];
__device__ int g_cur[N_NODES];
__device__ int g_csr[N_EDGES];
__device__ int g_blksum[128];
__device__ int g_blkoff[128];

#define SCAN_B 1024
#define NSCANBLK ((N_NODES + SCAN_B - 1) / SCAN_B)   // 98

// ------------------------ helpers --------------------------------------------
__device__ __forceinline__ uint32_t smem_u32(const void* p) {
    uint32_t a;
    asm("{ .reg .u64 t; cvta.to.shared.u64 t, %1; cvt.u32.u64 %0, t; }"
        : "=r"(a) : "l"(p));
    return a;
}
__device__ __forceinline__ void cpa16(uint32_t dst, const void* src) {
    asm volatile("cp.async.cg.shared.global [%0], [%1], 16;" :: "r"(dst), "l"(src));
}
#define CP_COMMIT() asm volatile("cp.async.commit_group;" ::: "memory")

__device__ __forceinline__ void ldsm4(uint32_t* r, uint32_t addr) {
    asm volatile("ldmatrix.sync.aligned.m8n8.x4.shared.b16 {%0,%1,%2,%3}, [%4];"
                 : "=r"(r[0]), "=r"(r[1]), "=r"(r[2]), "=r"(r[3]) : "r"(addr));
}
__device__ __forceinline__ void hmma(float* d, const uint32_t* a, const uint32_t* b) {
    asm volatile(
        "mma.sync.aligned.m16n8k16.row.col.f32.f16.f16.f32 "
        "{%0,%1,%2,%3}, {%4,%5,%6,%7}, {%8,%9}, {%0,%1,%2,%3};"
        : "+f"(d[0]), "+f"(d[1]), "+f"(d[2]), "+f"(d[3])
        : "r"(a[0]), "r"(a[1]), "r"(a[2]), "r"(a[3]), "r"(b[0]), "r"(b[1]));
}

// ------------------------ weight prep ----------------------------------------
__global__ void k_prep_w(const float* __restrict__ W_t,
                         const float* __restrict__ W_self0, const float* __restrict__ W_neigh0,
                         const float* __restrict__ W_self1, const float* __restrict__ W_neigh1) {
    int g = blockIdx.x * blockDim.x + threadIdx.x;
    if (g >= 3 * 128 * 256) return;
    int which = g / (128 * 256);
    int r = g % (128 * 256);
    int n = r / 256;
    int k = r % 256;
    float w;
    __half* dh;
    if (which == 0) { w = W_t[(size_t)k * 128 + n]; dh = g_Bt; }
    else if (which == 1) {
        w = (k < 128) ? W_self0[(size_t)k * 128 + n] : W_neigh0[(size_t)(k - 128) * 128 + n];
        dh = g_B0;
    } else {
        w = (k < 128) ? W_self1[(size_t)k * 128 + n] : W_neigh1[(size_t)(k - 128) * 128 + n];
        dh = g_B1;
    }
    dh[(size_t)n * 256 + k] = __float2half_rn(w);
}

// ------------------------ CSR build ------------------------------------------
__global__ void k_hist(const int* __restrict__ dst) {
    int i = blockIdx.x * blockDim.x + threadIdx.x;
    if (i < N_EDGES) atomicAdd(&g_cnt[dst[i]], 1);
}
__global__ void k_scan_block() {
    __shared__ int s[SCAN_B];
    int t = threadIdx.x;
    int i = blockIdx.x * SCAN_B + t;
    int v = (i < N_NODES) ? g_cnt[i] : 0;
    s[t] = v;
    __syncthreads();
    #pragma unroll
    for (int off = 1; off < SCAN_B; off <<= 1) {
        int x = (t >= off) ? s[t - off] : 0;
        __syncthreads();
        s[t] += x;
        __syncthreads();
    }
    if (i < N_NODES) g_off[i + 1] = s[t];
    if (t == SCAN_B - 1) g_blksum[blockIdx.x] = s[t];
}
__global__ void k_scan_top() {
    __shared__ int s[128];
    int t = threadIdx.x;
    int v = (t < NSCANBLK) ? g_blksum[t] : 0;
    s[t] = v;
    __syncthreads();
    #pragma unroll
    for (int off = 1; off < 128; off <<= 1) {
        int x = (t >= off) ? s[t - off] : 0;
        __syncthreads();
        s[t] += x;
        __syncthreads();
    }
    if (t < NSCANBLK) g_blkoff[t] = s[t] - v;
    if (t == 0) { g_off[0] = 0; g_cur[0] = 0; }
}
__global__ void k_scan_fin() {
    int i = blockIdx.x * blockDim.x + threadIdx.x;
    if (i < N_NODES) {
        int v = g_off[i + 1] + g_blkoff[i >> 10];
        g_off[i + 1] = v;
        if (i + 1 < N_NODES) g_cur[i + 1] = v;
    }
}
__global__ void k_fill(const int* __restrict__ src, const int* __restrict__ dst) {
    int i = blockIdx.x * blockDim.x + threadIdx.x;
    if (i < N_EDGES) {
        int d = dst[i];
        int p = atomicAdd(&g_cur[d], 1);
        g_csr[p] = src[i];
    }
}

// ------------------------ aggregation (warp per node, unrolled x4) -----------
__global__ void k_aggregate(const __half* __restrict__ Hhi,
                            __half* __restrict__ Ahi, __half* __restrict__ Alo) {
    int warp = (blockIdx.x * blockDim.x + threadIdx.x) >> 5;
    int lane = threadIdx.x & 31;
    if (warp >= N_NODES) return;
    int s = g_off[warp];
    int e = g_off[warp + 1];
    float vx = 0.f, vy = 0.f, vz = 0.f, vw = 0.f;
    int i = s;
    const size_t loff = (size_t)(lane * 4);
    for (; i + 4 <= e; i += 4) {
        int n0 = g_csr[i], n1 = g_csr[i + 1], n2 = g_csr[i + 2], n3 = g_csr[i + 3];
        uint2 r0 = *(const uint2*)(Hhi + (size_t)n0 * 256 + loff);
        uint2 r1 = *(const uint2*)(Hhi + (size_t)n1 * 256 + loff);
        uint2 r2 = *(const uint2*)(Hhi + (size_t)n2 * 256 + loff);
        uint2 r3 = *(const uint2*)(Hhi + (size_t)n3 * 256 + loff);
        float2 a0 = __half22float2(*(__half2*)&r0.x), b0 = __half22float2(*(__half2*)&r0.y);
        float2 a1 = __half22float2(*(__half2*)&r1.x), b1 = __half22float2(*(__half2*)&r1.y);
        float2 a2 = __half22float2(*(__half2*)&r2.x), b2 = __half22float2(*(__half2*)&r2.y);
        float2 a3 = __half22float2(*(__half2*)&r3.x), b3 = __half22float2(*(__half2*)&r3.y);
        vx += (a0.x + a1.x) + (a2.x + a3.x);
        vy += (a0.y + a1.y) + (a2.y + a3.y);
        vz += (b0.x + b1.x) + (b2.x + b3.x);
        vw += (b0.y + b1.y) + (b2.y + b3.y);
    }
    for (; i < e; i++) {
        int sc = g_csr[i];
        uint2 raw = *(const uint2*)(Hhi + (size_t)sc * 256 + loff);
        float2 p0 = __half22float2(*(__half2*)&raw.x);
        float2 p1 = __half22float2(*(__half2*)&raw.y);
        vx += p0.x; vy += p0.y; vz += p1.x; vw += p1.y;
    }
    float inv = 1.f / fmaxf((float)(e - s), 1.f);
    vx *= inv; vy *= inv; vz *= inv; vw *= inv;
    __half hx = __float2half_rn(vx), hy = __float2half_rn(vy);
    __half hz = __float2half_rn(vz), hw = __float2half_rn(vw);
    __half lx = __float2half_rn(vx - __half2float(hx));
    __half ly = __float2half_rn(vy - __half2float(hy));
    __half lz = __float2half_rn(vz - __half2float(hz));
    __half lw = __float2half_rn(vw - __half2float(hw));
    size_t o = (size_t)warp * 256 + 128 + loff;
    *(__half2*)(Ahi + o)     = __halves2half2(hx, hy);
    *(__half2*)(Ahi + o + 2) = __halves2half2(hz, hw);
    *(__half2*)(Alo + o)     = __halves2half2(lx, ly);
    *(__half2*)(Alo + o + 2) = __halves2half2(lz, lw);
}

// ------------------------ shared GEMM geometry -------------------------------
#define SA_STRIDE 72                        // halves per row (144 B)
#define A_TILE_B (64 * SA_STRIDE * 2)       // 9216 B
#define B_TILE_B (128 * SA_STRIDE * 2)      // 18432 B

// ------------------------ GEMM1: x(fp32, convert-on-load, hi-only) -----------
// C = x @ Bt^T + bias.  Single-term fp16. A loaded via LDG+cvt+STS (reg-staged
// double buffer); B via cp.async. CTA 64x128, 8 warps, warp tile 32x32.
#define X_STAGE_B (A_TILE_B + B_TILE_B)                 // 27648
#define SMEM_X (2 * X_STAGE_B + 512)                    // 55808

__global__ __launch_bounds__(256, 3) void k_gemm_x(
    const float* __restrict__ X, const __half* __restrict__ B,
    const float* __restrict__ bias,
    __half* __restrict__ Chi, __half* __restrict__ Clo)
{
    extern __shared__ __align__(16) char smem[];
    float* sbias = (float*)(smem + 2 * X_STAGE_B);

    const int tid = threadIdx.x;
    const int wid = tid >> 5;
    const int lane = tid & 31;
    const int wm = wid >> 2;
    const int wn = wid & 3;
    const int node0 = blockIdx.x * 64;
    const uint32_t sb = smem_u32(smem);

    if (tid < 128) sbias[tid] = bias[tid];

    // A loader mapping: thread -> row r0x (0..63), 4 float4 segs per chunk
    const int r0x = tid >> 2;
    const int s0x = tid & 3;
    // B loader mapping (cp.async)
    const int r0 = tid >> 3;
    const int s0 = tid & 7;

    float4 f[4];
    // prologue: LDG A chunk0, cp.async B chunk0 into stage 0
    {
        #pragma unroll
        for (int it = 0; it < 4; it++) {
            int seg = s0x + it * 4;
            int row = node0 + r0x;
            f[it] = (row < N_NODES)
                ? *(const float4*)(X + (size_t)row * 256 + 0 * 64 + seg * 4)
                : make_float4(0.f, 0.f, 0.f, 0.f);
        }
        #pragma unroll
        for (int it = 0; it < 4; it++) {
            int r = r0 + it * 32;
            cpa16(sb + A_TILE_B + (uint32_t)(r * SA_STRIDE + s0 * 8) * 2,
                  B + (size_t)r * 256 + 0 * 64 + s0 * 8);
        }
        CP_COMMIT();
        // STS A chunk0
        #pragma unroll
        for (int it = 0; it < 4; it++) {
            int seg = s0x + it * 4;
            __half2 h0 = __floats2half2_rn(f[it].x, f[it].y);
            __half2 h1 = __floats2half2_rn(f[it].z, f[it].w);
            uint2* p = (uint2*)(smem + (uint32_t)(r0x * SA_STRIDE + seg * 4) * 2);
            *p = make_uint2(*(uint32_t*)&h0, *(uint32_t*)&h1);
        }
    }

    float acc[2][4][4];
    #pragma unroll
    for (int i = 0; i < 2; i++)
        #pragma unroll
        for (int j = 0; j < 4; j++)
            #pragma unroll
            for (int q = 0; q < 4; q++) acc[i][j][q] = 0.f;

    const uint32_t a_off =
        (uint32_t)(((wm * 32 + (lane & 15)) * SA_STRIDE + (lane >> 4) * 8) * 2);
    const uint32_t b_off =
        (uint32_t)(((wn * 32 + (lane & 7) + (lane >> 4) * 8) * SA_STRIDE +
                    ((lane >> 3) & 1) * 8) * 2);

    const int ar = lane >> 2;
    const int ac = (lane & 3) * 2;

    #pragma unroll 1
    for (int c = 0; c < 4; c++) {
        if (c < 3) {
            // LDG next A chunk (latency hidden by MMA below)
            #pragma unroll
            for (int it = 0; it < 4; it++) {
                int seg = s0x + it * 4;
                int row = node0 + r0x;
                f[it] = (row < N_NODES)
                    ? *(const float4*)(X + (size_t)row * 256 + (c + 1) * 64 + seg * 4)
                    : make_float4(0.f, 0.f, 0.f, 0.f);
            }
            uint32_t st = ((c + 1) & 1) * X_STAGE_B;
            #pragma unroll
            for (int it = 0; it < 4; it++) {
                int r = r0 + it * 32;
                cpa16(sb + st + A_TILE_B + (uint32_t)(r * SA_STRIDE + s0 * 8) * 2,
                      B + (size_t)r * 256 + (c + 1) * 64 + s0 * 8);
            }
            CP_COMMIT();
            asm volatile("cp.async.wait_group 1;" ::: "memory");
        } else {
            asm volatile("cp.async.wait_group 0;" ::: "memory");
        }
        __syncthreads();

        const uint32_t stg = sb + (c & 1) * X_STAGE_B;
        const uint32_t aH = stg + a_off;
        const uint32_t bH = stg + A_TILE_B + b_off;

        #pragma unroll
        for (int k = 0; k < 4; k++) {
            const uint32_t kb = (uint32_t)(k * 32);
            uint32_t ah[2][4], bb[2][4];
            ldsm4(ah[0], aH + kb);
            ldsm4(ah[1], aH + (uint32_t)(16 * SA_STRIDE * 2) + kb);
            ldsm4(bb[0], bH + kb);
            ldsm4(bb[1], bH + (uint32_t)(16 * SA_STRIDE * 2) + kb);
            #pragma unroll
            for (int mt = 0; mt < 2; mt++)
                #pragma unroll
                for (int nt = 0; nt < 4; nt++)
                    hmma(acc[mt][nt], ah[mt], &bb[nt >> 1][(nt & 1) * 2]);
        }

        // STS next A chunk into the other stage (read only after next barrier)
        if (c < 3) {
            uint32_t st = ((c + 1) & 1) * X_STAGE_B;
            #pragma unroll
            for (int it = 0; it < 4; it++) {
                int seg = s0x + it * 4;
                __half2 h0 = __floats2half2_rn(f[it].x, f[it].y);
                __half2 h1 = __floats2half2_rn(f[it].z, f[it].w);
                uint2* p = (uint2*)(smem + st + (uint32_t)(r0x * SA_STRIDE + seg * 4) * 2);
                *p = make_uint2(*(uint32_t*)&h0, *(uint32_t*)&h1);
            }
        }
        __syncthreads();
    }

    // epilogue: write hi/lo halves (cols 0..127 of next layer A)
    #pragma unroll
    for (int mt = 0; mt < 2; mt++) {
        #pragma unroll
        for (int half = 0; half < 2; half++) {
            int node = node0 + wm * 32 + mt * 16 + ar + half * 8;
            #pragma unroll
            for (int nt = 0; nt < 4; nt++) {
                int col = wn * 32 + nt * 8 + ac;
                float v0 = acc[mt][nt][half * 2 + 0] + sbias[col];
                float v1 = acc[mt][nt][half * 2 + 1] + sbias[col + 1];
                __half h0 = __float2half_rn(v0);
                __half h1 = __float2half_rn(v1);
                __half l0 = __float2half_rn(v0 - __half2float(h0));
                __half l1 = __float2half_rn(v1 - __half2float(h1));
                size_t o = (size_t)node * 256 + col;
                *(__half2*)(Chi + o) = __halves2half2(h0, h1);
                *(__half2*)(Clo + o) = __halves2half2(l0, l1);
            }
        }
    }
}

// ------------------------ HMMA GEMM: CTA 64x128, 3 CTAs/SM (R9, proven) ------
#define STAGE_B (2 * A_TILE_B + B_TILE_B)   // 36864 B
#define SMEM_BYTES (2 * STAGE_B + 512 + 512 + 1024)   // 75776

__global__ __launch_bounds__(256, 3) void k_gemm_mma(
    const __half* __restrict__ Ahi, const __half* __restrict__ Alo,
    const __half* __restrict__ B,
    const float* __restrict__ bias, int relu,
    __half* __restrict__ Chi, __half* __restrict__ Clo,
    const float* __restrict__ Wfin, float* __restrict__ outv)
{
    extern __shared__ __align__(16) char smem[];
    float* sbias = (float*)(smem + 2 * STAGE_B);
    float* swfin = (float*)(smem + 2 * STAGE_B + 512);
    float (*sred)[4] = (float (*)[4])(smem + 2 * STAGE_B + 1024);

    const int tid = threadIdx.x;
    const int wid = tid >> 5;
    const int lane = tid & 31;
    const int wm = wid >> 2;
    const int wn = wid & 3;
    const int node0 = blockIdx.x * 64;
    const uint32_t sb = smem_u32(smem);

    if (tid < 128) {
        sbias[tid] = bias[tid];
        if (Wfin) swfin[tid] = Wfin[tid];
    }

    const int r0 = tid >> 3;
    const int s0 = tid & 7;

    {
        #pragma unroll
        for (int it = 0; it < 2; it++) {
            int r = r0 + it * 32;
            size_t ga = (size_t)(node0 + r) * 256 + s0 * 8;
            uint32_t so = (uint32_t)(r * SA_STRIDE + s0 * 8) * 2;
            cpa16(sb + 0 * A_TILE_B + so, Ahi + ga);
            cpa16(sb + 1 * A_TILE_B + so, Alo + ga);
        }
        #pragma unroll
        for (int it = 0; it < 4; it++) {
            int r = r0 + it * 32;
            size_t gb = (size_t)r * 256 + s0 * 8;
            uint32_t so = (uint32_t)(r * SA_STRIDE + s0 * 8) * 2;
            cpa16(sb + 2 * A_TILE_B + so, B + gb);
        }
        CP_COMMIT();
    }

    float acc[2][4][4];
    #pragma unroll
    for (int i = 0; i < 2; i++)
        #pragma unroll
        for (int j = 0; j < 4; j++)
            #pragma unroll
            for (int q = 0; q < 4; q++) acc[i][j][q] = 0.f;

    const uint32_t a_off =
        (uint32_t)(((wm * 32 + (lane & 15)) * SA_STRIDE + (lane >> 4) * 8) * 2);
    const uint32_t b_off =
        (uint32_t)(((wn * 32 + (lane & 7) + (lane >> 4) * 8) * SA_STRIDE +
                    ((lane >> 3) & 1) * 8) * 2);

    const int ar = lane >> 2;
    const int ac = (lane & 3) * 2;

    #pragma unroll 1
    for (int c = 0; c < 4; c++) {
        if (c < 3) {
            uint32_t st = ((c + 1) & 1) * STAGE_B;
            #pragma unroll
            for (int it = 0; it < 2; it++) {
                int r = r0 + it * 32;
                size_t ga = (size_t)(node0 + r) * 256 + (c + 1) * 64 + s0 * 8;
                uint32_t so = (uint32_t)(r * SA_STRIDE + s0 * 8) * 2;
                cpa16(sb + st + 0 * A_TILE_B + so, Ahi + ga);
                cpa16(sb + st + 1 * A_TILE_B + so, Alo + ga);
            }
            #pragma unroll
            for (int it = 0; it < 4; it++) {
                int r = r0 + it * 32;
                size_t gb = (size_t)r * 256 + (c + 1) * 64 + s0 * 8;
                uint32_t so = (uint32_t)(r * SA_STRIDE + s0 * 8) * 2;
                cpa16(sb + st + 2 * A_TILE_B + so, B + gb);
            }
            CP_COMMIT();
            asm volatile("cp.async.wait_group 1;" ::: "memory");
        } else {
            asm volatile("cp.async.wait_group 0;" ::: "memory");
        }
        __syncthreads();

        const uint32_t stg = sb + (c & 1) * STAGE_B;
        const uint32_t aH = stg + 0 * A_TILE_B + a_off;
        const uint32_t aL = stg + 1 * A_TILE_B + a_off;
        const uint32_t bH = stg + 2 * A_TILE_B + b_off;

        #pragma unroll
        for (int k = 0; k < 4; k++) {
            const uint32_t kb = (uint32_t)(k * 32);
            uint32_t ah[2][4], al[2][4], bb[2][4];
            ldsm4(ah[0], aH + kb);
            ldsm4(ah[1], aH + (uint32_t)(16 * SA_STRIDE * 2) + kb);
            ldsm4(bb[0], bH + kb);
            ldsm4(bb[1], bH + (uint32_t)(16 * SA_STRIDE * 2) + kb);
            ldsm4(al[0], aL + kb);
            ldsm4(al[1], aL + (uint32_t)(16 * SA_STRIDE * 2) + kb);
            #pragma unroll
            for (int mt = 0; mt < 2; mt++)
                #pragma unroll
                for (int nt = 0; nt < 4; nt++)
                    hmma(acc[mt][nt], ah[mt], &bb[nt >> 1][(nt & 1) * 2]);
            #pragma unroll
            for (int mt = 0; mt < 2; mt++)
                #pragma unroll
                for (int nt = 0; nt < 4; nt++)
                    hmma(acc[mt][nt], al[mt], &bb[nt >> 1][(nt & 1) * 2]);
        }
        __syncthreads();
    }

    if (outv) {
        #pragma unroll
        for (int mt = 0; mt < 2; mt++) {
            #pragma unroll
            for (int half = 0; half < 2; half++) {
                int rloc = wm * 32 + mt * 16 + ar + half * 8;
                float p = 0.f;
                #pragma unroll
                for (int nt = 0; nt < 4; nt++) {
                    int col = wn * 32 + nt * 8 + ac;
                    float v0 = acc[mt][nt][half * 2 + 0] + sbias[col];
                    float v1 = acc[mt][nt][half * 2 + 1] + sbias[col + 1];
                    if (relu) { v0 = fmaxf(v0, 0.f); v1 = fmaxf(v1, 0.f); }
                    p += v0 * swfin[col] + v1 * swfin[col + 1];
                }
                p += __shfl_xor_sync(0xffffffffu, p, 1);
                p += __shfl_xor_sync(0xffffffffu, p, 2);
                if ((lane & 3) == 0) sred[rloc][wn] = p;
            }
        }
        __syncthreads();
        if (tid < 64) {
            int node = node0 + tid;
            if (node < N_NODES)
                outv[node] = (sred[tid][0] + sred[tid][1]) + (sred[tid][2] + sred[tid][3]);
        }
        return;
    }

    #pragma unroll
    for (int mt = 0; mt < 2; mt++) {
        #pragma unroll
        for (int half = 0; half < 2; half++) {
            int node = node0 + wm * 32 + mt * 16 + ar + half * 8;
            #pragma unroll
            for (int nt = 0; nt < 4; nt++) {
                int col = wn * 32 + nt * 8 + ac;
                float v0 = acc[mt][nt][half * 2 + 0] + sbias[col];
                float v1 = acc[mt][nt][half * 2 + 1] + sbias[col + 1];
                if (relu) { v0 = fmaxf(v0, 0.f); v1 = fmaxf(v1, 0.f); }
                __half h0 = __float2half_rn(v0);
                __half h1 = __float2half_rn(v1);
                __half l0 = __float2half_rn(v0 - __half2float(h0));
                __half l1 = __float2half_rn(v1 - __half2float(h1));
                size_t o = (size_t)node * 256 + col;
                *(__half2*)(Chi + o) = __halves2half2(h0, h1);
                *(__half2*)(Clo + o) = __halves2half2(l0, l1);
            }
        }
    }
}

// ------------------------ launch ---------------------------------------------
extern "C" void kernel_launch(void* const* d_in, const int* in_sizes, int n_in,
                              void* d_out, int out_size)
{
    const float* x        = (const float*)d_in[0];
    const float* W_t      = (const float*)d_in[1];
    const float* b_t      = (const float*)d_in[2];
    const float* W_self0  = (const float*)d_in[3];
    const float* b_self0  = (const float*)d_in[4];
    const float* W_neigh0 = (const float*)d_in[5];
    const float* W_self1  = (const float*)d_in[6];
    const float* b_self1  = (const float*)d_in[7];
    const float* W_neigh1 = (const float*)d_in[8];
    const float* W_fin    = (const float*)d_in[9];
    const int*   src      = (const int*)d_in[10];
    const int*   dst      = (const int*)d_in[11];
    float* out = (float*)d_out;

    cudaFuncSetAttribute(k_gemm_mma, cudaFuncAttributeMaxDynamicSharedMemorySize,
                         SMEM_BYTES);
    cudaFuncSetAttribute(k_gemm_x, cudaFuncAttributeMaxDynamicSharedMemorySize,
                         SMEM_X);

    __half *A1hi, *A1lo, *A2hi, *A2lo;
    cudaGetSymbolAddress((void**)&A1hi, g_A1hi);
    cudaGetSymbolAddress((void**)&A1lo, g_A1lo);
    cudaGetSymbolAddress((void**)&A2hi, g_A2hi);
    cudaGetSymbolAddress((void**)&A2lo, g_A2lo);
    __half *Bt, *B0, *B1;
    cudaGetSymbolAddress((void**)&Bt, g_Bt);
    cudaGetSymbolAddress((void**)&B0, g_B0);
    cudaGetSymbolAddress((void**)&B1, g_B1);
    int* cntp;
    cudaGetSymbolAddress((void**)&cntp, g_cnt);

    static cudaStream_t s2 = nullptr;
    static cudaEvent_t ev_fork = nullptr, ev_join = nullptr;
    if (s2 == nullptr) {
        cudaStreamCreateWithFlags(&s2, cudaStreamNonBlocking);
        cudaEventCreateWithFlags(&ev_fork, cudaEventDisableTiming);
        cudaEventCreateWithFlags(&ev_join, cudaEventDisableTiming);
    }

    const int TB = 256;
    dim3 gridNodes((N_NODES + TB - 1) / TB);
    dim3 gridEdges((N_EDGES + TB - 1) / TB);
    dim3 gridWarp((N_NODES * 32 + TB - 1) / TB);

    // ---- fork: CSR build on s2, concurrent with prep/GEMM1 ----
    cudaEventRecord(ev_fork, 0);
    cudaStreamWaitEvent(s2, ev_fork, 0);

    k_prep_w<<<(3 * 128 * 256 + TB - 1) / TB, TB>>>(W_t, W_self0, W_neigh0,
                                                    W_self1, W_neigh1);
    cudaMemsetAsync(cntp, 0, N_NODES * sizeof(int), s2);
    k_hist<<<gridEdges, TB, 0, s2>>>(dst);
    // GEMM1: fused x conversion, hi-only
    k_gemm_x<<<NTILES64, 256, SMEM_X>>>(x, Bt, b_t, A1hi, A1lo);
    k_scan_block<<<NSCANBLK, SCAN_B, 0, s2>>>();
    k_scan_top<<<1, 128, 0, s2>>>();
    k_scan_fin<<<gridNodes, TB, 0, s2>>>();
    k_fill<<<gridEdges, TB, 0, s2>>>(src, dst);

    cudaEventRecord(ev_join, s2);
    cudaStreamWaitEvent(0, ev_join, 0);

    // layer 0
    k_aggregate<<<gridWarp, TB>>>(A1hi, A1hi, A1lo);
    k_gemm_mma<<<NTILES64, 256, SMEM_BYTES>>>(A1hi, A1lo, B0, b_self0, 1,
                                              A2hi, A2lo, nullptr, nullptr);
    // layer 1
    k_aggregate<<<gridWarp, TB>>>(A2hi, A2hi, A2lo);
    k_gemm_mma<<<NTILES64, 256, SMEM_BYTES>>>(A2hi, A2lo, B1, b_self1, 1,
                                              nullptr, nullptr, W_fin, out);
}

// round 11
// speedup vs baseline: 3.0453x; 1.1757x over previous
#include <cuda_runtime.h>
#include <cuda_fp16.h>
#include <cstdint>

#define N_NODES 100000
#define N_EDGES 1600000
#define DIN 256
#define HID 128

#define MPAD 100096
#define NTILES64 (MPAD / 64)     // 1564

// ------------------------ device scratch (no allocation) --------------------
__device__ __align__(256) __half g_A1[(size_t)MPAD * 256];   // h0 | h_neigh0 (fp16)
__device__ __align__(256) __half g_A2[(size_t)MPAD * 256];   // h1 | h_neigh1 (fp16)
__device__ __align__(256) __half g_Bt[128 * 256];
__device__ __align__(256) __half g_B0[128 * 256];
__device__ __align__(256) __half g_B1[128 * 256];

__device__ int g_cnt[N_NODES];
__device__ int g_off[N_NODES + 1];
__device__ int g_cur[N_NODES];
__device__ int g_csr[N_EDGES];
__device__ int g_blksum[128];
__device__ int g_blkoff[128];

#define SCAN_B 1024
#define NSCANBLK ((N_NODES + SCAN_B - 1) / SCAN_B)   // 98

// ------------------------ helpers --------------------------------------------
__device__ __forceinline__ uint32_t smem_u32(const void* p) {
    uint32_t a;
    asm("{ .reg .u64 t; cvta.to.shared.u64 t, %1; cvt.u32.u64 %0, t; }"
        : "=r"(a) : "l"(p));
    return a;
}
__device__ __forceinline__ void cpa16(uint32_t dst, const void* src) {
    asm volatile("cp.async.cg.shared.global [%0], [%1], 16;" :: "r"(dst), "l"(src));
}
#define CP_COMMIT() asm volatile("cp.async.commit_group;" ::: "memory")

__device__ __forceinline__ void ldsm4(uint32_t* r, uint32_t addr) {
    asm volatile("ldmatrix.sync.aligned.m8n8.x4.shared.b16 {%0,%1,%2,%3}, [%4];"
                 : "=r"(r[0]), "=r"(r[1]), "=r"(r[2]), "=r"(r[3]) : "r"(addr));
}
__device__ __forceinline__ void hmma(float* d, const uint32_t* a, const uint32_t* b) {
    asm volatile(
        "mma.sync.aligned.m16n8k16.row.col.f32.f16.f16.f32 "
        "{%0,%1,%2,%3}, {%4,%5,%6,%7}, {%8,%9}, {%0,%1,%2,%3};"
        : "+f"(d[0]), "+f"(d[1]), "+f"(d[2]), "+f"(d[3])
        : "r"(a[0]), "r"(a[1]), "r"(a[2]), "r"(a[3]), "r"(b[0]), "r"(b[1]));
}

// ------------------------ weight prep ----------------------------------------
__global__ void k_prep_w(const float* __restrict__ W_t,
                         const float* __restrict__ W_self0, const float* __restrict__ W_neigh0,
                         const float* __restrict__ W_self1, const float* __restrict__ W_neigh1) {
    int g = blockIdx.x * blockDim.x + threadIdx.x;
    if (g >= 3 * 128 * 256) return;
    int which = g / (128 * 256);
    int r = g % (128 * 256);
    int n = r / 256;
    int k = r % 256;
    float w;
    __half* dh;
    if (which == 0) { w = W_t[(size_t)k * 128 + n]; dh = g_Bt; }
    else if (which == 1) {
        w = (k < 128) ? W_self0[(size_t)k * 128 + n] : W_neigh0[(size_t)(k - 128) * 128 + n];
        dh = g_B0;
    } else {
        w = (k < 128) ? W_self1[(size_t)k * 128 + n] : W_neigh1[(size_t)(k - 128) * 128 + n];
        dh = g_B1;
    }
    dh[(size_t)n * 256 + k] = __float2half_rn(w);
}

// ------------------------ CSR build ------------------------------------------
__global__ void k_hist(const int* __restrict__ dst) {
    int i = blockIdx.x * blockDim.x + threadIdx.x;
    if (i < N_EDGES) atomicAdd(&g_cnt[dst[i]], 1);
}
__global__ void k_scan_block() {
    __shared__ int s[SCAN_B];
    int t = threadIdx.x;
    int i = blockIdx.x * SCAN_B + t;
    int v = (i < N_NODES) ? g_cnt[i] : 0;
    s[t] = v;
    __syncthreads();
    #pragma unroll
    for (int off = 1; off < SCAN_B; off <<= 1) {
        int x = (t >= off) ? s[t - off] : 0;
        __syncthreads();
        s[t] += x;
        __syncthreads();
    }
    if (i < N_NODES) g_off[i + 1] = s[t];
    if (t == SCAN_B - 1) g_blksum[blockIdx.x] = s[t];
}
__global__ void k_scan_top() {
    __shared__ int s[128];
    int t = threadIdx.x;
    int v = (t < NSCANBLK) ? g_blksum[t] : 0;
    s[t] = v;
    __syncthreads();
    #pragma unroll
    for (int off = 1; off < 128; off <<= 1) {
        int x = (t >= off) ? s[t - off] : 0;
        __syncthreads();
        s[t] += x;
        __syncthreads();
    }
    if (t < NSCANBLK) g_blkoff[t] = s[t] - v;
    if (t == 0) { g_off[0] = 0; g_cur[0] = 0; }
}
__global__ void k_scan_fin() {
    int i = blockIdx.x * blockDim.x + threadIdx.x;
    if (i < N_NODES) {
        int v = g_off[i + 1] + g_blkoff[i >> 10];
        g_off[i + 1] = v;
        if (i + 1 < N_NODES) g_cur[i + 1] = v;
    }
}
__global__ void k_fill(const int* __restrict__ src, const int* __restrict__ dst) {
    int i = blockIdx.x * blockDim.x + threadIdx.x;
    if (i < N_EDGES) {
        int d = dst[i];
        int p = atomicAdd(&g_cur[d], 1);
        g_csr[p] = src[i];
    }
}

// ------------------------ aggregation (warp per node, hi-only) ---------------
__global__ void k_aggregate(const __half* __restrict__ H, __half* __restrict__ A) {
    int warp = (blockIdx.x * blockDim.x + threadIdx.x) >> 5;
    int lane = threadIdx.x & 31;
    if (warp >= N_NODES) return;
    int s = g_off[warp];
    int e = g_off[warp + 1];
    float vx = 0.f, vy = 0.f, vz = 0.f, vw = 0.f;
    int i = s;
    const size_t loff = (size_t)(lane * 4);
    for (; i + 4 <= e; i += 4) {
        int n0 = g_csr[i], n1 = g_csr[i + 1], n2 = g_csr[i + 2], n3 = g_csr[i + 3];
        uint2 r0 = *(const uint2*)(H + (size_t)n0 * 256 + loff);
        uint2 r1 = *(const uint2*)(H + (size_t)n1 * 256 + loff);
        uint2 r2 = *(const uint2*)(H + (size_t)n2 * 256 + loff);
        uint2 r3 = *(const uint2*)(H + (size_t)n3 * 256 + loff);
        float2 a0 = __half22float2(*(__half2*)&r0.x), b0 = __half22float2(*(__half2*)&r0.y);
        float2 a1 = __half22float2(*(__half2*)&r1.x), b1 = __half22float2(*(__half2*)&r1.y);
        float2 a2 = __half22float2(*(__half2*)&r2.x), b2 = __half22float2(*(__half2*)&r2.y);
        float2 a3 = __half22float2(*(__half2*)&r3.x), b3 = __half22float2(*(__half2*)&r3.y);
        vx += (a0.x + a1.x) + (a2.x + a3.x);
        vy += (a0.y + a1.y) + (a2.y + a3.y);
        vz += (b0.x + b1.x) + (b2.x + b3.x);
        vw += (b0.y + b1.y) + (b2.y + b3.y);
    }
    for (; i < e; i++) {
        int sc = g_csr[i];
        uint2 raw = *(const uint2*)(H + (size_t)sc * 256 + loff);
        float2 p0 = __half22float2(*(__half2*)&raw.x);
        float2 p1 = __half22float2(*(__half2*)&raw.y);
        vx += p0.x; vy += p0.y; vz += p1.x; vw += p1.y;
    }
    float inv = 1.f / fmaxf((float)(e - s), 1.f);
    __half2 h0 = __floats2half2_rn(vx * inv, vy * inv);
    __half2 h1 = __floats2half2_rn(vz * inv, vw * inv);
    size_t o = (size_t)warp * 256 + 128 + loff;
    *(__half2*)(A + o)     = h0;
    *(__half2*)(A + o + 2) = h1;
}

// ------------------------ shared GEMM geometry -------------------------------
#define SA_STRIDE 72                        // halves per row (144 B)
#define A_TILE_B (64 * SA_STRIDE * 2)       // 9216 B
#define B_TILE_B (128 * SA_STRIDE * 2)      // 18432 B

// ------------------------ GEMM1: x(fp32, convert-on-load) --------------------
#define X_STAGE_B (A_TILE_B + B_TILE_B)                 // 27648
#define SMEM_X (2 * X_STAGE_B + 512)                    // 55808

__global__ __launch_bounds__(256, 3) void k_gemm_x(
    const float* __restrict__ X, const __half* __restrict__ B,
    const float* __restrict__ bias, __half* __restrict__ C)
{
    extern __shared__ __align__(16) char smem[];
    float* sbias = (float*)(smem + 2 * X_STAGE_B);

    const int tid = threadIdx.x;
    const int wid = tid >> 5;
    const int lane = tid & 31;
    const int wm = wid >> 2;
    const int wn = wid & 3;
    const int node0 = blockIdx.x * 64;
    const uint32_t sb = smem_u32(smem);

    if (tid < 128) sbias[tid] = bias[tid];

    const int r0x = tid >> 2;
    const int s0x = tid & 3;
    const int r0 = tid >> 3;
    const int s0 = tid & 7;

    float4 f[4];
    {
        #pragma unroll
        for (int it = 0; it < 4; it++) {
            int seg = s0x + it * 4;
            int row = node0 + r0x;
            f[it] = (row < N_NODES)
                ? *(const float4*)(X + (size_t)row * 256 + 0 * 64 + seg * 4)
                : make_float4(0.f, 0.f, 0.f, 0.f);
        }
        #pragma unroll
        for (int it = 0; it < 4; it++) {
            int r = r0 + it * 32;
            cpa16(sb + A_TILE_B + (uint32_t)(r * SA_STRIDE + s0 * 8) * 2,
                  B + (size_t)r * 256 + 0 * 64 + s0 * 8);
        }
        CP_COMMIT();
        #pragma unroll
        for (int it = 0; it < 4; it++) {
            int seg = s0x + it * 4;
            __half2 h0 = __floats2half2_rn(f[it].x, f[it].y);
            __half2 h1 = __floats2half2_rn(f[it].z, f[it].w);
            uint2* p = (uint2*)(smem + (uint32_t)(r0x * SA_STRIDE + seg * 4) * 2);
            *p = make_uint2(*(uint32_t*)&h0, *(uint32_t*)&h1);
        }
    }

    float acc[2][4][4];
    #pragma unroll
    for (int i = 0; i < 2; i++)
        #pragma unroll
        for (int j = 0; j < 4; j++)
            #pragma unroll
            for (int q = 0; q < 4; q++) acc[i][j][q] = 0.f;

    const uint32_t a_off =
        (uint32_t)(((wm * 32 + (lane & 15)) * SA_STRIDE + (lane >> 4) * 8) * 2);
    const uint32_t b_off =
        (uint32_t)(((wn * 32 + (lane & 7) + (lane >> 4) * 8) * SA_STRIDE +
                    ((lane >> 3) & 1) * 8) * 2);

    const int ar = lane >> 2;
    const int ac = (lane & 3) * 2;

    #pragma unroll 1
    for (int c = 0; c < 4; c++) {
        if (c < 3) {
            #pragma unroll
            for (int it = 0; it < 4; it++) {
                int seg = s0x + it * 4;
                int row = node0 + r0x;
                f[it] = (row < N_NODES)
                    ? *(const float4*)(X + (size_t)row * 256 + (c + 1) * 64 + seg * 4)
                    : make_float4(0.f, 0.f, 0.f, 0.f);
            }
            uint32_t st = ((c + 1) & 1) * X_STAGE_B;
            #pragma unroll
            for (int it = 0; it < 4; it++) {
                int r = r0 + it * 32;
                cpa16(sb + st + A_TILE_B + (uint32_t)(r * SA_STRIDE + s0 * 8) * 2,
                      B + (size_t)r * 256 + (c + 1) * 64 + s0 * 8);
            }
            CP_COMMIT();
            asm volatile("cp.async.wait_group 1;" ::: "memory");
        } else {
            asm volatile("cp.async.wait_group 0;" ::: "memory");
        }
        __syncthreads();

        const uint32_t stg = sb + (c & 1) * X_STAGE_B;
        const uint32_t aH = stg + a_off;
        const uint32_t bH = stg + A_TILE_B + b_off;

        #pragma unroll
        for (int k = 0; k < 4; k++) {
            const uint32_t kb = (uint32_t)(k * 32);
            uint32_t ah[2][4], bb[2][4];
            ldsm4(ah[0], aH + kb);
            ldsm4(ah[1], aH + (uint32_t)(16 * SA_STRIDE * 2) + kb);
            ldsm4(bb[0], bH + kb);
            ldsm4(bb[1], bH + (uint32_t)(16 * SA_STRIDE * 2) + kb);
            #pragma unroll
            for (int mt = 0; mt < 2; mt++)
                #pragma unroll
                for (int nt = 0; nt < 4; nt++)
                    hmma(acc[mt][nt], ah[mt], &bb[nt >> 1][(nt & 1) * 2]);
        }

        if (c < 3) {
            uint32_t st = ((c + 1) & 1) * X_STAGE_B;
            #pragma unroll
            for (int it = 0; it < 4; it++) {
                int seg = s0x + it * 4;
                __half2 h0 = __floats2half2_rn(f[it].x, f[it].y);
                __half2 h1 = __floats2half2_rn(f[it].z, f[it].w);
                uint2* p = (uint2*)(smem + st + (uint32_t)(r0x * SA_STRIDE + seg * 4) * 2);
                *p = make_uint2(*(uint32_t*)&h0, *(uint32_t*)&h1);
            }
        }
        __syncthreads();
    }

    #pragma unroll
    for (int mt = 0; mt < 2; mt++) {
        #pragma unroll
        for (int half = 0; half < 2; half++) {
            int node = node0 + wm * 32 + mt * 16 + ar + half * 8;
            #pragma unroll
            for (int nt = 0; nt < 4; nt++) {
                int col = wn * 32 + nt * 8 + ac;
                float v0 = acc[mt][nt][half * 2 + 0] + sbias[col];
                float v1 = acc[mt][nt][half * 2 + 1] + sbias[col + 1];
                *(__half2*)(C + (size_t)node * 256 + col) = __floats2half2_rn(v0, v1);
            }
        }
    }
}

// ------------------------ GEMM (layers): fp16 A, single-term -----------------
#define STAGE_B (A_TILE_B + B_TILE_B)                    // 27648
#define SMEM_BYTES (2 * STAGE_B + 512 + 512 + 1024)      // 57344

__global__ __launch_bounds__(256, 3) void k_gemm_h(
    const __half* __restrict__ A, const __half* __restrict__ B,
    const float* __restrict__ bias,
    __half* __restrict__ C,
    const float* __restrict__ Wfin, float* __restrict__ outv)
{
    extern __shared__ __align__(16) char smem[];
    float* sbias = (float*)(smem + 2 * STAGE_B);
    float* swfin = (float*)(smem + 2 * STAGE_B + 512);
    float (*sred)[4] = (float (*)[4])(smem + 2 * STAGE_B + 1024);

    const int tid = threadIdx.x;
    const int wid = tid >> 5;
    const int lane = tid & 31;
    const int wm = wid >> 2;
    const int wn = wid & 3;
    const int node0 = blockIdx.x * 64;
    const uint32_t sb = smem_u32(smem);

    if (tid < 128) {
        sbias[tid] = bias[tid];
        if (Wfin) swfin[tid] = Wfin[tid];
    }

    const int r0 = tid >> 3;
    const int s0 = tid & 7;

    {
        #pragma unroll
        for (int it = 0; it < 2; it++) {
            int r = r0 + it * 32;
            cpa16(sb + (uint32_t)(r * SA_STRIDE + s0 * 8) * 2,
                  A + (size_t)(node0 + r) * 256 + s0 * 8);
        }
        #pragma unroll
        for (int it = 0; it < 4; it++) {
            int r = r0 + it * 32;
            cpa16(sb + A_TILE_B + (uint32_t)(r * SA_STRIDE + s0 * 8) * 2,
                  B + (size_t)r * 256 + s0 * 8);
        }
        CP_COMMIT();
    }

    float acc[2][4][4];
    #pragma unroll
    for (int i = 0; i < 2; i++)
        #pragma unroll
        for (int j = 0; j < 4; j++)
            #pragma unroll
            for (int q = 0; q < 4; q++) acc[i][j][q] = 0.f;

    const uint32_t a_off =
        (uint32_t)(((wm * 32 + (lane & 15)) * SA_STRIDE + (lane >> 4) * 8) * 2);
    const uint32_t b_off =
        (uint32_t)(((wn * 32 + (lane & 7) + (lane >> 4) * 8) * SA_STRIDE +
                    ((lane >> 3) & 1) * 8) * 2);

    const int ar = lane >> 2;
    const int ac = (lane & 3) * 2;

    #pragma unroll 1
    for (int c = 0; c < 4; c++) {
        if (c < 3) {
            uint32_t st = ((c + 1) & 1) * STAGE_B;
            #pragma unroll
            for (int it = 0; it < 2; it++) {
                int r = r0 + it * 32;
                cpa16(sb + st + (uint32_t)(r * SA_STRIDE + s0 * 8) * 2,
                      A + (size_t)(node0 + r) * 256 + (c + 1) * 64 + s0 * 8);
            }
            #pragma unroll
            for (int it = 0; it < 4; it++) {
                int r = r0 + it * 32;
                cpa16(sb + st + A_TILE_B + (uint32_t)(r * SA_STRIDE + s0 * 8) * 2,
                      B + (size_t)r * 256 + (c + 1) * 64 + s0 * 8);
            }
            CP_COMMIT();
            asm volatile("cp.async.wait_group 1;" ::: "memory");
        } else {
            asm volatile("cp.async.wait_group 0;" ::: "memory");
        }
        __syncthreads();

        const uint32_t stg = sb + (c & 1) * STAGE_B;
        const uint32_t aH = stg + a_off;
        const uint32_t bH = stg + A_TILE_B + b_off;

        #pragma unroll
        for (int k = 0; k < 4; k++) {
            const uint32_t kb = (uint32_t)(k * 32);
            uint32_t ah[2][4], bb[2][4];
            ldsm4(ah[0], aH + kb);
            ldsm4(ah[1], aH + (uint32_t)(16 * SA_STRIDE * 2) + kb);
            ldsm4(bb[0], bH + kb);
            ldsm4(bb[1], bH + (uint32_t)(16 * SA_STRIDE * 2) + kb);
            #pragma unroll
            for (int mt = 0; mt < 2; mt++)
                #pragma unroll
                for (int nt = 0; nt < 4; nt++)
                    hmma(acc[mt][nt], ah[mt], &bb[nt >> 1][(nt & 1) * 2]);
        }
        __syncthreads();
    }

    if (outv) {
        #pragma unroll
        for (int mt = 0; mt < 2; mt++) {
            #pragma unroll
            for (int half = 0; half < 2; half++) {
                int rloc = wm * 32 + mt * 16 + ar + half * 8;
                float p = 0.f;
                #pragma unroll
                for (int nt = 0; nt < 4; nt++) {
                    int col = wn * 32 + nt * 8 + ac;
                    float v0 = fmaxf(acc[mt][nt][half * 2 + 0] + sbias[col], 0.f);
                    float v1 = fmaxf(acc[mt][nt][half * 2 + 1] + sbias[col + 1], 0.f);
                    p += v0 * swfin[col] + v1 * swfin[col + 1];
                }
                p += __shfl_xor_sync(0xffffffffu, p, 1);
                p += __shfl_xor_sync(0xffffffffu, p, 2);
                if ((lane & 3) == 0) sred[rloc][wn] = p;
            }
        }
        __syncthreads();
        if (tid < 64) {
            int node = node0 + tid;
            if (node < N_NODES)
                outv[node] = (sred[tid][0] + sred[tid][1]) + (sred[tid][2] + sred[tid][3]);
        }
        return;
    }

    #pragma unroll
    for (int mt = 0; mt < 2; mt++) {
        #pragma unroll
        for (int half = 0; half < 2; half++) {
            int node = node0 + wm * 32 + mt * 16 + ar + half * 8;
            #pragma unroll
            for (int nt = 0; nt < 4; nt++) {
                int col = wn * 32 + nt * 8 + ac;
                float v0 = fmaxf(acc[mt][nt][half * 2 + 0] + sbias[col], 0.f);
                float v1 = fmaxf(acc[mt][nt][half * 2 + 1] + sbias[col + 1], 0.f);
                *(__half2*)(C + (size_t)node * 256 + col) = __floats2half2_rn(v0, v1);
            }
        }
    }
}

// ------------------------ launch ---------------------------------------------
extern "C" void kernel_launch(void* const* d_in, const int* in_sizes, int n_in,
                              void* d_out, int out_size)
{
    const float* x        = (const float*)d_in[0];
    const float* W_t      = (const float*)d_in[1];
    const float* b_t      = (const float*)d_in[2];
    const float* W_self0  = (const float*)d_in[3];
    const float* b_self0  = (const float*)d_in[4];
    const float* W_neigh0 = (const float*)d_in[5];
    const float* W_self1  = (const float*)d_in[6];
    const float* b_self1  = (const float*)d_in[7];
    const float* W_neigh1 = (const float*)d_in[8];
    const float* W_fin    = (const float*)d_in[9];
    const int*   src      = (const int*)d_in[10];
    const int*   dst      = (const int*)d_in[11];
    float* out = (float*)d_out;

    cudaFuncSetAttribute(k_gemm_h, cudaFuncAttributeMaxDynamicSharedMemorySize,
                         SMEM_BYTES);
    cudaFuncSetAttribute(k_gemm_x, cudaFuncAttributeMaxDynamicSharedMemorySize,
                         SMEM_X);

    __half *A1, *A2;
    cudaGetSymbolAddress((void**)&A1, g_A1);
    cudaGetSymbolAddress((void**)&A2, g_A2);
    __half *Bt, *B0, *B1;
    cudaGetSymbolAddress((void**)&Bt, g_Bt);
    cudaGetSymbolAddress((void**)&B0, g_B0);
    cudaGetSymbolAddress((void**)&B1, g_B1);
    int* cntp;
    cudaGetSymbolAddress((void**)&cntp, g_cnt);

    static cudaStream_t s2 = nullptr;
    static cudaEvent_t ev_fork = nullptr, ev_join = nullptr;
    if (s2 == nullptr) {
        cudaStreamCreateWithFlags(&s2, cudaStreamNonBlocking);
        cudaEventCreateWithFlags(&ev_fork, cudaEventDisableTiming);
        cudaEventCreateWithFlags(&ev_join, cudaEventDisableTiming);
    }

    const int TB = 256;
    dim3 gridNodes((N_NODES + TB - 1) / TB);
    dim3 gridEdges((N_EDGES + TB - 1) / TB);
    dim3 gridWarp((N_NODES * 32 + TB - 1) / TB);

    // ---- fork: CSR build on s2, concurrent with prep/GEMM1 ----
    cudaEventRecord(ev_fork, 0);
    cudaStreamWaitEvent(s2, ev_fork, 0);

    k_prep_w<<<(3 * 128 * 256 + TB - 1) / TB, TB>>>(W_t, W_self0, W_neigh0,
                                                    W_self1, W_neigh1);
    cudaMemsetAsync(cntp, 0, N_NODES * sizeof(int), s2);
    k_hist<<<gridEdges, TB, 0, s2>>>(dst);
    // GEMM1: fused x conversion
    k_gemm_x<<<NTILES64, 256, SMEM_X>>>(x, Bt, b_t, A1);
    k_scan_block<<<NSCANBLK, SCAN_B, 0, s2>>>();
    k_scan_top<<<1, 128, 0, s2>>>();
    k_scan_fin<<<gridNodes, TB, 0, s2>>>();
    k_fill<<<gridEdges, TB, 0, s2>>>(src, dst);

    cudaEventRecord(ev_join, s2);
    cudaStreamWaitEvent(0, ev_join, 0);

    // layer 0
    k_aggregate<<<gridWarp, TB>>>(A1, A1);
    k_gemm_h<<<NTILES64, 256, SMEM_BYTES>>>(A1, B0, b_self0, A2, nullptr, nullptr);
    // layer 1
    k_aggregate<<<gridWarp, TB>>>(A2, A2);
    k_gemm_h<<<NTILES64, 256, SMEM_BYTES>>>(A2, B1, b_self1, nullptr, W_fin, out);
}